// round 8
// baseline (speedup 1.0000x reference)
#include <cuda_runtime.h>
#include <cuda_bf16.h>
#include <math.h>
#include <cstdint>

#define B_ 4
#define D_ 512
#define S_ 2048
#define L_ 8921

// bf16x2 split operands
__device__ __nv_bfloat16 g_Kh[B_ * S_ * D_];
__device__ __nv_bfloat16 g_Kl[B_ * S_ * D_];
__device__ __nv_bfloat16 g_VTh[B_ * D_ * S_];
__device__ __nv_bfloat16 g_VTl[B_ * D_ * S_];
__device__ __nv_bfloat16 g_Qh[L_ * D_];
__device__ __nv_bfloat16 g_Ql[L_ * D_];
__device__ __nv_bfloat16 g_Ah[(size_t)B_ * L_ * S_];
__device__ __nv_bfloat16 g_Al[(size_t)B_ * L_ * S_];
__device__ __nv_bfloat16 g_Hth[B_ * S_ * D_];   // H^T [B,S,D] hi
__device__ __nv_bfloat16 g_Htl[B_ * S_ * D_];   // H^T [B,S,D] lo
__device__ __nv_bfloat16 g_Wh[2 * D_ * D_];     // Wk | Wv hi
__device__ __nv_bfloat16 g_Wl[2 * D_ * D_];     // Wk | Wv lo

// ---------------------------------------------------------------------------
// helpers
// ---------------------------------------------------------------------------
__device__ __forceinline__ uint32_t smem_to_u32(const void* p) {
    uint32_t a;
    asm("{ .reg .u64 t; cvta.to.shared.u64 t, %1; cvt.u32.u64 %0, t; }" : "=r"(a) : "l"(p));
    return a;
}
__device__ __forceinline__ void cp_async16(uint32_t dst, const void* src) {
    asm volatile("cp.async.cg.shared.global [%0], [%1], 16;" :: "r"(dst), "l"(src));
}
#define CP_COMMIT() asm volatile("cp.async.commit_group;" ::: "memory")
#define CP_WAIT(n)  asm volatile("cp.async.wait_group %0;" :: "n"(n) : "memory")

__device__ __forceinline__ void mma_bf16(float* d, const uint32_t* a, const uint32_t* b) {
    asm volatile(
        "mma.sync.aligned.m16n8k16.row.col.f32.bf16.bf16.f32 "
        "{%0,%1,%2,%3}, {%4,%5,%6,%7}, {%8,%9}, {%0,%1,%2,%3};"
        : "+f"(d[0]), "+f"(d[1]), "+f"(d[2]), "+f"(d[3])
        : "r"(a[0]), "r"(a[1]), "r"(a[2]), "r"(a[3]), "r"(b[0]), "r"(b[1]));
}
__device__ __forceinline__ void ldmx4(uint32_t* r, uint32_t addr) {
    asm volatile("ldmatrix.sync.aligned.m8n8.x4.shared.b16 {%0,%1,%2,%3}, [%4];"
        : "=r"(r[0]), "=r"(r[1]), "=r"(r[2]), "=r"(r[3]) : "r"(addr));
}

__device__ __forceinline__ float elu_f(float x) { return x > 0.f ? x : expm1f(x); }

__device__ __forceinline__ void split_bf16(float x, __nv_bfloat16& hi, __nv_bfloat16& lo) {
    hi = __float2bfloat16(x);
    lo = __float2bfloat16(x - __bfloat162float(hi));
}

// ===========================================================================
// GEMM tile config (bf16x3 split mma.sync)
// CTA tile 128x64, TK=32, 8 warps (warp tile 32x32, 4M x 2N grid),
// single-sync double buffer, 3 CTAs/SM.
// ===========================================================================
#define TM 128
#define TN 64
#define TK 32
#define ROWB 80                          // 32 bf16 = 64B + 16B pad
#define A_SUB (TM * ROWB)                // 10240
#define B_SUB (TN * ROWB)                // 5120
#define STAGE (2 * A_SUB + 2 * B_SUB)    // Ah | Al | Bh | Bl = 30720
#define GEMM_SMEM (2 * STAGE)            // 61440 -> 3 CTAs/SM

// ---------------------------------------------------------------------------
// Main GEMM: C[m,n] = sum_k A[m,k]*B[n,k], fp32 output
// ---------------------------------------------------------------------------
__global__ __launch_bounds__(256, 3) void gemm_mma(
    const __nv_bfloat16* __restrict__ Ah, const __nv_bfloat16* __restrict__ Al,
    int lda, size_t sA,
    const __nv_bfloat16* __restrict__ Bh, const __nv_bfloat16* __restrict__ Bl,
    int ldb, size_t sB,
    float* __restrict__ C, int ldc, size_t sC,
    int kblocks, int Mtotal)
{
    extern __shared__ char smem[];
    const uint32_t sm0 = smem_to_u32(smem);

    const int t    = threadIdx.x;
    const int wid  = t >> 5, lane = t & 31;
    const int gid  = lane >> 2, tig = lane & 3;
    const int b    = blockIdx.z;
    const int m0   = blockIdx.y * TM;
    const int n0   = blockIdx.x * TN;

    Ah += (size_t)b * sA;  Al += (size_t)b * sA;
    Bh += (size_t)b * sB;  Bl += (size_t)b * sB;
    C  += (size_t)b * sC;

    const int wm0 = (wid & 3) * 32;
    const int wn0 = (wid >> 2) * 32;

    float acc[2][4][4];
#pragma unroll
    for (int i = 0; i < 2; i++)
#pragma unroll
        for (int j = 0; j < 4; j++)
#pragma unroll
            for (int q = 0; q < 4; q++) acc[i][j][q] = 0.f;

    // stage layout: Ah[0,10240) Al[10240,20480) Bh[20480,25600) Bl[25600,30720)
    auto issue_stage = [&](int kb, int stg) {
        const uint32_t sbase = sm0 + stg * STAGE;
        const int k0 = kb * TK;
        // A: 2 subs x 128 rows x 4 chunks = 1024 chunks
#pragma unroll
        for (int it = 0; it < 4; it++) {
            int idx = t + it * 256;
            int sub = idx >> 9;
            int r   = (idx >> 2) & 127;
            int c   = idx & 3;
            int gr = m0 + r; if (gr >= Mtotal) gr = Mtotal - 1;
            cp_async16(sbase + sub * A_SUB + r * ROWB + c * 16,
                       (sub == 0 ? Ah : Al) + (size_t)gr * lda + k0 + c * 8);
        }
        // B: 2 subs x 64 rows x 4 chunks = 512 chunks
        {
            int idx = t * 2;               // each thread 2 consecutive chunks
#pragma unroll
            for (int u = 0; u < 2; u++) {
                int id = idx + u;
                int sub = id >> 8;
                int r   = (id >> 2) & 63;
                int c   = id & 3;
                cp_async16(sbase + 2 * A_SUB + sub * B_SUB + r * ROWB + c * 16,
                           (sub == 0 ? Bh : Bl) + (size_t)(n0 + r) * ldb + k0 + c * 8);
            }
        }
    };

    const int arow = lane & 15;
    const int aoff = (lane >> 4) * 16;
    const int bprow = ((lane >> 4) & 1) * 8 + (lane & 7);
    const int bpoff = ((lane >> 3) & 1) * 16;

    issue_stage(0, 0);
    CP_COMMIT();

    for (int kb = 0; kb < kblocks; kb++) {
        CP_WAIT(0);
        __syncthreads();
        if (kb + 1 < kblocks) {
            issue_stage(kb + 1, (kb + 1) & 1);
            CP_COMMIT();
        }

        const uint32_t sbase = sm0 + (kb & 1) * STAGE;

#pragma unroll
        for (int ks = 0; ks < 2; ks++) {
            uint32_t ah[2][4], al[2][4];
#pragma unroll
            for (int mt = 0; mt < 2; mt++) {
                uint32_t ra = (wm0 + mt * 16 + arow) * ROWB + ks * 32 + aoff;
                ldmx4(ah[mt], sbase + ra);
                ldmx4(al[mt], sbase + A_SUB + ra);
            }
#pragma unroll
            for (int p = 0; p < 2; p++) {
                uint32_t rb = (wn0 + p * 16 + bprow) * ROWB + ks * 32 + bpoff;
                uint32_t bh4[4], bl4[4];
                ldmx4(bh4, sbase + 2 * A_SUB + rb);
                ldmx4(bl4, sbase + 2 * A_SUB + B_SUB + rb);
#pragma unroll
                for (int h = 0; h < 2; h++) {
                    int nt = 2 * p + h;
#pragma unroll
                    for (int mt = 0; mt < 2; mt++) {
                        mma_bf16(acc[mt][nt], ah[mt], bh4 + 2 * h);
                        mma_bf16(acc[mt][nt], ah[mt], bl4 + 2 * h);
                        mma_bf16(acc[mt][nt], al[mt], bh4 + 2 * h);
                    }
                }
            }
        }
    }

#pragma unroll
    for (int mt = 0; mt < 2; mt++) {
        int r0 = m0 + wm0 + mt * 16 + gid;
#pragma unroll
        for (int nt = 0; nt < 4; nt++) {
            int c0 = n0 + wn0 + nt * 8 + 2 * tig;
            if (r0 < Mtotal)
                *(float2*)(C + (size_t)r0 * ldc + c0) =
                    make_float2(acc[mt][nt][0], acc[mt][nt][1]);
            if (r0 + 8 < Mtotal)
                *(float2*)(C + (size_t)(r0 + 8) * ldc + c0) =
                    make_float2(acc[mt][nt][2], acc[mt][nt][3]);
        }
    }
}

// ---------------------------------------------------------------------------
// KV GEMM: same core; epilogue = +bias, ELU, bf16 split. Exact dims (no guards).
// ---------------------------------------------------------------------------
__global__ __launch_bounds__(256, 3) void kv_gemm(
    const __nv_bfloat16* __restrict__ Ah, const __nv_bfloat16* __restrict__ Al,
    int lda, size_t sA,
    const __nv_bfloat16* __restrict__ Bh, const __nv_bfloat16* __restrict__ Bl,
    int ldb, size_t sB,
    __nv_bfloat16* __restrict__ Oh, __nv_bfloat16* __restrict__ Ol,
    int ldc, size_t sC,
    const float* __restrict__ bias, int biasRow,
    int kblocks)
{
    extern __shared__ char smem[];
    const uint32_t sm0 = smem_to_u32(smem);

    const int t    = threadIdx.x;
    const int wid  = t >> 5, lane = t & 31;
    const int gid  = lane >> 2, tig = lane & 3;
    const int b    = blockIdx.z;
    const int m0   = blockIdx.y * TM;
    const int n0   = blockIdx.x * TN;

    Ah += (size_t)b * sA;  Al += (size_t)b * sA;
    Bh += (size_t)b * sB;  Bl += (size_t)b * sB;
    Oh += (size_t)b * sC;  Ol += (size_t)b * sC;

    const int wm0 = (wid & 3) * 32;
    const int wn0 = (wid >> 2) * 32;

    float acc[2][4][4];
#pragma unroll
    for (int i = 0; i < 2; i++)
#pragma unroll
        for (int j = 0; j < 4; j++)
#pragma unroll
            for (int q = 0; q < 4; q++) acc[i][j][q] = 0.f;

    auto issue_stage = [&](int kb, int stg) {
        const uint32_t sbase = sm0 + stg * STAGE;
        const int k0 = kb * TK;
#pragma unroll
        for (int it = 0; it < 4; it++) {
            int idx = t + it * 256;
            int sub = idx >> 9;
            int r   = (idx >> 2) & 127;
            int c   = idx & 3;
            cp_async16(sbase + sub * A_SUB + r * ROWB + c * 16,
                       (sub == 0 ? Ah : Al) + (size_t)(m0 + r) * lda + k0 + c * 8);
        }
        {
            int idx = t * 2;
#pragma unroll
            for (int u = 0; u < 2; u++) {
                int id = idx + u;
                int sub = id >> 8;
                int r   = (id >> 2) & 63;
                int c   = id & 3;
                cp_async16(sbase + 2 * A_SUB + sub * B_SUB + r * ROWB + c * 16,
                           (sub == 0 ? Bh : Bl) + (size_t)(n0 + r) * ldb + k0 + c * 8);
            }
        }
    };

    const int arow = lane & 15;
    const int aoff = (lane >> 4) * 16;
    const int bprow = ((lane >> 4) & 1) * 8 + (lane & 7);
    const int bpoff = ((lane >> 3) & 1) * 16;

    issue_stage(0, 0);
    CP_COMMIT();

    for (int kb = 0; kb < kblocks; kb++) {
        CP_WAIT(0);
        __syncthreads();
        if (kb + 1 < kblocks) {
            issue_stage(kb + 1, (kb + 1) & 1);
            CP_COMMIT();
        }

        const uint32_t sbase = sm0 + (kb & 1) * STAGE;

#pragma unroll
        for (int ks = 0; ks < 2; ks++) {
            uint32_t ah[2][4], al[2][4];
#pragma unroll
            for (int mt = 0; mt < 2; mt++) {
                uint32_t ra = (wm0 + mt * 16 + arow) * ROWB + ks * 32 + aoff;
                ldmx4(ah[mt], sbase + ra);
                ldmx4(al[mt], sbase + A_SUB + ra);
            }
#pragma unroll
            for (int p = 0; p < 2; p++) {
                uint32_t rb = (wn0 + p * 16 + bprow) * ROWB + ks * 32 + bpoff;
                uint32_t bh4[4], bl4[4];
                ldmx4(bh4, sbase + 2 * A_SUB + rb);
                ldmx4(bl4, sbase + 2 * A_SUB + B_SUB + rb);
#pragma unroll
                for (int h = 0; h < 2; h++) {
                    int nt = 2 * p + h;
#pragma unroll
                    for (int mt = 0; mt < 2; mt++) {
                        mma_bf16(acc[mt][nt], ah[mt], bh4 + 2 * h);
                        mma_bf16(acc[mt][nt], ah[mt], bl4 + 2 * h);
                        mma_bf16(acc[mt][nt], al[mt], bh4 + 2 * h);
                    }
                }
            }
        }
    }

    // epilogue: bias + ELU + split -> bf16x2 stores
#pragma unroll
    for (int mt = 0; mt < 2; mt++) {
        int r0 = m0 + wm0 + mt * 16 + gid;
#pragma unroll
        for (int nt = 0; nt < 4; nt++) {
            int c0 = n0 + wn0 + nt * 8 + 2 * tig;
            float b0, b1, b0r, b1r;
            if (biasRow) {
                b0 = b1 = bias[r0];
                b0r = b1r = bias[r0 + 8];
            } else {
                b0 = b0r = bias[c0];
                b1 = b1r = bias[c0 + 1];
            }
            __nv_bfloat16 h0, l0, h1, l1;
            split_bf16(elu_f(acc[mt][nt][0] + b0), h0, l0);
            split_bf16(elu_f(acc[mt][nt][1] + b1), h1, l1);
            *(__nv_bfloat162*)(Oh + (size_t)r0 * ldc + c0) = __nv_bfloat162(h0, h1);
            *(__nv_bfloat162*)(Ol + (size_t)r0 * ldc + c0) = __nv_bfloat162(l0, l1);
            split_bf16(elu_f(acc[mt][nt][2] + b0r), h0, l0);
            split_bf16(elu_f(acc[mt][nt][3] + b1r), h1, l1);
            *(__nv_bfloat162*)(Oh + (size_t)(r0 + 8) * ldc + c0) = __nv_bfloat162(h0, h1);
            *(__nv_bfloat162*)(Ol + (size_t)(r0 + 8) * ldc + c0) = __nv_bfloat162(l0, l1);
        }
    }
}

// ===========================================================================
// H^T split: H[b,d,s] -> g_Hth/g_Htl [b,s,d] bf16.  Tile 64d x 32s.
// ===========================================================================
__global__ __launch_bounds__(256) void ht_split(const float* __restrict__ H)
{
    __shared__ float tile[64][33];
    const int b = blockIdx.z, s0 = blockIdx.x * 32, d0 = blockIdx.y * 64;
    const int tx = threadIdx.x, ty = threadIdx.y;
    const float* Hb = H + ((size_t)b * D_ + d0) * S_ + s0;

#pragma unroll
    for (int i = 0; i < 8; i++)
        tile[ty * 8 + i][tx] = Hb[(size_t)(ty * 8 + i) * S_ + tx];
    __syncthreads();

    const int t  = ty * 32 + tx;
    const int dd = t & 63, sr = t >> 6;
    const size_t obase = ((size_t)b * S_ + s0) * D_ + d0;
#pragma unroll
    for (int i = 0; i < 8; i++) {
        int s = sr + i * 4;
        float v = tile[dd][s];
        __nv_bfloat16 h, l;
        split_bf16(v, h, l);
        g_Hth[obase + (size_t)s * D_ + dd] = h;
        g_Htl[obase + (size_t)s * D_ + dd] = l;
    }
}

// ===========================================================================
// W split
// ===========================================================================
__global__ __launch_bounds__(256) void w_split(
    const float* __restrict__ Wk, const float* __restrict__ Wv)
{
    int i = blockIdx.x * 1024 + threadIdx.x * 4;
    const float* src = (i < D_ * D_) ? (Wk + i) : (Wv + i - D_ * D_);
    float4 v = *(const float4*)src;
    __nv_bfloat16 h[4], l[4];
    split_bf16(v.x, h[0], l[0]); split_bf16(v.y, h[1], l[1]);
    split_bf16(v.z, h[2], l[2]); split_bf16(v.w, h[3], l[3]);
    *(__nv_bfloat162*)(g_Wh + i)     = __nv_bfloat162(h[0], h[1]);
    *(__nv_bfloat162*)(g_Wh + i + 2) = __nv_bfloat162(h[2], h[3]);
    *(__nv_bfloat162*)(g_Wl + i)     = __nv_bfloat162(l[0], l[1]);
    *(__nv_bfloat162*)(g_Wl + i + 2) = __nv_bfloat162(l[2], l[3]);
}

// ===========================================================================
// Q split
// ===========================================================================
__global__ __launch_bounds__(256) void split_q(const float* __restrict__ Q)
{
    int i = blockIdx.x * 512 + threadIdx.x * 2;
    float2 v = *(const float2*)(Q + i);
    __nv_bfloat16 h0, l0, h1, l1;
    split_bf16(v.x, h0, l0);
    split_bf16(v.y, h1, l1);
    *(__nv_bfloat162*)(g_Qh + i) = __nv_bfloat162(h0, h1);
    *(__nv_bfloat162*)(g_Ql + i) = __nv_bfloat162(l0, l1);
}

// ===========================================================================
// In-place row softmax over S=2048 (+ bf16x2 split)
// ===========================================================================
__global__ __launch_bounds__(256) void softmax_kernel(float* __restrict__ A)
{
    const size_t row = blockIdx.x;
    float* p = A + row * (size_t)S_;
    __nv_bfloat16* ph = g_Ah + row * (size_t)S_;
    __nv_bfloat16* pl = g_Al + row * (size_t)S_;
    const int t = threadIdx.x;
    const int lane = t & 31, wid = t >> 5;

    float4 va = *(const float4*)(p + t * 4);
    float4 vb = *(const float4*)(p + 1024 + t * 4);

    float m = fmaxf(fmaxf(fmaxf(va.x, va.y), fmaxf(va.z, va.w)),
                    fmaxf(fmaxf(vb.x, vb.y), fmaxf(vb.z, vb.w)));
#pragma unroll
    for (int o = 16; o > 0; o >>= 1) m = fmaxf(m, __shfl_xor_sync(0xffffffffu, m, o));

    __shared__ float red[8];
    if (lane == 0) red[wid] = m;
    __syncthreads();
    {
        float r = red[lane & 7];
#pragma unroll
        for (int o = 4; o > 0; o >>= 1) r = fmaxf(r, __shfl_xor_sync(0xffffffffu, r, o));
        m = r;
    }

    va.x = __expf(va.x - m); va.y = __expf(va.y - m);
    va.z = __expf(va.z - m); va.w = __expf(va.w - m);
    vb.x = __expf(vb.x - m); vb.y = __expf(vb.y - m);
    vb.z = __expf(vb.z - m); vb.w = __expf(vb.w - m);

    float s = va.x + va.y + va.z + va.w + vb.x + vb.y + vb.z + vb.w;
#pragma unroll
    for (int o = 16; o > 0; o >>= 1) s += __shfl_xor_sync(0xffffffffu, s, o);
    __syncthreads();
    if (lane == 0) red[wid] = s;
    __syncthreads();
    {
        float r = red[lane & 7];
#pragma unroll
        for (int o = 4; o > 0; o >>= 1) r += __shfl_xor_sync(0xffffffffu, r, o);
        s = r;
    }
    float inv = 1.f / s;

    va.x *= inv; va.y *= inv; va.z *= inv; va.w *= inv;
    vb.x *= inv; vb.y *= inv; vb.z *= inv; vb.w *= inv;

    *(float4*)(p + t * 4) = va;
    *(float4*)(p + 1024 + t * 4) = vb;

    __nv_bfloat16 h[8], l[8];
    split_bf16(va.x, h[0], l[0]); split_bf16(va.y, h[1], l[1]);
    split_bf16(va.z, h[2], l[2]); split_bf16(va.w, h[3], l[3]);
    split_bf16(vb.x, h[4], l[4]); split_bf16(vb.y, h[5], l[5]);
    split_bf16(vb.z, h[6], l[6]); split_bf16(vb.w, h[7], l[7]);

    *(__nv_bfloat162*)(ph + t * 4)     = __nv_bfloat162(h[0], h[1]);
    *(__nv_bfloat162*)(ph + t * 4 + 2) = __nv_bfloat162(h[2], h[3]);
    *(__nv_bfloat162*)(ph + 1024 + t * 4)     = __nv_bfloat162(h[4], h[5]);
    *(__nv_bfloat162*)(ph + 1024 + t * 4 + 2) = __nv_bfloat162(h[6], h[7]);
    *(__nv_bfloat162*)(pl + t * 4)     = __nv_bfloat162(l[0], l[1]);
    *(__nv_bfloat162*)(pl + t * 4 + 2) = __nv_bfloat162(l[2], l[3]);
    *(__nv_bfloat162*)(pl + 1024 + t * 4)     = __nv_bfloat162(l[4], l[5]);
    *(__nv_bfloat162*)(pl + 1024 + t * 4 + 2) = __nv_bfloat162(l[6], l[7]);
}

// ===========================================================================
extern "C" void kernel_launch(void* const* d_in, const int* in_sizes, int n_in,
                              void* d_out, int out_size)
{
    const float* H  = (const float*)d_in[0];
    const float* Wk = (const float*)d_in[1];
    const float* bk = (const float*)d_in[2];
    const float* Wv = (const float*)d_in[3];
    const float* bv = (const float*)d_in[4];
    const float* Q  = (const float*)d_in[5];

    float* out  = (float*)d_out;
    float* Cout = out;                          // [B, L, D]
    float* Aout = out + (size_t)B_ * L_ * D_;   // [B, L, S]

    static __nv_bfloat16 *gKh, *gKl, *gVTh, *gVTl, *gQh, *gQl, *gAh, *gAl;
    static __nv_bfloat16 *gHth, *gHtl, *gWh, *gWl;
    static bool init = false;
    if (!init) {
        cudaGetSymbolAddress((void**)&gKh,  g_Kh);
        cudaGetSymbolAddress((void**)&gKl,  g_Kl);
        cudaGetSymbolAddress((void**)&gVTh, g_VTh);
        cudaGetSymbolAddress((void**)&gVTl, g_VTl);
        cudaGetSymbolAddress((void**)&gQh,  g_Qh);
        cudaGetSymbolAddress((void**)&gQl,  g_Ql);
        cudaGetSymbolAddress((void**)&gAh,  g_Ah);
        cudaGetSymbolAddress((void**)&gAl,  g_Al);
        cudaGetSymbolAddress((void**)&gHth, g_Hth);
        cudaGetSymbolAddress((void**)&gHtl, g_Htl);
        cudaGetSymbolAddress((void**)&gWh,  g_Wh);
        cudaGetSymbolAddress((void**)&gWl,  g_Wl);
        cudaFuncSetAttribute(gemm_mma, cudaFuncAttributeMaxDynamicSharedMemorySize, GEMM_SMEM);
        cudaFuncSetAttribute(kv_gemm, cudaFuncAttributeMaxDynamicSharedMemorySize, GEMM_SMEM);
        init = true;
    }

    const int MT = (L_ + TM - 1) / TM;  // 70

    // 0) splits / transpose
    split_q<<<dim3(L_), 256>>>(Q);
    ht_split<<<dim3(S_ / 32, D_ / 64, B_), dim3(32, 8)>>>(H);
    w_split<<<dim3(2 * D_ * D_ / 1024), 256>>>(Wk, Wv);

    // 1a) K[b,s,o] = H^T * Wk
    kv_gemm<<<dim3(D_ / TN, S_ / TM, B_), 256, GEMM_SMEM>>>(
        gHth, gHtl, D_, (size_t)S_ * D_,
        gWh, gWl, D_, 0,
        gKh, gKl, D_, (size_t)S_ * D_,
        bk, 0, D_ / TK);

    // 1b) V^T[b,o,s] = Wv * H^T
    kv_gemm<<<dim3(S_ / TN, D_ / TM, B_), 256, GEMM_SMEM>>>(
        gWh + D_ * D_, gWl + D_ * D_, D_, 0,
        gHth, gHtl, D_, (size_t)S_ * D_,
        gVTh, gVTl, S_, (size_t)D_ * S_,
        bv, 1, D_ / TK);

    // 2) E = Q K^T -> Aout
    gemm_mma<<<dim3(S_ / TN, MT, B_), 256, GEMM_SMEM>>>(
        gQh, gQl, D_, 0,
        gKh, gKl, D_, (size_t)S_ * D_,
        Aout, S_, (size_t)L_ * S_,
        D_ / TK, L_);

    // 3) softmax rows (+ bf16x2 split of A)
    softmax_kernel<<<dim3(B_ * L_), 256>>>(Aout);

    // 4) C = A V -> Cout
    gemm_mma<<<dim3(D_ / TN, MT, B_), 256, GEMM_SMEM>>>(
        gAh, gAl, S_, (size_t)L_ * S_,
        gVTh, gVTl, S_, (size_t)D_ * S_,
        Cout, D_, (size_t)L_ * D_,
        S_ / TK, L_);
}

// round 9
// speedup vs baseline: 1.1157x; 1.1157x over previous
#include <cuda_runtime.h>
#include <cuda_bf16.h>
#include <math.h>
#include <cstdint>

#define B_ 4
#define D_ 512
#define S_ 2048
#define L_ 8921

// bf16x2 split operands
__device__ __nv_bfloat16 g_Kh[B_ * S_ * D_];
__device__ __nv_bfloat16 g_Kl[B_ * S_ * D_];
__device__ __nv_bfloat16 g_VTh[B_ * D_ * S_];
__device__ __nv_bfloat16 g_VTl[B_ * D_ * S_];
__device__ __nv_bfloat16 g_Qh[L_ * D_];
__device__ __nv_bfloat16 g_Ql[L_ * D_];
__device__ __nv_bfloat16 g_Ah[(size_t)B_ * L_ * S_];
__device__ __nv_bfloat16 g_Al[(size_t)B_ * L_ * S_];
__device__ __nv_bfloat16 g_Hth[B_ * S_ * D_];   // H^T [B,S,D] hi
__device__ __nv_bfloat16 g_Htl[B_ * S_ * D_];   // H^T [B,S,D] lo
__device__ __nv_bfloat16 g_Wh[2 * D_ * D_];     // Wk | Wv hi
__device__ __nv_bfloat16 g_Wl[2 * D_ * D_];     // Wk | Wv lo

// ---------------------------------------------------------------------------
// helpers
// ---------------------------------------------------------------------------
__device__ __forceinline__ uint32_t smem_to_u32(const void* p) {
    uint32_t a;
    asm("{ .reg .u64 t; cvta.to.shared.u64 t, %1; cvt.u32.u64 %0, t; }" : "=r"(a) : "l"(p));
    return a;
}
__device__ __forceinline__ void cp_async16(uint32_t dst, const void* src) {
    asm volatile("cp.async.cg.shared.global [%0], [%1], 16;" :: "r"(dst), "l"(src));
}
#define CP_COMMIT() asm volatile("cp.async.commit_group;" ::: "memory")
#define CP_WAIT(n)  asm volatile("cp.async.wait_group %0;" :: "n"(n) : "memory")

// NOTE: non-volatile on purpose — register-only op, let ptxas schedule freely.
__device__ __forceinline__ void mma_bf16(float* d, const uint32_t* a, const uint32_t* b) {
    asm("mma.sync.aligned.m16n8k16.row.col.f32.bf16.bf16.f32 "
        "{%0,%1,%2,%3}, {%4,%5,%6,%7}, {%8,%9}, {%0,%1,%2,%3};"
        : "+f"(d[0]), "+f"(d[1]), "+f"(d[2]), "+f"(d[3])
        : "r"(a[0]), "r"(a[1]), "r"(a[2]), "r"(a[3]), "r"(b[0]), "r"(b[1]));
}
__device__ __forceinline__ void ldmx4(uint32_t* r, uint32_t addr) {
    asm volatile("ldmatrix.sync.aligned.m8n8.x4.shared.b16 {%0,%1,%2,%3}, [%4];"
        : "=r"(r[0]), "=r"(r[1]), "=r"(r[2]), "=r"(r[3]) : "r"(addr));
}

__device__ __forceinline__ float elu_f(float x) { return x > 0.f ? x : expm1f(x); }

__device__ __forceinline__ void split_bf16(float x, __nv_bfloat16& hi, __nv_bfloat16& lo) {
    hi = __float2bfloat16(x);
    lo = __float2bfloat16(x - __bfloat162float(hi));
}

// ===========================================================================
// GEMM tile config (bf16x3 split mma.sync)
// Block 128x128, TK=32, 8 warps (warp tile 64x32), single-sync double buffer,
// 2 CTAs/SM. Term-major MMA ordering to break accumulator dependency chains.
// ===========================================================================
#define TM 128
#define TN 128
#define TK 32
#define ROWB 80                          // 32 bf16 = 64B + 16B pad
#define SUB  (128 * ROWB)                // 10240 per sub-tile
#define STAGE (4 * SUB)                  // Ah | Al | Bh | Bl = 40960
#define GEMM_SMEM (2 * STAGE)            // 81920 -> 2 CTAs/SM

// ---------------------------------------------------------------------------
// Main GEMM: C[m,n] = sum_k A[m,k]*B[n,k], fp32 output
// ---------------------------------------------------------------------------
__global__ __launch_bounds__(256, 2) void gemm_mma(
    const __nv_bfloat16* __restrict__ Ah, const __nv_bfloat16* __restrict__ Al,
    int lda, size_t sA,
    const __nv_bfloat16* __restrict__ Bh, const __nv_bfloat16* __restrict__ Bl,
    int ldb, size_t sB,
    float* __restrict__ C, int ldc, size_t sC,
    int kblocks, int Mtotal)
{
    extern __shared__ char smem[];
    const uint32_t sm0 = smem_to_u32(smem);

    const int t    = threadIdx.x;
    const int wid  = t >> 5, lane = t & 31;
    const int gid  = lane >> 2, tig = lane & 3;
    const int b    = blockIdx.z;
    const int m0   = blockIdx.y * TM;
    const int n0   = blockIdx.x * TN;

    Ah += (size_t)b * sA;  Al += (size_t)b * sA;
    Bh += (size_t)b * sB;  Bl += (size_t)b * sB;
    C  += (size_t)b * sC;

    const int wm0 = (wid & 1) * 64;
    const int wn0 = (wid >> 1) * 32;

    float acc[4][4][4];
#pragma unroll
    for (int i = 0; i < 4; i++)
#pragma unroll
        for (int j = 0; j < 4; j++)
#pragma unroll
            for (int q = 0; q < 4; q++) acc[i][j][q] = 0.f;

    auto issue_stage = [&](int kb, int stg) {
        const uint32_t sbase = sm0 + stg * STAGE;
        const int k0 = kb * TK;
#pragma unroll
        for (int it = 0; it < 8; it++) {
            int idx = t + it * 256;
            int sub = idx >> 9;
            int r   = (idx >> 2) & 127;
            int c   = idx & 3;
            uint32_t dst = sbase + sub * SUB + r * ROWB + c * 16;
            const __nv_bfloat16* src;
            if (sub < 2) {
                int gr = m0 + r; if (gr >= Mtotal) gr = Mtotal - 1;
                src = (sub == 0 ? Ah : Al) + (size_t)gr * lda + k0 + c * 8;
            } else {
                src = (sub == 2 ? Bh : Bl) + (size_t)(n0 + r) * ldb + k0 + c * 8;
            }
            cp_async16(dst, src);
        }
    };

    const int arow = lane & 15;
    const int aoff = (lane >> 4) * 16;
    const int bprow = ((lane >> 4) & 1) * 8 + (lane & 7);
    const int bpoff = ((lane >> 3) & 1) * 16;

    issue_stage(0, 0);
    CP_COMMIT();

    for (int kb = 0; kb < kblocks; kb++) {
        CP_WAIT(0);
        __syncthreads();
        if (kb + 1 < kblocks) {
            issue_stage(kb + 1, (kb + 1) & 1);
            CP_COMMIT();
        }

        const uint32_t sbase = sm0 + (kb & 1) * STAGE;

#pragma unroll
        for (int ks = 0; ks < 2; ks++) {
            uint32_t ah[4][4], al[4][4];
#pragma unroll
            for (int mt = 0; mt < 4; mt++) {
                uint32_t ra = (wm0 + mt * 16 + arow) * ROWB + ks * 32 + aoff;
                ldmx4(ah[mt], sbase + 0 * SUB + ra);
                ldmx4(al[mt], sbase + 1 * SUB + ra);
            }
#pragma unroll
            for (int p = 0; p < 2; p++) {
                uint32_t rb = (wn0 + p * 16 + bprow) * ROWB + ks * 32 + bpoff;
                uint32_t bh4[4], bl4[4];
                ldmx4(bh4, sbase + 2 * SUB + rb);
                ldmx4(bl4, sbase + 3 * SUB + rb);
                // term-major ordering: 8 independent accumulators between
                // dependent writes to the same accumulator.
#pragma unroll
                for (int mt = 0; mt < 4; mt++)
#pragma unroll
                    for (int h = 0; h < 2; h++)
                        mma_bf16(acc[mt][2 * p + h], ah[mt], bh4 + 2 * h);
#pragma unroll
                for (int mt = 0; mt < 4; mt++)
#pragma unroll
                    for (int h = 0; h < 2; h++)
                        mma_bf16(acc[mt][2 * p + h], ah[mt], bl4 + 2 * h);
#pragma unroll
                for (int mt = 0; mt < 4; mt++)
#pragma unroll
                    for (int h = 0; h < 2; h++)
                        mma_bf16(acc[mt][2 * p + h], al[mt], bh4 + 2 * h);
            }
        }
    }

#pragma unroll
    for (int mt = 0; mt < 4; mt++) {
        int r0 = m0 + wm0 + mt * 16 + gid;
#pragma unroll
        for (int nt = 0; nt < 4; nt++) {
            int c0 = n0 + wn0 + nt * 8 + 2 * tig;
            if (r0 < Mtotal)
                *(float2*)(C + (size_t)r0 * ldc + c0) =
                    make_float2(acc[mt][nt][0], acc[mt][nt][1]);
            if (r0 + 8 < Mtotal)
                *(float2*)(C + (size_t)(r0 + 8) * ldc + c0) =
                    make_float2(acc[mt][nt][2], acc[mt][nt][3]);
        }
    }
}

// ---------------------------------------------------------------------------
// KV GEMM: same core; epilogue = +bias, ELU, bf16 split.
// ---------------------------------------------------------------------------
__global__ __launch_bounds__(256, 2) void kv_gemm(
    const __nv_bfloat16* __restrict__ Ah, const __nv_bfloat16* __restrict__ Al,
    int lda, size_t sA,
    const __nv_bfloat16* __restrict__ Bh, const __nv_bfloat16* __restrict__ Bl,
    int ldb, size_t sB,
    __nv_bfloat16* __restrict__ Oh, __nv_bfloat16* __restrict__ Ol,
    int ldc, size_t sC,
    const float* __restrict__ bias, int biasRow,
    int kblocks)
{
    extern __shared__ char smem[];
    const uint32_t sm0 = smem_to_u32(smem);

    const int t    = threadIdx.x;
    const int wid  = t >> 5, lane = t & 31;
    const int gid  = lane >> 2, tig = lane & 3;
    const int b    = blockIdx.z;
    const int m0   = blockIdx.y * TM;
    const int n0   = blockIdx.x * TN;

    Ah += (size_t)b * sA;  Al += (size_t)b * sA;
    Bh += (size_t)b * sB;  Bl += (size_t)b * sB;
    Oh += (size_t)b * sC;  Ol += (size_t)b * sC;

    const int wm0 = (wid & 1) * 64;
    const int wn0 = (wid >> 1) * 32;

    float acc[4][4][4];
#pragma unroll
    for (int i = 0; i < 4; i++)
#pragma unroll
        for (int j = 0; j < 4; j++)
#pragma unroll
            for (int q = 0; q < 4; q++) acc[i][j][q] = 0.f;

    auto issue_stage = [&](int kb, int stg) {
        const uint32_t sbase = sm0 + stg * STAGE;
        const int k0 = kb * TK;
#pragma unroll
        for (int it = 0; it < 8; it++) {
            int idx = t + it * 256;
            int sub = idx >> 9;
            int r   = (idx >> 2) & 127;
            int c   = idx & 3;
            uint32_t dst = sbase + sub * SUB + r * ROWB + c * 16;
            const __nv_bfloat16* src;
            if (sub < 2)
                src = (sub == 0 ? Ah : Al) + (size_t)(m0 + r) * lda + k0 + c * 8;
            else
                src = (sub == 2 ? Bh : Bl) + (size_t)(n0 + r) * ldb + k0 + c * 8;
            cp_async16(dst, src);
        }
    };

    const int arow = lane & 15;
    const int aoff = (lane >> 4) * 16;
    const int bprow = ((lane >> 4) & 1) * 8 + (lane & 7);
    const int bpoff = ((lane >> 3) & 1) * 16;

    issue_stage(0, 0);
    CP_COMMIT();

    for (int kb = 0; kb < kblocks; kb++) {
        CP_WAIT(0);
        __syncthreads();
        if (kb + 1 < kblocks) {
            issue_stage(kb + 1, (kb + 1) & 1);
            CP_COMMIT();
        }

        const uint32_t sbase = sm0 + (kb & 1) * STAGE;

#pragma unroll
        for (int ks = 0; ks < 2; ks++) {
            uint32_t ah[4][4], al[4][4];
#pragma unroll
            for (int mt = 0; mt < 4; mt++) {
                uint32_t ra = (wm0 + mt * 16 + arow) * ROWB + ks * 32 + aoff;
                ldmx4(ah[mt], sbase + 0 * SUB + ra);
                ldmx4(al[mt], sbase + 1 * SUB + ra);
            }
#pragma unroll
            for (int p = 0; p < 2; p++) {
                uint32_t rb = (wn0 + p * 16 + bprow) * ROWB + ks * 32 + bpoff;
                uint32_t bh4[4], bl4[4];
                ldmx4(bh4, sbase + 2 * SUB + rb);
                ldmx4(bl4, sbase + 3 * SUB + rb);
#pragma unroll
                for (int mt = 0; mt < 4; mt++)
#pragma unroll
                    for (int h = 0; h < 2; h++)
                        mma_bf16(acc[mt][2 * p + h], ah[mt], bh4 + 2 * h);
#pragma unroll
                for (int mt = 0; mt < 4; mt++)
#pragma unroll
                    for (int h = 0; h < 2; h++)
                        mma_bf16(acc[mt][2 * p + h], ah[mt], bl4 + 2 * h);
#pragma unroll
                for (int mt = 0; mt < 4; mt++)
#pragma unroll
                    for (int h = 0; h < 2; h++)
                        mma_bf16(acc[mt][2 * p + h], al[mt], bh4 + 2 * h);
            }
        }
    }

    // epilogue: bias + ELU + split -> bf16x2 stores
#pragma unroll
    for (int mt = 0; mt < 4; mt++) {
        int r0 = m0 + wm0 + mt * 16 + gid;
#pragma unroll
        for (int nt = 0; nt < 4; nt++) {
            int c0 = n0 + wn0 + nt * 8 + 2 * tig;
            float b0, b1, b0r, b1r;
            if (biasRow) {
                b0 = b1 = bias[r0];
                b0r = b1r = bias[r0 + 8];
            } else {
                b0 = b0r = bias[c0];
                b1 = b1r = bias[c0 + 1];
            }
            __nv_bfloat16 h0, l0, h1, l1;
            split_bf16(elu_f(acc[mt][nt][0] + b0), h0, l0);
            split_bf16(elu_f(acc[mt][nt][1] + b1), h1, l1);
            *(__nv_bfloat162*)(Oh + (size_t)r0 * ldc + c0) = __nv_bfloat162(h0, h1);
            *(__nv_bfloat162*)(Ol + (size_t)r0 * ldc + c0) = __nv_bfloat162(l0, l1);
            split_bf16(elu_f(acc[mt][nt][2] + b0r), h0, l0);
            split_bf16(elu_f(acc[mt][nt][3] + b1r), h1, l1);
            *(__nv_bfloat162*)(Oh + (size_t)(r0 + 8) * ldc + c0) = __nv_bfloat162(h0, h1);
            *(__nv_bfloat162*)(Ol + (size_t)(r0 + 8) * ldc + c0) = __nv_bfloat162(l0, l1);
        }
    }
}

// ===========================================================================
// H^T split: H[b,d,s] -> g_Hth/g_Htl [b,s,d] bf16.  Tile 64d x 32s.
// ===========================================================================
__global__ __launch_bounds__(256) void ht_split(const float* __restrict__ H)
{
    __shared__ float tile[64][33];
    const int b = blockIdx.z, s0 = blockIdx.x * 32, d0 = blockIdx.y * 64;
    const int tx = threadIdx.x, ty = threadIdx.y;
    const float* Hb = H + ((size_t)b * D_ + d0) * S_ + s0;

#pragma unroll
    for (int i = 0; i < 8; i++)
        tile[ty * 8 + i][tx] = Hb[(size_t)(ty * 8 + i) * S_ + tx];
    __syncthreads();

    const int t  = ty * 32 + tx;
    const int dd = t & 63, sr = t >> 6;
    const size_t obase = ((size_t)b * S_ + s0) * D_ + d0;
#pragma unroll
    for (int i = 0; i < 8; i++) {
        int s = sr + i * 4;
        float v = tile[dd][s];
        __nv_bfloat16 h, l;
        split_bf16(v, h, l);
        g_Hth[obase + (size_t)s * D_ + dd] = h;
        g_Htl[obase + (size_t)s * D_ + dd] = l;
    }
}

// ===========================================================================
// W split
// ===========================================================================
__global__ __launch_bounds__(256) void w_split(
    const float* __restrict__ Wk, const float* __restrict__ Wv)
{
    int i = blockIdx.x * 1024 + threadIdx.x * 4;
    const float* src = (i < D_ * D_) ? (Wk + i) : (Wv + i - D_ * D_);
    float4 v = *(const float4*)src;
    __nv_bfloat16 h[4], l[4];
    split_bf16(v.x, h[0], l[0]); split_bf16(v.y, h[1], l[1]);
    split_bf16(v.z, h[2], l[2]); split_bf16(v.w, h[3], l[3]);
    *(__nv_bfloat162*)(g_Wh + i)     = __nv_bfloat162(h[0], h[1]);
    *(__nv_bfloat162*)(g_Wh + i + 2) = __nv_bfloat162(h[2], h[3]);
    *(__nv_bfloat162*)(g_Wl + i)     = __nv_bfloat162(l[0], l[1]);
    *(__nv_bfloat162*)(g_Wl + i + 2) = __nv_bfloat162(l[2], l[3]);
}

// ===========================================================================
// Q split
// ===========================================================================
__global__ __launch_bounds__(256) void split_q(const float* __restrict__ Q)
{
    int i = blockIdx.x * 512 + threadIdx.x * 2;
    float2 v = *(const float2*)(Q + i);
    __nv_bfloat16 h0, l0, h1, l1;
    split_bf16(v.x, h0, l0);
    split_bf16(v.y, h1, l1);
    *(__nv_bfloat162*)(g_Qh + i) = __nv_bfloat162(h0, h1);
    *(__nv_bfloat162*)(g_Ql + i) = __nv_bfloat162(l0, l1);
}

// ===========================================================================
// In-place row softmax over S=2048 (+ bf16x2 split)
// ===========================================================================
__global__ __launch_bounds__(256) void softmax_kernel(float* __restrict__ A)
{
    const size_t row = blockIdx.x;
    float* p = A + row * (size_t)S_;
    __nv_bfloat16* ph = g_Ah + row * (size_t)S_;
    __nv_bfloat16* pl = g_Al + row * (size_t)S_;
    const int t = threadIdx.x;
    const int lane = t & 31, wid = t >> 5;

    float4 va = *(const float4*)(p + t * 4);
    float4 vb = *(const float4*)(p + 1024 + t * 4);

    float m = fmaxf(fmaxf(fmaxf(va.x, va.y), fmaxf(va.z, va.w)),
                    fmaxf(fmaxf(vb.x, vb.y), fmaxf(vb.z, vb.w)));
#pragma unroll
    for (int o = 16; o > 0; o >>= 1) m = fmaxf(m, __shfl_xor_sync(0xffffffffu, m, o));

    __shared__ float red[8];
    if (lane == 0) red[wid] = m;
    __syncthreads();
    {
        float r = red[lane & 7];
#pragma unroll
        for (int o = 4; o > 0; o >>= 1) r = fmaxf(r, __shfl_xor_sync(0xffffffffu, r, o));
        m = r;
    }

    va.x = __expf(va.x - m); va.y = __expf(va.y - m);
    va.z = __expf(va.z - m); va.w = __expf(va.w - m);
    vb.x = __expf(vb.x - m); vb.y = __expf(vb.y - m);
    vb.z = __expf(vb.z - m); vb.w = __expf(vb.w - m);

    float s = va.x + va.y + va.z + va.w + vb.x + vb.y + vb.z + vb.w;
#pragma unroll
    for (int o = 16; o > 0; o >>= 1) s += __shfl_xor_sync(0xffffffffu, s, o);
    __syncthreads();
    if (lane == 0) red[wid] = s;
    __syncthreads();
    {
        float r = red[lane & 7];
#pragma unroll
        for (int o = 4; o > 0; o >>= 1) r += __shfl_xor_sync(0xffffffffu, r, o);
        s = r;
    }
    float inv = 1.f / s;

    va.x *= inv; va.y *= inv; va.z *= inv; va.w *= inv;
    vb.x *= inv; vb.y *= inv; vb.z *= inv; vb.w *= inv;

    *(float4*)(p + t * 4) = va;
    *(float4*)(p + 1024 + t * 4) = vb;

    __nv_bfloat16 h[8], l[8];
    split_bf16(va.x, h[0], l[0]); split_bf16(va.y, h[1], l[1]);
    split_bf16(va.z, h[2], l[2]); split_bf16(va.w, h[3], l[3]);
    split_bf16(vb.x, h[4], l[4]); split_bf16(vb.y, h[5], l[5]);
    split_bf16(vb.z, h[6], l[6]); split_bf16(vb.w, h[7], l[7]);

    *(__nv_bfloat162*)(ph + t * 4)     = __nv_bfloat162(h[0], h[1]);
    *(__nv_bfloat162*)(ph + t * 4 + 2) = __nv_bfloat162(h[2], h[3]);
    *(__nv_bfloat162*)(ph + 1024 + t * 4)     = __nv_bfloat162(h[4], h[5]);
    *(__nv_bfloat162*)(ph + 1024 + t * 4 + 2) = __nv_bfloat162(h[6], h[7]);
    *(__nv_bfloat162*)(pl + t * 4)     = __nv_bfloat162(l[0], l[1]);
    *(__nv_bfloat162*)(pl + t * 4 + 2) = __nv_bfloat162(l[2], l[3]);
    *(__nv_bfloat162*)(pl + 1024 + t * 4)     = __nv_bfloat162(l[4], l[5]);
    *(__nv_bfloat162*)(pl + 1024 + t * 4 + 2) = __nv_bfloat162(l[6], l[7]);
}

// ===========================================================================
extern "C" void kernel_launch(void* const* d_in, const int* in_sizes, int n_in,
                              void* d_out, int out_size)
{
    const float* H  = (const float*)d_in[0];
    const float* Wk = (const float*)d_in[1];
    const float* bk = (const float*)d_in[2];
    const float* Wv = (const float*)d_in[3];
    const float* bv = (const float*)d_in[4];
    const float* Q  = (const float*)d_in[5];

    float* out  = (float*)d_out;
    float* Cout = out;                          // [B, L, D]
    float* Aout = out + (size_t)B_ * L_ * D_;   // [B, L, S]

    static __nv_bfloat16 *gKh, *gKl, *gVTh, *gVTl, *gQh, *gQl, *gAh, *gAl;
    static __nv_bfloat16 *gHth, *gHtl, *gWh, *gWl;
    static bool init = false;
    if (!init) {
        cudaGetSymbolAddress((void**)&gKh,  g_Kh);
        cudaGetSymbolAddress((void**)&gKl,  g_Kl);
        cudaGetSymbolAddress((void**)&gVTh, g_VTh);
        cudaGetSymbolAddress((void**)&gVTl, g_VTl);
        cudaGetSymbolAddress((void**)&gQh,  g_Qh);
        cudaGetSymbolAddress((void**)&gQl,  g_Ql);
        cudaGetSymbolAddress((void**)&gAh,  g_Ah);
        cudaGetSymbolAddress((void**)&gAl,  g_Al);
        cudaGetSymbolAddress((void**)&gHth, g_Hth);
        cudaGetSymbolAddress((void**)&gHtl, g_Htl);
        cudaGetSymbolAddress((void**)&gWh,  g_Wh);
        cudaGetSymbolAddress((void**)&gWl,  g_Wl);
        cudaFuncSetAttribute(gemm_mma, cudaFuncAttributeMaxDynamicSharedMemorySize, GEMM_SMEM);
        cudaFuncSetAttribute(kv_gemm, cudaFuncAttributeMaxDynamicSharedMemorySize, GEMM_SMEM);
        init = true;
    }

    const int MT = (L_ + TM - 1) / TM;  // 70

    // 0) splits / transpose
    split_q<<<dim3(L_), 256>>>(Q);
    ht_split<<<dim3(S_ / 32, D_ / 64, B_), dim3(32, 8)>>>(H);
    w_split<<<dim3(2 * D_ * D_ / 1024), 256>>>(Wk, Wv);

    // 1a) K[b,s,o] = H^T * Wk
    kv_gemm<<<dim3(D_ / TN, S_ / TM, B_), 256, GEMM_SMEM>>>(
        gHth, gHtl, D_, (size_t)S_ * D_,
        gWh, gWl, D_, 0,
        gKh, gKl, D_, (size_t)S_ * D_,
        bk, 0, D_ / TK);

    // 1b) V^T[b,o,s] = Wv * H^T
    kv_gemm<<<dim3(S_ / TN, D_ / TM, B_), 256, GEMM_SMEM>>>(
        gWh + D_ * D_, gWl + D_ * D_, D_, 0,
        gHth, gHtl, D_, (size_t)S_ * D_,
        gVTh, gVTl, S_, (size_t)D_ * S_,
        bv, 1, D_ / TK);

    // 2) E = Q K^T -> Aout
    gemm_mma<<<dim3(S_ / TN, MT, B_), 256, GEMM_SMEM>>>(
        gQh, gQl, D_, 0,
        gKh, gKl, D_, (size_t)S_ * D_,
        Aout, S_, (size_t)L_ * S_,
        D_ / TK, L_);

    // 3) softmax rows (+ bf16x2 split of A)
    softmax_kernel<<<dim3(B_ * L_), 256>>>(Aout);

    // 4) C = A V -> Cout
    gemm_mma<<<dim3(D_ / TN, MT, B_), 256, GEMM_SMEM>>>(
        gAh, gAl, S_, (size_t)L_ * S_,
        gVTh, gVTl, S_, (size_t)D_ * S_,
        Cout, D_, (size_t)L_ * D_,
        S_ / TK, L_);
}

// round 10
// speedup vs baseline: 1.3071x; 1.1716x over previous
#include <cuda_runtime.h>
#include <cuda_bf16.h>
#include <math.h>
#include <cstdint>

#define B_ 4
#define D_ 512
#define S_ 2048
#define L_ 8921

#define SLOT 32768              // one packed (tile128 x kb64) slot: hi 16KB | lo 16KB
#define HSUB 16384

// Packed operand buffers (swizzled tiles, bulk-copy ready)
__device__ char g_Qp[(size_t)70 * 8 * SLOT];            // Q  [8960, 512]
__device__ char g_Hp[(size_t)4 * 16 * 8 * SLOT];        // H^T per b: [2048, 512]
__device__ char g_Wp[(size_t)2 * 4 * 8 * SLOT];         // Wk|Wv [512, 512]
__device__ char g_Kp[(size_t)4 * 16 * 8 * SLOT];        // K per b: [2048, 512]
__device__ char g_Vp[(size_t)4 * 4 * 32 * SLOT];        // V^T per b: [512, 2048]
__device__ char g_Ap[(size_t)4 * 70 * 32 * SLOT];       // attn per b: [8960, 2048]

// ---------------------------------------------------------------------------
// helpers
// ---------------------------------------------------------------------------
__device__ __forceinline__ uint32_t smem_to_u32(const void* p) {
    uint32_t a;
    asm("{ .reg .u64 t; cvta.to.shared.u64 t, %1; cvt.u32.u64 %0, t; }" : "=r"(a) : "l"(p));
    return a;
}
__device__ __forceinline__ uint32_t swz(uint32_t off) { return off ^ ((off >> 3) & 0x70); }

__device__ __forceinline__ void bulk_g2s(uint32_t dst, const void* src, uint32_t bytes, uint32_t mbar) {
    asm volatile("cp.async.bulk.shared::cta.global.mbarrier::complete_tx::bytes [%0], [%1], %2, [%3];"
        :: "r"(dst), "l"(src), "r"(bytes), "r"(mbar) : "memory");
}
#define MBARRIER_INIT(mbar, count) \
    asm volatile("mbarrier.init.shared.b64 [%0], %1;" :: "r"((uint32_t)(mbar)), "r"((uint32_t)(count)) : "memory")
#define MBARRIER_EXPECT_TX(mbar, bytes) \
    asm volatile("mbarrier.arrive.expect_tx.shared.b64 _, [%0], %1;" :: "r"((uint32_t)(mbar)), "r"((uint32_t)(bytes)) : "memory")
#define MBARRIER_WAIT_PARITY(mbar, parity) do { \
    uint32_t _m = (uint32_t)(mbar), _p = (uint32_t)(parity), _d; \
    asm volatile("{\n\t.reg .pred p;\n\t" \
        "mbarrier.try_wait.parity.acquire.cta.shared::cta.b64 p, [%1], %2;\n\t" \
        "selp.b32 %0, 1, 0, p;\n\t}" : "=r"(_d) : "r"(_m), "r"(_p) : "memory"); \
    if (!_d) { \
        asm volatile("{\n\t.reg .pred P1;\n\t" \
            "WL_%=:\n\t" \
            "mbarrier.try_wait.parity.acquire.cta.shared::cta.b64 P1, [%0], %1, 0x989680;\n\t" \
            "@P1 bra.uni WD_%=;\n\t" \
            "bra.uni WL_%=;\n\t" \
            "WD_%=:\n\t}" :: "r"(_m), "r"(_p) : "memory"); \
    } \
} while (0)

__device__ __forceinline__ void mma_bf16(float* d, const uint32_t* a, const uint32_t* b) {
    asm("mma.sync.aligned.m16n8k16.row.col.f32.bf16.bf16.f32 "
        "{%0,%1,%2,%3}, {%4,%5,%6,%7}, {%8,%9}, {%0,%1,%2,%3};"
        : "+f"(d[0]), "+f"(d[1]), "+f"(d[2]), "+f"(d[3])
        : "r"(a[0]), "r"(a[1]), "r"(a[2]), "r"(a[3]), "r"(b[0]), "r"(b[1]));
}
__device__ __forceinline__ void ldmx4(uint32_t* r, uint32_t addr) {
    asm volatile("ldmatrix.sync.aligned.m8n8.x4.shared.b16 {%0,%1,%2,%3}, [%4];"
        : "=r"(r[0]), "=r"(r[1]), "=r"(r[2]), "=r"(r[3]) : "r"(addr));
}
__device__ __forceinline__ float elu_f(float x) { return x > 0.f ? x : expm1f(x); }
__device__ __forceinline__ void split_bf16(float x, __nv_bfloat16& hi, __nv_bfloat16& lo) {
    hi = __float2bfloat16(x);
    lo = __float2bfloat16(x - __bfloat162float(hi));
}

// ===========================================================================
// GEMM config: CTA tile 128x128, TK=64, double-buffered 64KB stages via
// cp.async.bulk, 8 warps (warp tile 64x32), 1 CTA/SM.
// smem: [align 1KB][stage0 64KB][stage1 64KB][2 mbarriers]
// ===========================================================================
#define TM 128
#define TN 128
#define TKB 64
#define STAGE_SM 65536
#define DSMEM (1024 + 2 * STAGE_SM + 32)

// slot index helper: base + (b*bs + (tile)*kbn + kb) * SLOT
#define SLOT_PTR(base, bz, bs, tile, kbn, kb) \
    ((base) + ((size_t)(bz) * (bs) + (size_t)(tile) * (kbn) + (kb)) * SLOT)

// ---------------------------------------------------------------------------
// Main GEMM: C[m,n] = sum_k A[m,k]*B[n,k], fp32 output with M guard.
// ---------------------------------------------------------------------------
__global__ __launch_bounds__(256) void gemm_bulk(
    const char* __restrict__ Ap, int bsA,
    const char* __restrict__ Bp, int bsB,
    float* __restrict__ C, int ldc, size_t sC,
    int kbn, int Mtotal)
{
    extern __shared__ char smem_raw[];
    const uint32_t base = (smem_to_u32(smem_raw) + 1023) & ~1023u;
    const uint32_t mbar = base + 2 * STAGE_SM;

    const int t    = threadIdx.x;
    const int wid  = t >> 5, lane = t & 31;
    const int gid  = lane >> 2, tig = lane & 3;
    const int bz   = blockIdx.z;
    const int m0   = blockIdx.y * TM;
    const int n0   = blockIdx.x * TN;

    C += (size_t)bz * sC;

    const int wm0 = (wid & 1) * 64;
    const int wn0 = (wid >> 1) * 32;

    float acc[4][4][4];
#pragma unroll
    for (int i = 0; i < 4; i++)
#pragma unroll
        for (int j = 0; j < 4; j++)
#pragma unroll
            for (int q = 0; q < 4; q++) acc[i][j][q] = 0.f;

    if (t == 0) { MBARRIER_INIT(mbar, 1); MBARRIER_INIT(mbar + 8, 1); }
    __syncthreads();

    auto issue = [&](int kb, int stg) {
        if (t == 0) {
            uint32_t bar = mbar + 8 * stg;
            MBARRIER_EXPECT_TX(bar, 2 * SLOT);
            bulk_g2s(base + stg * STAGE_SM,
                     SLOT_PTR(Ap, bz, bsA, m0 >> 7, kbn, kb), SLOT, bar);
            bulk_g2s(base + stg * STAGE_SM + SLOT,
                     SLOT_PTR(Bp, bz, bsB, n0 >> 7, kbn, kb), SLOT, bar);
        }
    };

    const int arow = lane & 15;
    const int aoff = (lane >> 4) * 16;
    const int bprow = ((lane >> 4) & 1) * 8 + (lane & 7);
    const int bpoff = ((lane >> 3) & 1) * 16;

    issue(0, 0);

    for (int kb = 0; kb < kbn; kb++) {
        if (kb + 1 < kbn) issue(kb + 1, (kb + 1) & 1);
        MBARRIER_WAIT_PARITY(mbar + 8 * (kb & 1), (kb >> 1) & 1);

        const uint32_t sb = base + (kb & 1) * STAGE_SM;

#pragma unroll
        for (int ks = 0; ks < 4; ks++) {
            uint32_t ah[4][4], al[4][4];
#pragma unroll
            for (int mt = 0; mt < 4; mt++) {
                uint32_t off = swz((wm0 + mt * 16 + arow) * 128 + ks * 32 + aoff);
                ldmx4(ah[mt], sb + off);
                ldmx4(al[mt], sb + HSUB + off);
            }
#pragma unroll
            for (int p = 0; p < 2; p++) {
                uint32_t offb = swz((wn0 + p * 16 + bprow) * 128 + ks * 32 + bpoff);
                uint32_t bh4[4], bl4[4];
                ldmx4(bh4, sb + SLOT + offb);
                ldmx4(bl4, sb + SLOT + HSUB + offb);
#pragma unroll
                for (int mt = 0; mt < 4; mt++)
#pragma unroll
                    for (int h = 0; h < 2; h++)
                        mma_bf16(acc[mt][2 * p + h], ah[mt], bh4 + 2 * h);
#pragma unroll
                for (int mt = 0; mt < 4; mt++)
#pragma unroll
                    for (int h = 0; h < 2; h++)
                        mma_bf16(acc[mt][2 * p + h], ah[mt], bl4 + 2 * h);
#pragma unroll
                for (int mt = 0; mt < 4; mt++)
#pragma unroll
                    for (int h = 0; h < 2; h++)
                        mma_bf16(acc[mt][2 * p + h], al[mt], bh4 + 2 * h);
            }
        }
        __syncthreads();
    }

#pragma unroll
    for (int mt = 0; mt < 4; mt++) {
        int r0 = m0 + wm0 + mt * 16 + gid;
#pragma unroll
        for (int nt = 0; nt < 4; nt++) {
            int c0 = n0 + wn0 + nt * 8 + 2 * tig;
            if (r0 < Mtotal)
                *(float2*)(C + (size_t)r0 * ldc + c0) =
                    make_float2(acc[mt][nt][0], acc[mt][nt][1]);
            if (r0 + 8 < Mtotal)
                *(float2*)(C + (size_t)(r0 + 8) * ldc + c0) =
                    make_float2(acc[mt][nt][2], acc[mt][nt][3]);
        }
    }
}

// ---------------------------------------------------------------------------
// KV GEMM: same core; epilogue = bias + ELU + bf16 split into PACKED output.
// All dims exact multiples of tile sizes.
// ---------------------------------------------------------------------------
__global__ __launch_bounds__(256) void kv_gemm_bulk(
    const char* __restrict__ Ap, int bsA,
    const char* __restrict__ Bp, int bsB,
    char* __restrict__ Op, int bsO, int kbO,
    const float* __restrict__ bias, int biasRow,
    int kbn)
{
    extern __shared__ char smem_raw[];
    const uint32_t base = (smem_to_u32(smem_raw) + 1023) & ~1023u;
    const uint32_t mbar = base + 2 * STAGE_SM;

    const int t    = threadIdx.x;
    const int wid  = t >> 5, lane = t & 31;
    const int gid  = lane >> 2, tig = lane & 3;
    const int bz   = blockIdx.z;
    const int m0   = blockIdx.y * TM;
    const int n0   = blockIdx.x * TN;

    const int wm0 = (wid & 1) * 64;
    const int wn0 = (wid >> 1) * 32;

    float acc[4][4][4];
#pragma unroll
    for (int i = 0; i < 4; i++)
#pragma unroll
        for (int j = 0; j < 4; j++)
#pragma unroll
            for (int q = 0; q < 4; q++) acc[i][j][q] = 0.f;

    if (t == 0) { MBARRIER_INIT(mbar, 1); MBARRIER_INIT(mbar + 8, 1); }
    __syncthreads();

    auto issue = [&](int kb, int stg) {
        if (t == 0) {
            uint32_t bar = mbar + 8 * stg;
            MBARRIER_EXPECT_TX(bar, 2 * SLOT);
            bulk_g2s(base + stg * STAGE_SM,
                     SLOT_PTR(Ap, bz, bsA, m0 >> 7, kbn, kb), SLOT, bar);
            bulk_g2s(base + stg * STAGE_SM + SLOT,
                     SLOT_PTR(Bp, bz, bsB, n0 >> 7, kbn, kb), SLOT, bar);
        }
    };

    const int arow = lane & 15;
    const int aoff = (lane >> 4) * 16;
    const int bprow = ((lane >> 4) & 1) * 8 + (lane & 7);
    const int bpoff = ((lane >> 3) & 1) * 16;

    issue(0, 0);

    for (int kb = 0; kb < kbn; kb++) {
        if (kb + 1 < kbn) issue(kb + 1, (kb + 1) & 1);
        MBARRIER_WAIT_PARITY(mbar + 8 * (kb & 1), (kb >> 1) & 1);

        const uint32_t sb = base + (kb & 1) * STAGE_SM;

#pragma unroll
        for (int ks = 0; ks < 4; ks++) {
            uint32_t ah[4][4], al[4][4];
#pragma unroll
            for (int mt = 0; mt < 4; mt++) {
                uint32_t off = swz((wm0 + mt * 16 + arow) * 128 + ks * 32 + aoff);
                ldmx4(ah[mt], sb + off);
                ldmx4(al[mt], sb + HSUB + off);
            }
#pragma unroll
            for (int p = 0; p < 2; p++) {
                uint32_t offb = swz((wn0 + p * 16 + bprow) * 128 + ks * 32 + bpoff);
                uint32_t bh4[4], bl4[4];
                ldmx4(bh4, sb + SLOT + offb);
                ldmx4(bl4, sb + SLOT + HSUB + offb);
#pragma unroll
                for (int mt = 0; mt < 4; mt++)
#pragma unroll
                    for (int h = 0; h < 2; h++)
                        mma_bf16(acc[mt][2 * p + h], ah[mt], bh4 + 2 * h);
#pragma unroll
                for (int mt = 0; mt < 4; mt++)
#pragma unroll
                    for (int h = 0; h < 2; h++)
                        mma_bf16(acc[mt][2 * p + h], ah[mt], bl4 + 2 * h);
#pragma unroll
                for (int mt = 0; mt < 4; mt++)
#pragma unroll
                    for (int h = 0; h < 2; h++)
                        mma_bf16(acc[mt][2 * p + h], al[mt], bh4 + 2 * h);
            }
        }
        __syncthreads();
    }

    // epilogue: packed-swizzled bf16 hi/lo writes
#pragma unroll
    for (int mt = 0; mt < 4; mt++) {
#pragma unroll
        for (int half = 0; half < 2; half++) {
            int m = m0 + wm0 + mt * 16 + gid + half * 8;
#pragma unroll
            for (int nt = 0; nt < 4; nt++) {
                int n = n0 + wn0 + nt * 8 + 2 * tig;
                float v0 = acc[mt][nt][2 * half + 0];
                float v1 = acc[mt][nt][2 * half + 1];
                float b0 = biasRow ? bias[m] : bias[n];
                float b1 = biasRow ? bias[m] : bias[n + 1];
                __nv_bfloat16 h0, l0, h1, l1;
                split_bf16(elu_f(v0 + b0), h0, l0);
                split_bf16(elu_f(v1 + b1), h1, l1);
                char* slot = Op + ((size_t)bz * bsO + (size_t)(m >> 7) * kbO + (n >> 6)) * SLOT;
                uint32_t off = swz((uint32_t)(m & 127) * 128 + (uint32_t)(n & 63) * 2);
                *(__nv_bfloat162*)(slot + off)        = __nv_bfloat162(h0, h1);
                *(__nv_bfloat162*)(slot + HSUB + off) = __nv_bfloat162(l0, l1);
            }
        }
    }
}

// ===========================================================================
// Packers
// ===========================================================================
// Q [L,D] fp32 -> g_Qp packed (8960 rows, clamped)
__global__ __launch_bounds__(256) void pack_q(const float* __restrict__ Q)
{
    int row = blockIdx.x;                     // 0..8959
    int src = row < L_ ? row : L_ - 1;
    int t = threadIdx.x;
    float2 v = *(const float2*)(Q + (size_t)src * D_ + t * 2);
    __nv_bfloat16 h0, l0, h1, l1;
    split_bf16(v.x, h0, l0);
    split_bf16(v.y, h1, l1);
    int r = row & 127, tile = row >> 7;
    int d0 = t * 2, kb = d0 >> 6, c = d0 & 63;
    char* slot = g_Qp + ((size_t)tile * 8 + kb) * SLOT;
    uint32_t off = swz((uint32_t)r * 128 + (uint32_t)c * 2);
    *(__nv_bfloat162*)(slot + off)        = __nv_bfloat162(h0, h1);
    *(__nv_bfloat162*)(slot + HSUB + off) = __nv_bfloat162(l0, l1);
}

// H [b,d,s] -> g_Hp packed over (s-tile, d-kb). grid (S/32, D/64, B), block (32,8)
__global__ __launch_bounds__(256) void pack_h(const float* __restrict__ H)
{
    __shared__ float tile[64][33];
    const int b = blockIdx.z, s0 = blockIdx.x * 32, d0 = blockIdx.y * 64;
    const int tx = threadIdx.x, ty = threadIdx.y;
    const float* Hb = H + ((size_t)b * D_ + d0) * S_ + s0;

#pragma unroll
    for (int i = 0; i < 8; i++)
        tile[ty * 8 + i][tx] = Hb[(size_t)(ty * 8 + i) * S_ + tx];
    __syncthreads();

    const int t = ty * 32 + tx;
    const int s = t & 31;            // local s
    const int dp = t >> 5;           // d-pair group 0..7
    const int gs = s0 + s;
    const int r = gs & 127;
    char* slot = g_Hp + (((size_t)b * 16 + (gs >> 7)) * 8 + blockIdx.y) * SLOT;
#pragma unroll
    for (int i = 0; i < 4; i++) {
        int d = dp * 2 + i * 16;     // 0..62 even
        __nv_bfloat16 h0, l0, h1, l1;
        split_bf16(tile[d][s], h0, l0);
        split_bf16(tile[d + 1][s], h1, l1);
        uint32_t off = swz((uint32_t)r * 128 + (uint32_t)d * 2);
        *(__nv_bfloat162*)(slot + off)        = __nv_bfloat162(h0, h1);
        *(__nv_bfloat162*)(slot + HSUB + off) = __nv_bfloat162(l0, l1);
    }
}

// Wk, Wv [512,512] -> g_Wp packed. grid 1024 (2 mats x 512 rows)
__global__ __launch_bounds__(256) void pack_w(
    const float* __restrict__ Wk, const float* __restrict__ Wv)
{
    int which = blockIdx.x >> 9;
    int o = blockIdx.x & 511;
    const float* W = which ? Wv : Wk;
    int t = threadIdx.x;
    float2 v = *(const float2*)(W + (size_t)o * D_ + t * 2);
    __nv_bfloat16 h0, l0, h1, l1;
    split_bf16(v.x, h0, l0);
    split_bf16(v.y, h1, l1);
    int r = o & 127, tile = o >> 7;
    int d0 = t * 2, kb = d0 >> 6, c = d0 & 63;
    char* slot = g_Wp + (((size_t)which * 4 + tile) * 8 + kb) * SLOT;
    uint32_t off = swz((uint32_t)r * 128 + (uint32_t)c * 2);
    *(__nv_bfloat162*)(slot + off)        = __nv_bfloat162(h0, h1);
    *(__nv_bfloat162*)(slot + HSUB + off) = __nv_bfloat162(l0, l1);
}

// ===========================================================================
// In-place row softmax over S=2048; emits packed bf16 hi/lo of A.
// ===========================================================================
__global__ __launch_bounds__(256) void softmax_kernel(float* __restrict__ A)
{
    const int row = blockIdx.x;               // b*L + l
    const int b = row / L_;
    const int l = row - b * L_;
    float* p = A + (size_t)row * S_;
    const int t = threadIdx.x;
    const int lane = t & 31, wid = t >> 5;

    float4 va = *(const float4*)(p + t * 4);
    float4 vb = *(const float4*)(p + 1024 + t * 4);

    float m = fmaxf(fmaxf(fmaxf(va.x, va.y), fmaxf(va.z, va.w)),
                    fmaxf(fmaxf(vb.x, vb.y), fmaxf(vb.z, vb.w)));
#pragma unroll
    for (int o = 16; o > 0; o >>= 1) m = fmaxf(m, __shfl_xor_sync(0xffffffffu, m, o));

    __shared__ float red[8];
    if (lane == 0) red[wid] = m;
    __syncthreads();
    {
        float r = red[lane & 7];
#pragma unroll
        for (int o = 4; o > 0; o >>= 1) r = fmaxf(r, __shfl_xor_sync(0xffffffffu, r, o));
        m = r;
    }

    va.x = __expf(va.x - m); va.y = __expf(va.y - m);
    va.z = __expf(va.z - m); va.w = __expf(va.w - m);
    vb.x = __expf(vb.x - m); vb.y = __expf(vb.y - m);
    vb.z = __expf(vb.z - m); vb.w = __expf(vb.w - m);

    float s = va.x + va.y + va.z + va.w + vb.x + vb.y + vb.z + vb.w;
#pragma unroll
    for (int o = 16; o > 0; o >>= 1) s += __shfl_xor_sync(0xffffffffu, s, o);
    __syncthreads();
    if (lane == 0) red[wid] = s;
    __syncthreads();
    {
        float r = red[lane & 7];
#pragma unroll
        for (int o = 4; o > 0; o >>= 1) r += __shfl_xor_sync(0xffffffffu, r, o);
        s = r;
    }
    float inv = 1.f / s;

    va.x *= inv; va.y *= inv; va.z *= inv; va.w *= inv;
    vb.x *= inv; vb.y *= inv; vb.z *= inv; vb.w *= inv;

    *(float4*)(p + t * 4) = va;
    *(float4*)(p + 1024 + t * 4) = vb;

    // packed hi/lo writes
    char* tslot = g_Ap + ((size_t)b * (70 * 32) + (size_t)(l >> 7) * 32) * SLOT;
    const uint32_t r = l & 127;

    float g[2][4] = {{va.x, va.y, va.z, va.w}, {vb.x, vb.y, vb.z, vb.w}};
#pragma unroll
    for (int half = 0; half < 2; half++) {
        int sidx = half * 1024 + t * 4;
        int kb = sidx >> 6, c = sidx & 63;
        char* slot = tslot + (size_t)kb * SLOT;
        uint32_t off = swz(r * 128 + (uint32_t)c * 2);
        __nv_bfloat16 h0, l0, h1, l1, h2, l2, h3, l3;
        split_bf16(g[half][0], h0, l0);
        split_bf16(g[half][1], h1, l1);
        split_bf16(g[half][2], h2, l2);
        split_bf16(g[half][3], h3, l3);
        *(__nv_bfloat162*)(slot + off)            = __nv_bfloat162(h0, h1);
        *(__nv_bfloat162*)(slot + off + 4)        = __nv_bfloat162(h2, h3);
        *(__nv_bfloat162*)(slot + HSUB + off)     = __nv_bfloat162(l0, l1);
        *(__nv_bfloat162*)(slot + HSUB + off + 4) = __nv_bfloat162(l2, l3);
    }
}

// ===========================================================================
extern "C" void kernel_launch(void* const* d_in, const int* in_sizes, int n_in,
                              void* d_out, int out_size)
{
    const float* H  = (const float*)d_in[0];
    const float* Wk = (const float*)d_in[1];
    const float* bk = (const float*)d_in[2];
    const float* Wv = (const float*)d_in[3];
    const float* bv = (const float*)d_in[4];
    const float* Q  = (const float*)d_in[5];

    float* out  = (float*)d_out;
    float* Cout = out;                          // [B, L, D]
    float* Aout = out + (size_t)B_ * L_ * D_;   // [B, L, S]

    static char *gQp, *gHp, *gWp, *gKp, *gVp, *gAp;
    static bool init = false;
    if (!init) {
        cudaGetSymbolAddress((void**)&gQp, g_Qp);
        cudaGetSymbolAddress((void**)&gHp, g_Hp);
        cudaGetSymbolAddress((void**)&gWp, g_Wp);
        cudaGetSymbolAddress((void**)&gKp, g_Kp);
        cudaGetSymbolAddress((void**)&gVp, g_Vp);
        cudaGetSymbolAddress((void**)&gAp, g_Ap);
        cudaFuncSetAttribute(gemm_bulk, cudaFuncAttributeMaxDynamicSharedMemorySize, DSMEM);
        cudaFuncSetAttribute(kv_gemm_bulk, cudaFuncAttributeMaxDynamicSharedMemorySize, DSMEM);
        init = true;
    }

    // 0) packers
    pack_q<<<8960, 256>>>(Q);
    pack_h<<<dim3(S_ / 32, D_ / 64, B_), dim3(32, 8)>>>(H);
    pack_w<<<1024, 256>>>(Wk, Wv);

    // 1a) K = H^T * Wk   (M=S tiles 16, N=D, K=D; out packed over (s-tile, o-kb))
    kv_gemm_bulk<<<dim3(D_ / TN, S_ / TM, B_), 256, DSMEM>>>(
        gHp, 128, gWp, 0,
        gKp, 128, 8, bk, 0, 8);

    // 1b) V^T = Wv * H^T (M=D tiles 4, N=S; out packed over (o-tile, s-kb))
    kv_gemm_bulk<<<dim3(S_ / TN, D_ / TM, B_), 256, DSMEM>>>(
        gWp + (size_t)32 * SLOT, 0, gHp, 128,
        gVp, 128, 32, bv, 1, 8);

    // 2) E = Q K^T -> Aout (fp32)
    gemm_bulk<<<dim3(S_ / TN, 70, B_), 256, DSMEM>>>(
        gQp, 0, gKp, 128,
        Aout, S_, (size_t)L_ * S_, 8, L_);

    // 3) softmax (+ packed split of A)
    softmax_kernel<<<dim3(B_ * L_), 256>>>(Aout);

    // 4) C = A V -> Cout
    gemm_bulk<<<dim3(D_ / TN, 70, B_), 256, DSMEM>>>(
        gAp, 70 * 32, gVp, 128,
        Cout, D_, (size_t)L_ * D_, 32, L_);
}

// round 11
// speedup vs baseline: 1.4359x; 1.0985x over previous
#include <cuda_runtime.h>
#include <cuda_bf16.h>
#include <math.h>
#include <cstdint>

#define B_ 4
#define D_ 512
#define S_ 2048
#define L_ 8921

#define SLOT 16384              // packed (tile128 x k32) slot: hi 8KB | lo 8KB
#define HSUB 8192

// Packed operand buffers (swizzled tiles, bulk-copy ready)
__device__ char g_Qp[(size_t)70 * 16 * SLOT];            // Q  [8960, 512]
__device__ char g_Hp[(size_t)4 * 16 * 16 * SLOT];        // H^T per b: [2048, 512]
__device__ char g_Wp[(size_t)2 * 4 * 16 * SLOT];         // Wk|Wv [512, 512]
__device__ char g_Kp[(size_t)4 * 16 * 16 * SLOT];        // K per b: [2048, 512]
__device__ char g_Vp[(size_t)4 * 4 * 64 * SLOT];         // V^T per b: [512, 2048]
__device__ char g_Ap[(size_t)4 * 70 * 64 * SLOT];        // attn per b: [8960, 2048]

// ---------------------------------------------------------------------------
// helpers
// ---------------------------------------------------------------------------
__device__ __forceinline__ uint32_t smem_to_u32(const void* p) {
    uint32_t a;
    asm("{ .reg .u64 t; cvta.to.shared.u64 t, %1; cvt.u32.u64 %0, t; }" : "=r"(a) : "l"(p));
    return a;
}
// SW64 swizzle for 64B rows: XOR bits[5:4] with row bits (off bits [9:8] -> [5:4])
__device__ __forceinline__ uint32_t swz(uint32_t off) { return off ^ ((off >> 3) & 0x30); }

__device__ __forceinline__ void bulk_g2s(uint32_t dst, const void* src, uint32_t bytes, uint32_t mbar) {
    asm volatile("cp.async.bulk.shared::cta.global.mbarrier::complete_tx::bytes [%0], [%1], %2, [%3];"
        :: "r"(dst), "l"(src), "r"(bytes), "r"(mbar) : "memory");
}
#define MBARRIER_INIT(mbar, count) \
    asm volatile("mbarrier.init.shared.b64 [%0], %1;" :: "r"((uint32_t)(mbar)), "r"((uint32_t)(count)) : "memory")
#define MBARRIER_EXPECT_TX(mbar, bytes) \
    asm volatile("mbarrier.arrive.expect_tx.shared.b64 _, [%0], %1;" :: "r"((uint32_t)(mbar)), "r"((uint32_t)(bytes)) : "memory")
#define MBARRIER_WAIT_PARITY(mbar, parity) do { \
    uint32_t _m = (uint32_t)(mbar), _p = (uint32_t)(parity), _d; \
    asm volatile("{\n\t.reg .pred p;\n\t" \
        "mbarrier.try_wait.parity.acquire.cta.shared::cta.b64 p, [%1], %2;\n\t" \
        "selp.b32 %0, 1, 0, p;\n\t}" : "=r"(_d) : "r"(_m), "r"(_p) : "memory"); \
    if (!_d) { \
        asm volatile("{\n\t.reg .pred P1;\n\t" \
            "WL_%=:\n\t" \
            "mbarrier.try_wait.parity.acquire.cta.shared::cta.b64 P1, [%0], %1, 0x989680;\n\t" \
            "@P1 bra.uni WD_%=;\n\t" \
            "bra.uni WL_%=;\n\t" \
            "WD_%=:\n\t}" :: "r"(_m), "r"(_p) : "memory"); \
    } \
} while (0)

__device__ __forceinline__ void mma_bf16(float* d, const uint32_t* a, const uint32_t* b) {
    asm("mma.sync.aligned.m16n8k16.row.col.f32.bf16.bf16.f32 "
        "{%0,%1,%2,%3}, {%4,%5,%6,%7}, {%8,%9}, {%0,%1,%2,%3};"
        : "+f"(d[0]), "+f"(d[1]), "+f"(d[2]), "+f"(d[3])
        : "r"(a[0]), "r"(a[1]), "r"(a[2]), "r"(a[3]), "r"(b[0]), "r"(b[1]));
}
__device__ __forceinline__ void ldmx4(uint32_t* r, uint32_t addr) {
    asm volatile("ldmatrix.sync.aligned.m8n8.x4.shared.b16 {%0,%1,%2,%3}, [%4];"
        : "=r"(r[0]), "=r"(r[1]), "=r"(r[2]), "=r"(r[3]) : "r"(addr));
}
__device__ __forceinline__ float elu_f(float x) { return x > 0.f ? x : expm1f(x); }
__device__ __forceinline__ void split_bf16(float x, __nv_bfloat16& hi, __nv_bfloat16& lo) {
    hi = __float2bfloat16(x);
    lo = __float2bfloat16(x - __bfloat162float(hi));
}

// ===========================================================================
// GEMM config: CTA tile 128x128, TK=32, double-buffered 32KB stages via
// cp.async.bulk, 8 warps (warp tile 64x32), 2 CTAs/SM.
// smem: [align 1KB][stage0 32KB][stage1 32KB][2 mbarriers]
// ===========================================================================
#define TM 128
#define TN 128
#define STAGE_SM 32768
#define DSMEM (1024 + 2 * STAGE_SM + 32)

#define SLOT_PTR(base, bz, bs, tile, kbn, kb) \
    ((base) + ((size_t)(bz) * (bs) + (size_t)(tile) * (kbn) + (kb)) * SLOT)

// ---------------------------------------------------------------------------
// Main GEMM: C[m,n] = sum_k A[m,k]*B[n,k], fp32 output with M guard.
// ---------------------------------------------------------------------------
__global__ __launch_bounds__(256, 2) void gemm_bulk(
    const char* __restrict__ Ap, int bsA,
    const char* __restrict__ Bp, int bsB,
    float* __restrict__ C, int ldc, size_t sC,
    int kbn, int Mtotal)
{
    extern __shared__ char smem_raw[];
    const uint32_t base = (smem_to_u32(smem_raw) + 1023) & ~1023u;
    const uint32_t mbar = base + 2 * STAGE_SM;

    const int t    = threadIdx.x;
    const int wid  = t >> 5, lane = t & 31;
    const int gid  = lane >> 2, tig = lane & 3;
    const int bz   = blockIdx.z;
    const int m0   = blockIdx.y * TM;
    const int n0   = blockIdx.x * TN;

    C += (size_t)bz * sC;

    const int wm0 = (wid & 1) * 64;
    const int wn0 = (wid >> 1) * 32;

    float acc[4][4][4];
#pragma unroll
    for (int i = 0; i < 4; i++)
#pragma unroll
        for (int j = 0; j < 4; j++)
#pragma unroll
            for (int q = 0; q < 4; q++) acc[i][j][q] = 0.f;

    if (t == 0) { MBARRIER_INIT(mbar, 1); MBARRIER_INIT(mbar + 8, 1); }
    __syncthreads();

    auto issue = [&](int kb, int stg) {
        if (t == 0) {
            uint32_t bar = mbar + 8 * stg;
            MBARRIER_EXPECT_TX(bar, 2 * SLOT);
            bulk_g2s(base + stg * STAGE_SM,
                     SLOT_PTR(Ap, bz, bsA, m0 >> 7, kbn, kb), SLOT, bar);
            bulk_g2s(base + stg * STAGE_SM + SLOT,
                     SLOT_PTR(Bp, bz, bsB, n0 >> 7, kbn, kb), SLOT, bar);
        }
    };

    const int arow = lane & 15;
    const int aoff = (lane >> 4) * 16;
    const int bprow = ((lane >> 4) & 1) * 8 + (lane & 7);
    const int bpoff = ((lane >> 3) & 1) * 16;

    issue(0, 0);

    for (int kb = 0; kb < kbn; kb++) {
        if (kb + 1 < kbn) issue(kb + 1, (kb + 1) & 1);
        MBARRIER_WAIT_PARITY(mbar + 8 * (kb & 1), (kb >> 1) & 1);

        const uint32_t sb = base + (kb & 1) * STAGE_SM;

#pragma unroll
        for (int ks = 0; ks < 2; ks++) {
            uint32_t ah[4][4], al[4][4];
#pragma unroll
            for (int mt = 0; mt < 4; mt++) {
                uint32_t off = swz((wm0 + mt * 16 + arow) * 64 + ks * 32 + aoff);
                ldmx4(ah[mt], sb + off);
                ldmx4(al[mt], sb + HSUB + off);
            }
#pragma unroll
            for (int p = 0; p < 2; p++) {
                uint32_t offb = swz((wn0 + p * 16 + bprow) * 64 + ks * 32 + bpoff);
                uint32_t bh4[4], bl4[4];
                ldmx4(bh4, sb + SLOT + offb);
                ldmx4(bl4, sb + SLOT + HSUB + offb);
#pragma unroll
                for (int mt = 0; mt < 4; mt++)
#pragma unroll
                    for (int h = 0; h < 2; h++)
                        mma_bf16(acc[mt][2 * p + h], ah[mt], bh4 + 2 * h);
#pragma unroll
                for (int mt = 0; mt < 4; mt++)
#pragma unroll
                    for (int h = 0; h < 2; h++)
                        mma_bf16(acc[mt][2 * p + h], ah[mt], bl4 + 2 * h);
#pragma unroll
                for (int mt = 0; mt < 4; mt++)
#pragma unroll
                    for (int h = 0; h < 2; h++)
                        mma_bf16(acc[mt][2 * p + h], al[mt], bh4 + 2 * h);
            }
        }
        __syncthreads();
    }

#pragma unroll
    for (int mt = 0; mt < 4; mt++) {
        int r0 = m0 + wm0 + mt * 16 + gid;
#pragma unroll
        for (int nt = 0; nt < 4; nt++) {
            int c0 = n0 + wn0 + nt * 8 + 2 * tig;
            if (r0 < Mtotal)
                *(float2*)(C + (size_t)r0 * ldc + c0) =
                    make_float2(acc[mt][nt][0], acc[mt][nt][1]);
            if (r0 + 8 < Mtotal)
                *(float2*)(C + (size_t)(r0 + 8) * ldc + c0) =
                    make_float2(acc[mt][nt][2], acc[mt][nt][3]);
        }
    }
}

// ---------------------------------------------------------------------------
// KV GEMM: same core; epilogue = bias + ELU + bf16 split into PACKED output.
// ---------------------------------------------------------------------------
__global__ __launch_bounds__(256, 2) void kv_gemm_bulk(
    const char* __restrict__ Ap, int bsA,
    const char* __restrict__ Bp, int bsB,
    char* __restrict__ Op, int bsO, int kbO,
    const float* __restrict__ bias, int biasRow,
    int kbn)
{
    extern __shared__ char smem_raw[];
    const uint32_t base = (smem_to_u32(smem_raw) + 1023) & ~1023u;
    const uint32_t mbar = base + 2 * STAGE_SM;

    const int t    = threadIdx.x;
    const int wid  = t >> 5, lane = t & 31;
    const int gid  = lane >> 2, tig = lane & 3;
    const int bz   = blockIdx.z;
    const int m0   = blockIdx.y * TM;
    const int n0   = blockIdx.x * TN;

    const int wm0 = (wid & 1) * 64;
    const int wn0 = (wid >> 1) * 32;

    float acc[4][4][4];
#pragma unroll
    for (int i = 0; i < 4; i++)
#pragma unroll
        for (int j = 0; j < 4; j++)
#pragma unroll
            for (int q = 0; q < 4; q++) acc[i][j][q] = 0.f;

    if (t == 0) { MBARRIER_INIT(mbar, 1); MBARRIER_INIT(mbar + 8, 1); }
    __syncthreads();

    auto issue = [&](int kb, int stg) {
        if (t == 0) {
            uint32_t bar = mbar + 8 * stg;
            MBARRIER_EXPECT_TX(bar, 2 * SLOT);
            bulk_g2s(base + stg * STAGE_SM,
                     SLOT_PTR(Ap, bz, bsA, m0 >> 7, kbn, kb), SLOT, bar);
            bulk_g2s(base + stg * STAGE_SM + SLOT,
                     SLOT_PTR(Bp, bz, bsB, n0 >> 7, kbn, kb), SLOT, bar);
        }
    };

    const int arow = lane & 15;
    const int aoff = (lane >> 4) * 16;
    const int bprow = ((lane >> 4) & 1) * 8 + (lane & 7);
    const int bpoff = ((lane >> 3) & 1) * 16;

    issue(0, 0);

    for (int kb = 0; kb < kbn; kb++) {
        if (kb + 1 < kbn) issue(kb + 1, (kb + 1) & 1);
        MBARRIER_WAIT_PARITY(mbar + 8 * (kb & 1), (kb >> 1) & 1);

        const uint32_t sb = base + (kb & 1) * STAGE_SM;

#pragma unroll
        for (int ks = 0; ks < 2; ks++) {
            uint32_t ah[4][4], al[4][4];
#pragma unroll
            for (int mt = 0; mt < 4; mt++) {
                uint32_t off = swz((wm0 + mt * 16 + arow) * 64 + ks * 32 + aoff);
                ldmx4(ah[mt], sb + off);
                ldmx4(al[mt], sb + HSUB + off);
            }
#pragma unroll
            for (int p = 0; p < 2; p++) {
                uint32_t offb = swz((wn0 + p * 16 + bprow) * 64 + ks * 32 + bpoff);
                uint32_t bh4[4], bl4[4];
                ldmx4(bh4, sb + SLOT + offb);
                ldmx4(bl4, sb + SLOT + HSUB + offb);
#pragma unroll
                for (int mt = 0; mt < 4; mt++)
#pragma unroll
                    for (int h = 0; h < 2; h++)
                        mma_bf16(acc[mt][2 * p + h], ah[mt], bh4 + 2 * h);
#pragma unroll
                for (int mt = 0; mt < 4; mt++)
#pragma unroll
                    for (int h = 0; h < 2; h++)
                        mma_bf16(acc[mt][2 * p + h], ah[mt], bl4 + 2 * h);
#pragma unroll
                for (int mt = 0; mt < 4; mt++)
#pragma unroll
                    for (int h = 0; h < 2; h++)
                        mma_bf16(acc[mt][2 * p + h], al[mt], bh4 + 2 * h);
            }
        }
        __syncthreads();
    }

    // epilogue: packed-swizzled bf16 hi/lo writes (kb granularity = 32 cols)
#pragma unroll
    for (int mt = 0; mt < 4; mt++) {
#pragma unroll
        for (int half = 0; half < 2; half++) {
            int m = m0 + wm0 + mt * 16 + gid + half * 8;
#pragma unroll
            for (int nt = 0; nt < 4; nt++) {
                int n = n0 + wn0 + nt * 8 + 2 * tig;
                float v0 = acc[mt][nt][2 * half + 0];
                float v1 = acc[mt][nt][2 * half + 1];
                float b0 = biasRow ? bias[m] : bias[n];
                float b1 = biasRow ? bias[m] : bias[n + 1];
                __nv_bfloat16 h0, l0, h1, l1;
                split_bf16(elu_f(v0 + b0), h0, l0);
                split_bf16(elu_f(v1 + b1), h1, l1);
                char* slot = Op + ((size_t)bz * bsO + (size_t)(m >> 7) * kbO + (n >> 5)) * SLOT;
                uint32_t off = swz((uint32_t)(m & 127) * 64 + (uint32_t)(n & 31) * 2);
                *(__nv_bfloat162*)(slot + off)        = __nv_bfloat162(h0, h1);
                *(__nv_bfloat162*)(slot + HSUB + off) = __nv_bfloat162(l0, l1);
            }
        }
    }
}

// ===========================================================================
// Packers
// ===========================================================================
// Q [L,D] fp32 -> g_Qp packed (8960 rows, clamped)
__global__ __launch_bounds__(256) void pack_q(const float* __restrict__ Q)
{
    int row = blockIdx.x;                     // 0..8959
    int src = row < L_ ? row : L_ - 1;
    int t = threadIdx.x;
    float2 v = *(const float2*)(Q + (size_t)src * D_ + t * 2);
    __nv_bfloat16 h0, l0, h1, l1;
    split_bf16(v.x, h0, l0);
    split_bf16(v.y, h1, l1);
    int r = row & 127, tile = row >> 7;
    int d0 = t * 2, kb = d0 >> 5, c = d0 & 31;
    char* slot = g_Qp + ((size_t)tile * 16 + kb) * SLOT;
    uint32_t off = swz((uint32_t)r * 64 + (uint32_t)c * 2);
    *(__nv_bfloat162*)(slot + off)        = __nv_bfloat162(h0, h1);
    *(__nv_bfloat162*)(slot + HSUB + off) = __nv_bfloat162(l0, l1);
}

// H [b,d,s] -> g_Hp packed over (s-tile, d-kb). grid (S/32, D/64, B), block (32,8)
__global__ __launch_bounds__(256) void pack_h(const float* __restrict__ H)
{
    __shared__ float tile[64][33];
    const int b = blockIdx.z, s0 = blockIdx.x * 32, d0 = blockIdx.y * 64;
    const int tx = threadIdx.x, ty = threadIdx.y;
    const float* Hb = H + ((size_t)b * D_ + d0) * S_ + s0;

#pragma unroll
    for (int i = 0; i < 8; i++)
        tile[ty * 8 + i][tx] = Hb[(size_t)(ty * 8 + i) * S_ + tx];
    __syncthreads();

    const int t = ty * 32 + tx;
    const int s = t & 31;
    const int dp = t >> 5;           // 0..7
    const int gs = s0 + s;
    const int r = gs & 127;
#pragma unroll
    for (int i = 0; i < 4; i++) {
        int d = dp * 2 + i * 16;     // even, 0..62
        int kbl = d >> 5, c = d & 31;
        char* slot = g_Hp + (((size_t)b * 16 + (gs >> 7)) * 16 + blockIdx.y * 2 + kbl) * SLOT;
        __nv_bfloat16 h0, l0, h1, l1;
        split_bf16(tile[d][s], h0, l0);
        split_bf16(tile[d + 1][s], h1, l1);
        uint32_t off = swz((uint32_t)r * 64 + (uint32_t)c * 2);
        *(__nv_bfloat162*)(slot + off)        = __nv_bfloat162(h0, h1);
        *(__nv_bfloat162*)(slot + HSUB + off) = __nv_bfloat162(l0, l1);
    }
}

// Wk, Wv [512,512] -> g_Wp packed. grid 1024 (2 mats x 512 rows)
__global__ __launch_bounds__(256) void pack_w(
    const float* __restrict__ Wk, const float* __restrict__ Wv)
{
    int which = blockIdx.x >> 9;
    int o = blockIdx.x & 511;
    const float* W = which ? Wv : Wk;
    int t = threadIdx.x;
    float2 v = *(const float2*)(W + (size_t)o * D_ + t * 2);
    __nv_bfloat16 h0, l0, h1, l1;
    split_bf16(v.x, h0, l0);
    split_bf16(v.y, h1, l1);
    int r = o & 127, tile = o >> 7;
    int d0 = t * 2, kb = d0 >> 5, c = d0 & 31;
    char* slot = g_Wp + (((size_t)which * 4 + tile) * 16 + kb) * SLOT;
    uint32_t off = swz((uint32_t)r * 64 + (uint32_t)c * 2);
    *(__nv_bfloat162*)(slot + off)        = __nv_bfloat162(h0, h1);
    *(__nv_bfloat162*)(slot + HSUB + off) = __nv_bfloat162(l0, l1);
}

// ===========================================================================
// In-place row softmax over S=2048; emits packed bf16 hi/lo of A.
// ===========================================================================
__global__ __launch_bounds__(256) void softmax_kernel(float* __restrict__ A)
{
    const int row = blockIdx.x;               // b*L + l
    const int b = row / L_;
    const int l = row - b * L_;
    float* p = A + (size_t)row * S_;
    const int t = threadIdx.x;
    const int lane = t & 31, wid = t >> 5;

    float4 va = *(const float4*)(p + t * 4);
    float4 vb = *(const float4*)(p + 1024 + t * 4);

    float m = fmaxf(fmaxf(fmaxf(va.x, va.y), fmaxf(va.z, va.w)),
                    fmaxf(fmaxf(vb.x, vb.y), fmaxf(vb.z, vb.w)));
#pragma unroll
    for (int o = 16; o > 0; o >>= 1) m = fmaxf(m, __shfl_xor_sync(0xffffffffu, m, o));

    __shared__ float red[8];
    if (lane == 0) red[wid] = m;
    __syncthreads();
    {
        float r = red[lane & 7];
#pragma unroll
        for (int o = 4; o > 0; o >>= 1) r = fmaxf(r, __shfl_xor_sync(0xffffffffu, r, o));
        m = r;
    }

    va.x = __expf(va.x - m); va.y = __expf(va.y - m);
    va.z = __expf(va.z - m); va.w = __expf(va.w - m);
    vb.x = __expf(vb.x - m); vb.y = __expf(vb.y - m);
    vb.z = __expf(vb.z - m); vb.w = __expf(vb.w - m);

    float s = va.x + va.y + va.z + va.w + vb.x + vb.y + vb.z + vb.w;
#pragma unroll
    for (int o = 16; o > 0; o >>= 1) s += __shfl_xor_sync(0xffffffffu, s, o);
    __syncthreads();
    if (lane == 0) red[wid] = s;
    __syncthreads();
    {
        float r = red[lane & 7];
#pragma unroll
        for (int o = 4; o > 0; o >>= 1) r += __shfl_xor_sync(0xffffffffu, r, o);
        s = r;
    }
    float inv = 1.f / s;

    va.x *= inv; va.y *= inv; va.z *= inv; va.w *= inv;
    vb.x *= inv; vb.y *= inv; vb.z *= inv; vb.w *= inv;

    *(float4*)(p + t * 4) = va;
    *(float4*)(p + 1024 + t * 4) = vb;

    char* tslot = g_Ap + ((size_t)b * (70 * 64) + (size_t)(l >> 7) * 64) * SLOT;
    const uint32_t r = l & 127;

    float g[2][4] = {{va.x, va.y, va.z, va.w}, {vb.x, vb.y, vb.z, vb.w}};
#pragma unroll
    for (int half = 0; half < 2; half++) {
        int sidx = half * 1024 + t * 4;
        int kb = sidx >> 5, c = sidx & 31;
        char* slot = tslot + (size_t)kb * SLOT;
        uint32_t off = swz(r * 64 + (uint32_t)c * 2);
        __nv_bfloat16 h0, l0, h1, l1, h2, l2, h3, l3;
        split_bf16(g[half][0], h0, l0);
        split_bf16(g[half][1], h1, l1);
        split_bf16(g[half][2], h2, l2);
        split_bf16(g[half][3], h3, l3);
        *(__nv_bfloat162*)(slot + off)            = __nv_bfloat162(h0, h1);
        *(__nv_bfloat162*)(slot + off + 4)        = __nv_bfloat162(h2, h3);
        *(__nv_bfloat162*)(slot + HSUB + off)     = __nv_bfloat162(l0, l1);
        *(__nv_bfloat162*)(slot + HSUB + off + 4) = __nv_bfloat162(l2, l3);
    }
}

// ===========================================================================
extern "C" void kernel_launch(void* const* d_in, const int* in_sizes, int n_in,
                              void* d_out, int out_size)
{
    const float* H  = (const float*)d_in[0];
    const float* Wk = (const float*)d_in[1];
    const float* bk = (const float*)d_in[2];
    const float* Wv = (const float*)d_in[3];
    const float* bv = (const float*)d_in[4];
    const float* Q  = (const float*)d_in[5];

    float* out  = (float*)d_out;
    float* Cout = out;                          // [B, L, D]
    float* Aout = out + (size_t)B_ * L_ * D_;   // [B, L, S]

    static char *gQp, *gHp, *gWp, *gKp, *gVp, *gAp;
    static bool init = false;
    if (!init) {
        cudaGetSymbolAddress((void**)&gQp, g_Qp);
        cudaGetSymbolAddress((void**)&gHp, g_Hp);
        cudaGetSymbolAddress((void**)&gWp, g_Wp);
        cudaGetSymbolAddress((void**)&gKp, g_Kp);
        cudaGetSymbolAddress((void**)&gVp, g_Vp);
        cudaGetSymbolAddress((void**)&gAp, g_Ap);
        cudaFuncSetAttribute(gemm_bulk, cudaFuncAttributeMaxDynamicSharedMemorySize, DSMEM);
        cudaFuncSetAttribute(kv_gemm_bulk, cudaFuncAttributeMaxDynamicSharedMemorySize, DSMEM);
        init = true;
    }

    // 0) packers
    pack_q<<<8960, 256>>>(Q);
    pack_h<<<dim3(S_ / 32, D_ / 64, B_), dim3(32, 8)>>>(H);
    pack_w<<<1024, 256>>>(Wk, Wv);

    // 1a) K = H^T * Wk  (M=S: 16 tiles x 16 kb, N=D; out packed (s-tile, o-kb))
    kv_gemm_bulk<<<dim3(D_ / TN, S_ / TM, B_), 256, DSMEM>>>(
        gHp, 256, gWp, 0,
        gKp, 256, 16, bk, 0, 16);

    // 1b) V^T = Wv * H^T (M=D: 4 tiles, N=S; out packed (o-tile, s-kb))
    kv_gemm_bulk<<<dim3(S_ / TN, D_ / TM, B_), 256, DSMEM>>>(
        gWp + (size_t)64 * SLOT, 0, gHp, 256,
        gVp, 256, 64, bv, 1, 16);

    // 2) E = Q K^T -> Aout (fp32)
    gemm_bulk<<<dim3(S_ / TN, 70, B_), 256, DSMEM>>>(
        gQp, 0, gKp, 256,
        Aout, S_, (size_t)L_ * S_, 16, L_);

    // 3) softmax (+ packed split of A)
    softmax_kernel<<<dim3(B_ * L_), 256>>>(Aout);

    // 4) C = A V -> Cout
    gemm_bulk<<<dim3(D_ / TN, 70, B_), 256, DSMEM>>>(
        gAp, 70 * 64, gVp, 256,
        Cout, D_, (size_t)L_ * D_, 64, L_);
}

// round 12
// speedup vs baseline: 1.6391x; 1.1415x over previous
#include <cuda_runtime.h>
#include <cuda_bf16.h>
#include <math.h>
#include <cstdint>

#define B_ 4
#define D_ 512
#define S_ 2048
#define L_ 8921

#define SLOT 16384              // packed (tile128 x k32) slot: hi 8KB | lo 8KB
#define HSUB 8192
#define ASLOT 8192              // hi-only slot (C-gemm A operand)

// Packed operand buffers (swizzled tiles, bulk-copy ready)
__device__ char g_Qp[(size_t)70 * 16 * SLOT];            // Q  [8960, 512] hi|lo
__device__ char g_Hp[(size_t)4 * 16 * 16 * SLOT];        // H^T per b: [2048, 512]
__device__ char g_Wp[(size_t)2 * 4 * 16 * SLOT];         // Wk|Wv [512, 512]
__device__ char g_Kp[(size_t)4 * 16 * 16 * SLOT];        // K per b: [2048, 512]
__device__ char g_Vp[(size_t)4 * 4 * 64 * SLOT];         // V^T per b: [512, 2048]
__device__ char g_Ap[(size_t)4 * 70 * 64 * ASLOT];       // attn per b: [8960, 2048] HI ONLY

// ---------------------------------------------------------------------------
// helpers
// ---------------------------------------------------------------------------
__device__ __forceinline__ uint32_t smem_to_u32(const void* p) {
    uint32_t a;
    asm("{ .reg .u64 t; cvta.to.shared.u64 t, %1; cvt.u32.u64 %0, t; }" : "=r"(a) : "l"(p));
    return a;
}
// SW64 swizzle for 64B rows
__device__ __forceinline__ uint32_t swz(uint32_t off) { return off ^ ((off >> 3) & 0x30); }

__device__ __forceinline__ void bulk_g2s(uint32_t dst, const void* src, uint32_t bytes, uint32_t mbar) {
    asm volatile("cp.async.bulk.shared::cta.global.mbarrier::complete_tx::bytes [%0], [%1], %2, [%3];"
        :: "r"(dst), "l"(src), "r"(bytes), "r"(mbar) : "memory");
}
#define MBARRIER_INIT(mbar, count) \
    asm volatile("mbarrier.init.shared.b64 [%0], %1;" :: "r"((uint32_t)(mbar)), "r"((uint32_t)(count)) : "memory")
#define MBARRIER_EXPECT_TX(mbar, bytes) \
    asm volatile("mbarrier.arrive.expect_tx.shared.b64 _, [%0], %1;" :: "r"((uint32_t)(mbar)), "r"((uint32_t)(bytes)) : "memory")
#define MBARRIER_WAIT_PARITY(mbar, parity) do { \
    uint32_t _m = (uint32_t)(mbar), _p = (uint32_t)(parity), _d; \
    asm volatile("{\n\t.reg .pred p;\n\t" \
        "mbarrier.try_wait.parity.acquire.cta.shared::cta.b64 p, [%1], %2;\n\t" \
        "selp.b32 %0, 1, 0, p;\n\t}" : "=r"(_d) : "r"(_m), "r"(_p) : "memory"); \
    if (!_d) { \
        asm volatile("{\n\t.reg .pred P1;\n\t" \
            "WL_%=:\n\t" \
            "mbarrier.try_wait.parity.acquire.cta.shared::cta.b64 P1, [%0], %1, 0x989680;\n\t" \
            "@P1 bra.uni WD_%=;\n\t" \
            "bra.uni WL_%=;\n\t" \
            "WD_%=:\n\t}" :: "r"(_m), "r"(_p) : "memory"); \
    } \
} while (0)

__device__ __forceinline__ void mma_bf16(float* d, const uint32_t* a, const uint32_t* b) {
    asm("mma.sync.aligned.m16n8k16.row.col.f32.bf16.bf16.f32 "
        "{%0,%1,%2,%3}, {%4,%5,%6,%7}, {%8,%9}, {%0,%1,%2,%3};"
        : "+f"(d[0]), "+f"(d[1]), "+f"(d[2]), "+f"(d[3])
        : "r"(a[0]), "r"(a[1]), "r"(a[2]), "r"(a[3]), "r"(b[0]), "r"(b[1]));
}
__device__ __forceinline__ void ldmx4(uint32_t* r, uint32_t addr) {
    asm volatile("ldmatrix.sync.aligned.m8n8.x4.shared.b16 {%0,%1,%2,%3}, [%4];"
        : "=r"(r[0]), "=r"(r[1]), "=r"(r[2]), "=r"(r[3]) : "r"(addr));
}
__device__ __forceinline__ float elu_f(float x) { return x > 0.f ? x : expm1f(x); }
__device__ __forceinline__ void split_bf16(float x, __nv_bfloat16& hi, __nv_bfloat16& lo) {
    hi = __float2bfloat16(x);
    lo = __float2bfloat16(x - __bfloat162float(hi));
}

// ===========================================================================
// GEMM config: CTA tile 128x128, TK=32, double-buffered stages via
// cp.async.bulk, 8 warps (warp tile 64x32), 2 CTAs/SM.
// ===========================================================================
#define TM 128
#define TN 128
#define STAGE_SM 32768
#define DSMEM (1024 + 2 * STAGE_SM + 32)

#define STAGE_C (ASLOT + SLOT)            // 24576
#define DSMEM_C (1024 + 2 * STAGE_C + 32)

#define SLOT_PTR(base, bz, bs, tile, kbn, kb) \
    ((base) + ((size_t)(bz) * (bs) + (size_t)(tile) * (kbn) + (kb)) * SLOT)

// ---------------------------------------------------------------------------
// Main GEMM (3-term): C[m,n] = sum_k A[m,k]*B[n,k], fp32 output with M guard.
// ---------------------------------------------------------------------------
__global__ __launch_bounds__(256, 2) void gemm_bulk(
    const char* __restrict__ Ap, int bsA,
    const char* __restrict__ Bp, int bsB,
    float* __restrict__ C, int ldc, size_t sC,
    int kbn, int Mtotal)
{
    extern __shared__ char smem_raw[];
    const uint32_t base = (smem_to_u32(smem_raw) + 1023) & ~1023u;
    const uint32_t mbar = base + 2 * STAGE_SM;

    const int t    = threadIdx.x;
    const int wid  = t >> 5, lane = t & 31;
    const int gid  = lane >> 2, tig = lane & 3;
    const int bz   = blockIdx.z;
    const int m0   = blockIdx.y * TM;
    const int n0   = blockIdx.x * TN;

    C += (size_t)bz * sC;

    const int wm0 = (wid & 1) * 64;
    const int wn0 = (wid >> 1) * 32;

    float acc[4][4][4];
#pragma unroll
    for (int i = 0; i < 4; i++)
#pragma unroll
        for (int j = 0; j < 4; j++)
#pragma unroll
            for (int q = 0; q < 4; q++) acc[i][j][q] = 0.f;

    if (t == 0) { MBARRIER_INIT(mbar, 1); MBARRIER_INIT(mbar + 8, 1); }
    __syncthreads();

    auto issue = [&](int kb, int stg) {
        if (t == 0) {
            uint32_t bar = mbar + 8 * stg;
            MBARRIER_EXPECT_TX(bar, 2 * SLOT);
            bulk_g2s(base + stg * STAGE_SM,
                     SLOT_PTR(Ap, bz, bsA, m0 >> 7, kbn, kb), SLOT, bar);
            bulk_g2s(base + stg * STAGE_SM + SLOT,
                     SLOT_PTR(Bp, bz, bsB, n0 >> 7, kbn, kb), SLOT, bar);
        }
    };

    const int arow = lane & 15;
    const int aoff = (lane >> 4) * 16;
    const int bprow = ((lane >> 4) & 1) * 8 + (lane & 7);
    const int bpoff = ((lane >> 3) & 1) * 16;

    issue(0, 0);

    for (int kb = 0; kb < kbn; kb++) {
        if (kb + 1 < kbn) issue(kb + 1, (kb + 1) & 1);
        MBARRIER_WAIT_PARITY(mbar + 8 * (kb & 1), (kb >> 1) & 1);

        const uint32_t sb = base + (kb & 1) * STAGE_SM;

#pragma unroll
        for (int ks = 0; ks < 2; ks++) {
            uint32_t ah[4][4], al[4][4];
#pragma unroll
            for (int mt = 0; mt < 4; mt++) {
                uint32_t off = swz((wm0 + mt * 16 + arow) * 64 + ks * 32 + aoff);
                ldmx4(ah[mt], sb + off);
                ldmx4(al[mt], sb + HSUB + off);
            }
#pragma unroll
            for (int p = 0; p < 2; p++) {
                uint32_t offb = swz((wn0 + p * 16 + bprow) * 64 + ks * 32 + bpoff);
                uint32_t bh4[4], bl4[4];
                ldmx4(bh4, sb + SLOT + offb);
                ldmx4(bl4, sb + SLOT + HSUB + offb);
#pragma unroll
                for (int mt = 0; mt < 4; mt++)
#pragma unroll
                    for (int h = 0; h < 2; h++)
                        mma_bf16(acc[mt][2 * p + h], ah[mt], bh4 + 2 * h);
#pragma unroll
                for (int mt = 0; mt < 4; mt++)
#pragma unroll
                    for (int h = 0; h < 2; h++)
                        mma_bf16(acc[mt][2 * p + h], ah[mt], bl4 + 2 * h);
#pragma unroll
                for (int mt = 0; mt < 4; mt++)
#pragma unroll
                    for (int h = 0; h < 2; h++)
                        mma_bf16(acc[mt][2 * p + h], al[mt], bh4 + 2 * h);
            }
        }
        __syncthreads();
    }

#pragma unroll
    for (int mt = 0; mt < 4; mt++) {
        int r0 = m0 + wm0 + mt * 16 + gid;
#pragma unroll
        for (int nt = 0; nt < 4; nt++) {
            int c0 = n0 + wn0 + nt * 8 + 2 * tig;
            if (r0 < Mtotal)
                *(float2*)(C + (size_t)r0 * ldc + c0) =
                    make_float2(acc[mt][nt][0], acc[mt][nt][1]);
            if (r0 + 8 < Mtotal)
                *(float2*)(C + (size_t)(r0 + 8) * ldc + c0) =
                    make_float2(acc[mt][nt][2], acc[mt][nt][3]);
        }
    }
}

// ---------------------------------------------------------------------------
// C GEMM (2-term): A is hi-only (8KB slots), B is hi|lo. 64 MMAs/kb.
// ---------------------------------------------------------------------------
__global__ __launch_bounds__(256, 2) void gemm_c(
    const char* __restrict__ Ap, int bsA,        // bsA in ASLOT units
    const char* __restrict__ Bp, int bsB,        // bsB in SLOT units
    float* __restrict__ C, int ldc, size_t sC,
    int kbn, int Mtotal)
{
    extern __shared__ char smem_raw[];
    const uint32_t base = (smem_to_u32(smem_raw) + 1023) & ~1023u;
    const uint32_t mbar = base + 2 * STAGE_C;

    const int t    = threadIdx.x;
    const int wid  = t >> 5, lane = t & 31;
    const int gid  = lane >> 2, tig = lane & 3;
    const int bz   = blockIdx.z;
    const int m0   = blockIdx.y * TM;
    const int n0   = blockIdx.x * TN;

    C += (size_t)bz * sC;

    const int wm0 = (wid & 1) * 64;
    const int wn0 = (wid >> 1) * 32;

    float acc[4][4][4];
#pragma unroll
    for (int i = 0; i < 4; i++)
#pragma unroll
        for (int j = 0; j < 4; j++)
#pragma unroll
            for (int q = 0; q < 4; q++) acc[i][j][q] = 0.f;

    if (t == 0) { MBARRIER_INIT(mbar, 1); MBARRIER_INIT(mbar + 8, 1); }
    __syncthreads();

    auto issue = [&](int kb, int stg) {
        if (t == 0) {
            uint32_t bar = mbar + 8 * stg;
            MBARRIER_EXPECT_TX(bar, ASLOT + SLOT);
            bulk_g2s(base + stg * STAGE_C,
                     Ap + ((size_t)bz * bsA + (size_t)(m0 >> 7) * kbn + kb) * ASLOT,
                     ASLOT, bar);
            bulk_g2s(base + stg * STAGE_C + ASLOT,
                     Bp + ((size_t)bz * bsB + (size_t)(n0 >> 7) * kbn + kb) * SLOT,
                     SLOT, bar);
        }
    };

    const int arow = lane & 15;
    const int aoff = (lane >> 4) * 16;
    const int bprow = ((lane >> 4) & 1) * 8 + (lane & 7);
    const int bpoff = ((lane >> 3) & 1) * 16;

    issue(0, 0);

    for (int kb = 0; kb < kbn; kb++) {
        if (kb + 1 < kbn) issue(kb + 1, (kb + 1) & 1);
        MBARRIER_WAIT_PARITY(mbar + 8 * (kb & 1), (kb >> 1) & 1);

        const uint32_t sb = base + (kb & 1) * STAGE_C;

#pragma unroll
        for (int ks = 0; ks < 2; ks++) {
            uint32_t ah[4][4];
#pragma unroll
            for (int mt = 0; mt < 4; mt++) {
                uint32_t off = swz((wm0 + mt * 16 + arow) * 64 + ks * 32 + aoff);
                ldmx4(ah[mt], sb + off);
            }
#pragma unroll
            for (int p = 0; p < 2; p++) {
                uint32_t offb = swz((wn0 + p * 16 + bprow) * 64 + ks * 32 + bpoff);
                uint32_t bh4[4], bl4[4];
                ldmx4(bh4, sb + ASLOT + offb);
                ldmx4(bl4, sb + ASLOT + HSUB + offb);
#pragma unroll
                for (int mt = 0; mt < 4; mt++)
#pragma unroll
                    for (int h = 0; h < 2; h++)
                        mma_bf16(acc[mt][2 * p + h], ah[mt], bh4 + 2 * h);
#pragma unroll
                for (int mt = 0; mt < 4; mt++)
#pragma unroll
                    for (int h = 0; h < 2; h++)
                        mma_bf16(acc[mt][2 * p + h], ah[mt], bl4 + 2 * h);
            }
        }
        __syncthreads();
    }

#pragma unroll
    for (int mt = 0; mt < 4; mt++) {
        int r0 = m0 + wm0 + mt * 16 + gid;
#pragma unroll
        for (int nt = 0; nt < 4; nt++) {
            int c0 = n0 + wn0 + nt * 8 + 2 * tig;
            if (r0 < Mtotal)
                *(float2*)(C + (size_t)r0 * ldc + c0) =
                    make_float2(acc[mt][nt][0], acc[mt][nt][1]);
            if (r0 + 8 < Mtotal)
                *(float2*)(C + (size_t)(r0 + 8) * ldc + c0) =
                    make_float2(acc[mt][nt][2], acc[mt][nt][3]);
        }
    }
}

// ---------------------------------------------------------------------------
// KV GEMM (3-term): epilogue = bias + ELU + bf16 split into PACKED output.
// ---------------------------------------------------------------------------
__global__ __launch_bounds__(256, 2) void kv_gemm_bulk(
    const char* __restrict__ Ap, int bsA,
    const char* __restrict__ Bp, int bsB,
    char* __restrict__ Op, int bsO, int kbO,
    const float* __restrict__ bias, int biasRow,
    int kbn)
{
    extern __shared__ char smem_raw[];
    const uint32_t base = (smem_to_u32(smem_raw) + 1023) & ~1023u;
    const uint32_t mbar = base + 2 * STAGE_SM;

    const int t    = threadIdx.x;
    const int wid  = t >> 5, lane = t & 31;
    const int gid  = lane >> 2, tig = lane & 3;
    const int bz   = blockIdx.z;
    const int m0   = blockIdx.y * TM;
    const int n0   = blockIdx.x * TN;

    const int wm0 = (wid & 1) * 64;
    const int wn0 = (wid >> 1) * 32;

    float acc[4][4][4];
#pragma unroll
    for (int i = 0; i < 4; i++)
#pragma unroll
        for (int j = 0; j < 4; j++)
#pragma unroll
            for (int q = 0; q < 4; q++) acc[i][j][q] = 0.f;

    if (t == 0) { MBARRIER_INIT(mbar, 1); MBARRIER_INIT(mbar + 8, 1); }
    __syncthreads();

    auto issue = [&](int kb, int stg) {
        if (t == 0) {
            uint32_t bar = mbar + 8 * stg;
            MBARRIER_EXPECT_TX(bar, 2 * SLOT);
            bulk_g2s(base + stg * STAGE_SM,
                     SLOT_PTR(Ap, bz, bsA, m0 >> 7, kbn, kb), SLOT, bar);
            bulk_g2s(base + stg * STAGE_SM + SLOT,
                     SLOT_PTR(Bp, bz, bsB, n0 >> 7, kbn, kb), SLOT, bar);
        }
    };

    const int arow = lane & 15;
    const int aoff = (lane >> 4) * 16;
    const int bprow = ((lane >> 4) & 1) * 8 + (lane & 7);
    const int bpoff = ((lane >> 3) & 1) * 16;

    issue(0, 0);

    for (int kb = 0; kb < kbn; kb++) {
        if (kb + 1 < kbn) issue(kb + 1, (kb + 1) & 1);
        MBARRIER_WAIT_PARITY(mbar + 8 * (kb & 1), (kb >> 1) & 1);

        const uint32_t sb = base + (kb & 1) * STAGE_SM;

#pragma unroll
        for (int ks = 0; ks < 2; ks++) {
            uint32_t ah[4][4], al[4][4];
#pragma unroll
            for (int mt = 0; mt < 4; mt++) {
                uint32_t off = swz((wm0 + mt * 16 + arow) * 64 + ks * 32 + aoff);
                ldmx4(ah[mt], sb + off);
                ldmx4(al[mt], sb + HSUB + off);
            }
#pragma unroll
            for (int p = 0; p < 2; p++) {
                uint32_t offb = swz((wn0 + p * 16 + bprow) * 64 + ks * 32 + bpoff);
                uint32_t bh4[4], bl4[4];
                ldmx4(bh4, sb + SLOT + offb);
                ldmx4(bl4, sb + SLOT + HSUB + offb);
#pragma unroll
                for (int mt = 0; mt < 4; mt++)
#pragma unroll
                    for (int h = 0; h < 2; h++)
                        mma_bf16(acc[mt][2 * p + h], ah[mt], bh4 + 2 * h);
#pragma unroll
                for (int mt = 0; mt < 4; mt++)
#pragma unroll
                    for (int h = 0; h < 2; h++)
                        mma_bf16(acc[mt][2 * p + h], ah[mt], bl4 + 2 * h);
#pragma unroll
                for (int mt = 0; mt < 4; mt++)
#pragma unroll
                    for (int h = 0; h < 2; h++)
                        mma_bf16(acc[mt][2 * p + h], al[mt], bh4 + 2 * h);
            }
        }
        __syncthreads();
    }

    // epilogue: packed-swizzled bf16 hi/lo writes
#pragma unroll
    for (int mt = 0; mt < 4; mt++) {
#pragma unroll
        for (int half = 0; half < 2; half++) {
            int m = m0 + wm0 + mt * 16 + gid + half * 8;
#pragma unroll
            for (int nt = 0; nt < 4; nt++) {
                int n = n0 + wn0 + nt * 8 + 2 * tig;
                float v0 = acc[mt][nt][2 * half + 0];
                float v1 = acc[mt][nt][2 * half + 1];
                float b0 = biasRow ? bias[m] : bias[n];
                float b1 = biasRow ? bias[m] : bias[n + 1];
                __nv_bfloat16 h0, l0, h1, l1;
                split_bf16(elu_f(v0 + b0), h0, l0);
                split_bf16(elu_f(v1 + b1), h1, l1);
                char* slot = Op + ((size_t)bz * bsO + (size_t)(m >> 7) * kbO + (n >> 5)) * SLOT;
                uint32_t off = swz((uint32_t)(m & 127) * 64 + (uint32_t)(n & 31) * 2);
                *(__nv_bfloat162*)(slot + off)        = __nv_bfloat162(h0, h1);
                *(__nv_bfloat162*)(slot + HSUB + off) = __nv_bfloat162(l0, l1);
            }
        }
    }
}

// ===========================================================================
// Packers
// ===========================================================================
__global__ __launch_bounds__(256) void pack_q(const float* __restrict__ Q)
{
    int row = blockIdx.x;                     // 0..8959
    int src = row < L_ ? row : L_ - 1;
    int t = threadIdx.x;
    float2 v = *(const float2*)(Q + (size_t)src * D_ + t * 2);
    __nv_bfloat16 h0, l0, h1, l1;
    split_bf16(v.x, h0, l0);
    split_bf16(v.y, h1, l1);
    int r = row & 127, tile = row >> 7;
    int d0 = t * 2, kb = d0 >> 5, c = d0 & 31;
    char* slot = g_Qp + ((size_t)tile * 16 + kb) * SLOT;
    uint32_t off = swz((uint32_t)r * 64 + (uint32_t)c * 2);
    *(__nv_bfloat162*)(slot + off)        = __nv_bfloat162(h0, h1);
    *(__nv_bfloat162*)(slot + HSUB + off) = __nv_bfloat162(l0, l1);
}

__global__ __launch_bounds__(256) void pack_h(const float* __restrict__ H)
{
    __shared__ float tile[64][33];
    const int b = blockIdx.z, s0 = blockIdx.x * 32, d0 = blockIdx.y * 64;
    const int tx = threadIdx.x, ty = threadIdx.y;
    const float* Hb = H + ((size_t)b * D_ + d0) * S_ + s0;

#pragma unroll
    for (int i = 0; i < 8; i++)
        tile[ty * 8 + i][tx] = Hb[(size_t)(ty * 8 + i) * S_ + tx];
    __syncthreads();

    const int t = ty * 32 + tx;
    const int s = t & 31;
    const int dp = t >> 5;
    const int gs = s0 + s;
    const int r = gs & 127;
#pragma unroll
    for (int i = 0; i < 4; i++) {
        int d = dp * 2 + i * 16;
        int kbl = d >> 5, c = d & 31;
        char* slot = g_Hp + (((size_t)b * 16 + (gs >> 7)) * 16 + blockIdx.y * 2 + kbl) * SLOT;
        __nv_bfloat16 h0, l0, h1, l1;
        split_bf16(tile[d][s], h0, l0);
        split_bf16(tile[d + 1][s], h1, l1);
        uint32_t off = swz((uint32_t)r * 64 + (uint32_t)c * 2);
        *(__nv_bfloat162*)(slot + off)        = __nv_bfloat162(h0, h1);
        *(__nv_bfloat162*)(slot + HSUB + off) = __nv_bfloat162(l0, l1);
    }
}

__global__ __launch_bounds__(256) void pack_w(
    const float* __restrict__ Wk, const float* __restrict__ Wv)
{
    int which = blockIdx.x >> 9;
    int o = blockIdx.x & 511;
    const float* W = which ? Wv : Wk;
    int t = threadIdx.x;
    float2 v = *(const float2*)(W + (size_t)o * D_ + t * 2);
    __nv_bfloat16 h0, l0, h1, l1;
    split_bf16(v.x, h0, l0);
    split_bf16(v.y, h1, l1);
    int r = o & 127, tile = o >> 7;
    int d0 = t * 2, kb = d0 >> 5, c = d0 & 31;
    char* slot = g_Wp + (((size_t)which * 4 + tile) * 16 + kb) * SLOT;
    uint32_t off = swz((uint32_t)r * 64 + (uint32_t)c * 2);
    *(__nv_bfloat162*)(slot + off)        = __nv_bfloat162(h0, h1);
    *(__nv_bfloat162*)(slot + HSUB + off) = __nv_bfloat162(l0, l1);
}

// ===========================================================================
// In-place row softmax over S=2048; emits packed bf16 HI of A only.
// ===========================================================================
__global__ __launch_bounds__(256) void softmax_kernel(float* __restrict__ A)
{
    const int row = blockIdx.x;               // b*L + l
    const int b = row / L_;
    const int l = row - b * L_;
    float* p = A + (size_t)row * S_;
    const int t = threadIdx.x;
    const int lane = t & 31, wid = t >> 5;

    float4 va = *(const float4*)(p + t * 4);
    float4 vb = *(const float4*)(p + 1024 + t * 4);

    float m = fmaxf(fmaxf(fmaxf(va.x, va.y), fmaxf(va.z, va.w)),
                    fmaxf(fmaxf(vb.x, vb.y), fmaxf(vb.z, vb.w)));
#pragma unroll
    for (int o = 16; o > 0; o >>= 1) m = fmaxf(m, __shfl_xor_sync(0xffffffffu, m, o));

    __shared__ float red[8];
    if (lane == 0) red[wid] = m;
    __syncthreads();
    {
        float r = red[lane & 7];
#pragma unroll
        for (int o = 4; o > 0; o >>= 1) r = fmaxf(r, __shfl_xor_sync(0xffffffffu, r, o));
        m = r;
    }

    va.x = __expf(va.x - m); va.y = __expf(va.y - m);
    va.z = __expf(va.z - m); va.w = __expf(va.w - m);
    vb.x = __expf(vb.x - m); vb.y = __expf(vb.y - m);
    vb.z = __expf(vb.z - m); vb.w = __expf(vb.w - m);

    float s = va.x + va.y + va.z + va.w + vb.x + vb.y + vb.z + vb.w;
#pragma unroll
    for (int o = 16; o > 0; o >>= 1) s += __shfl_xor_sync(0xffffffffu, s, o);
    __syncthreads();
    if (lane == 0) red[wid] = s;
    __syncthreads();
    {
        float r = red[lane & 7];
#pragma unroll
        for (int o = 4; o > 0; o >>= 1) r += __shfl_xor_sync(0xffffffffu, r, o);
        s = r;
    }
    float inv = 1.f / s;

    va.x *= inv; va.y *= inv; va.z *= inv; va.w *= inv;
    vb.x *= inv; vb.y *= inv; vb.z *= inv; vb.w *= inv;

    *(float4*)(p + t * 4) = va;
    *(float4*)(p + 1024 + t * 4) = vb;

    char* tslot = g_Ap + ((size_t)b * (70 * 64) + (size_t)(l >> 7) * 64) * ASLOT;
    const uint32_t r = l & 127;

    float g[2][4] = {{va.x, va.y, va.z, va.w}, {vb.x, vb.y, vb.z, vb.w}};
#pragma unroll
    for (int half = 0; half < 2; half++) {
        int sidx = half * 1024 + t * 4;
        int kb = sidx >> 5, c = sidx & 31;
        char* slot = tslot + (size_t)kb * ASLOT;
        uint32_t off = swz(r * 64 + (uint32_t)c * 2);
        *(__nv_bfloat162*)(slot + off) =
            __nv_bfloat162(__float2bfloat16(g[half][0]), __float2bfloat16(g[half][1]));
        *(__nv_bfloat162*)(slot + off + 4) =
            __nv_bfloat162(__float2bfloat16(g[half][2]), __float2bfloat16(g[half][3]));
    }
}

// ===========================================================================
extern "C" void kernel_launch(void* const* d_in, const int* in_sizes, int n_in,
                              void* d_out, int out_size)
{
    const float* H  = (const float*)d_in[0];
    const float* Wk = (const float*)d_in[1];
    const float* bk = (const float*)d_in[2];
    const float* Wv = (const float*)d_in[3];
    const float* bv = (const float*)d_in[4];
    const float* Q  = (const float*)d_in[5];

    float* out  = (float*)d_out;
    float* Cout = out;                          // [B, L, D]
    float* Aout = out + (size_t)B_ * L_ * D_;   // [B, L, S]

    static char *gQp, *gHp, *gWp, *gKp, *gVp, *gAp;
    static bool init = false;
    if (!init) {
        cudaGetSymbolAddress((void**)&gQp, g_Qp);
        cudaGetSymbolAddress((void**)&gHp, g_Hp);
        cudaGetSymbolAddress((void**)&gWp, g_Wp);
        cudaGetSymbolAddress((void**)&gKp, g_Kp);
        cudaGetSymbolAddress((void**)&gVp, g_Vp);
        cudaGetSymbolAddress((void**)&gAp, g_Ap);
        cudaFuncSetAttribute(gemm_bulk, cudaFuncAttributeMaxDynamicSharedMemorySize, DSMEM);
        cudaFuncSetAttribute(gemm_c, cudaFuncAttributeMaxDynamicSharedMemorySize, DSMEM_C);
        cudaFuncSetAttribute(kv_gemm_bulk, cudaFuncAttributeMaxDynamicSharedMemorySize, DSMEM);
        init = true;
    }

    // 0) packers
    pack_q<<<8960, 256>>>(Q);
    pack_h<<<dim3(S_ / 32, D_ / 64, B_), dim3(32, 8)>>>(H);
    pack_w<<<1024, 256>>>(Wk, Wv);

    // 1a) K = H^T * Wk
    kv_gemm_bulk<<<dim3(D_ / TN, S_ / TM, B_), 256, DSMEM>>>(
        gHp, 256, gWp, 0,
        gKp, 256, 16, bk, 0, 16);

    // 1b) V^T = Wv * H^T
    kv_gemm_bulk<<<dim3(S_ / TN, D_ / TM, B_), 256, DSMEM>>>(
        gWp + (size_t)64 * SLOT, 0, gHp, 256,
        gVp, 256, 64, bv, 1, 16);

    // 2) E = Q K^T -> Aout (fp32), 3-term
    gemm_bulk<<<dim3(S_ / TN, 70, B_), 256, DSMEM>>>(
        gQp, 0, gKp, 256,
        Aout, S_, (size_t)L_ * S_, 16, L_);

    // 3) softmax (+ packed HI split of A)
    softmax_kernel<<<dim3(B_ * L_), 256>>>(Aout);

    // 4) C = A V -> Cout, 2-term (A hi-only)
    gemm_c<<<dim3(D_ / TN, 70, B_), 256, DSMEM_C>>>(
        gAp, 70 * 64, gVp, 256,
        Cout, D_, (size_t)L_ * D_, 64, L_);
}

// round 13
// speedup vs baseline: 1.6600x; 1.0128x over previous
#include <cuda_runtime.h>
#include <cuda_bf16.h>
#include <math.h>
#include <cstdint>

#define B_ 4
#define D_ 512
#define S_ 2048
#define L_ 8921

#define SLOT 16384              // packed (tile128 x k32) slot: hi 8KB | lo 8KB
#define HSUB 8192
#define ASLOT 8192              // hi-only slot (C-gemm A operand)

// Packed operand buffers (swizzled tiles, bulk-copy ready)
__device__ char g_Qp[(size_t)70 * 16 * SLOT];            // Q  [8960, 512] hi|lo
__device__ char g_Hp[(size_t)4 * 16 * 16 * SLOT];        // H^T per b: [2048, 512]
__device__ char g_Wp[(size_t)2 * 4 * 16 * SLOT];         // Wk|Wv [512, 512]
__device__ char g_Kp[(size_t)4 * 16 * 16 * SLOT];        // K per b: [2048, 512]
__device__ char g_Vp[(size_t)4 * 4 * 64 * SLOT];         // V^T per b: [512, 2048]
__device__ char g_Ap[(size_t)4 * 70 * 64 * ASLOT];       // attn per b: [8960, 2048] HI ONLY

// ---------------------------------------------------------------------------
// helpers
// ---------------------------------------------------------------------------
__device__ __forceinline__ uint32_t smem_to_u32(const void* p) {
    uint32_t a;
    asm("{ .reg .u64 t; cvta.to.shared.u64 t, %1; cvt.u32.u64 %0, t; }" : "=r"(a) : "l"(p));
    return a;
}
// SW64 swizzle for 64B rows
__device__ __forceinline__ uint32_t swz(uint32_t off) { return off ^ ((off >> 3) & 0x30); }

__device__ __forceinline__ void bulk_g2s(uint32_t dst, const void* src, uint32_t bytes, uint32_t mbar) {
    asm volatile("cp.async.bulk.shared::cta.global.mbarrier::complete_tx::bytes [%0], [%1], %2, [%3];"
        :: "r"(dst), "l"(src), "r"(bytes), "r"(mbar) : "memory");
}
#define MBARRIER_INIT(mbar, count) \
    asm volatile("mbarrier.init.shared.b64 [%0], %1;" :: "r"((uint32_t)(mbar)), "r"((uint32_t)(count)) : "memory")
#define MBARRIER_EXPECT_TX(mbar, bytes) \
    asm volatile("mbarrier.arrive.expect_tx.shared.b64 _, [%0], %1;" :: "r"((uint32_t)(mbar)), "r"((uint32_t)(bytes)) : "memory")
#define MBARRIER_WAIT_PARITY(mbar, parity) do { \
    uint32_t _m = (uint32_t)(mbar), _p = (uint32_t)(parity), _d; \
    asm volatile("{\n\t.reg .pred p;\n\t" \
        "mbarrier.try_wait.parity.acquire.cta.shared::cta.b64 p, [%1], %2;\n\t" \
        "selp.b32 %0, 1, 0, p;\n\t}" : "=r"(_d) : "r"(_m), "r"(_p) : "memory"); \
    if (!_d) { \
        asm volatile("{\n\t.reg .pred P1;\n\t" \
            "WL_%=:\n\t" \
            "mbarrier.try_wait.parity.acquire.cta.shared::cta.b64 P1, [%0], %1, 0x989680;\n\t" \
            "@P1 bra.uni WD_%=;\n\t" \
            "bra.uni WL_%=;\n\t" \
            "WD_%=:\n\t}" :: "r"(_m), "r"(_p) : "memory"); \
    } \
} while (0)

__device__ __forceinline__ void mma_bf16(float* d, const uint32_t* a, const uint32_t* b) {
    asm("mma.sync.aligned.m16n8k16.row.col.f32.bf16.bf16.f32 "
        "{%0,%1,%2,%3}, {%4,%5,%6,%7}, {%8,%9}, {%0,%1,%2,%3};"
        : "+f"(d[0]), "+f"(d[1]), "+f"(d[2]), "+f"(d[3])
        : "r"(a[0]), "r"(a[1]), "r"(a[2]), "r"(a[3]), "r"(b[0]), "r"(b[1]));
}
__device__ __forceinline__ void ldmx4(uint32_t* r, uint32_t addr) {
    asm volatile("ldmatrix.sync.aligned.m8n8.x4.shared.b16 {%0,%1,%2,%3}, [%4];"
        : "=r"(r[0]), "=r"(r[1]), "=r"(r[2]), "=r"(r[3]) : "r"(addr));
}
__device__ __forceinline__ float elu_f(float x) { return x > 0.f ? x : expm1f(x); }
__device__ __forceinline__ void split_bf16(float x, __nv_bfloat16& hi, __nv_bfloat16& lo) {
    hi = __float2bfloat16(x);
    lo = __float2bfloat16(x - __bfloat162float(hi));
}

// ===========================================================================
// GEMM config: CTA tile 128x128, TK=32, TRIPLE-buffered stages via
// cp.async.bulk, 8 warps (warp tile 64x32), 2 CTAs/SM.
// ===========================================================================
#define TM 128
#define TN 128
#define NSTG 3
#define STAGE_SM 32768
#define DSMEM (1024 + NSTG * STAGE_SM + 64)

#define STAGE_C (ASLOT + SLOT)            // 24576
#define DSMEM_C (1024 + NSTG * STAGE_C + 64)

#define SLOT_PTR(base, bz, bs, tile, kbn, kb) \
    ((base) + ((size_t)(bz) * (bs) + (size_t)(tile) * (kbn) + (kb)) * SLOT)

// ---------------------------------------------------------------------------
// Main GEMM (3-term): C[m,n] = sum_k A[m,k]*B[n,k], fp32 output with M guard.
// ---------------------------------------------------------------------------
__global__ __launch_bounds__(256, 2) void gemm_bulk(
    const char* __restrict__ Ap, int bsA,
    const char* __restrict__ Bp, int bsB,
    float* __restrict__ C, int ldc, size_t sC,
    int kbn, int Mtotal)
{
    extern __shared__ char smem_raw[];
    const uint32_t base = (smem_to_u32(smem_raw) + 1023) & ~1023u;
    const uint32_t mbar = base + NSTG * STAGE_SM;

    const int t    = threadIdx.x;
    const int wid  = t >> 5, lane = t & 31;
    const int gid  = lane >> 2, tig = lane & 3;
    const int bz   = blockIdx.z;
    const int m0   = blockIdx.y * TM;
    const int n0   = blockIdx.x * TN;

    C += (size_t)bz * sC;

    const int wm0 = (wid & 1) * 64;
    const int wn0 = (wid >> 1) * 32;

    float acc[4][4][4];
#pragma unroll
    for (int i = 0; i < 4; i++)
#pragma unroll
        for (int j = 0; j < 4; j++)
#pragma unroll
            for (int q = 0; q < 4; q++) acc[i][j][q] = 0.f;

    if (t == 0) {
        MBARRIER_INIT(mbar, 1); MBARRIER_INIT(mbar + 8, 1); MBARRIER_INIT(mbar + 16, 1);
    }
    __syncthreads();

    auto issue = [&](int kb) {
        if (t == 0) {
            int stg = kb % NSTG;
            uint32_t bar = mbar + 8 * stg;
            MBARRIER_EXPECT_TX(bar, 2 * SLOT);
            bulk_g2s(base + stg * STAGE_SM,
                     SLOT_PTR(Ap, bz, bsA, m0 >> 7, kbn, kb), SLOT, bar);
            bulk_g2s(base + stg * STAGE_SM + SLOT,
                     SLOT_PTR(Bp, bz, bsB, n0 >> 7, kbn, kb), SLOT, bar);
        }
    };

    const int arow = lane & 15;
    const int aoff = (lane >> 4) * 16;
    const int bprow = ((lane >> 4) & 1) * 8 + (lane & 7);
    const int bpoff = ((lane >> 3) & 1) * 16;

    issue(0);
    if (1 < kbn) issue(1);

    for (int kb = 0; kb < kbn; kb++) {
        if (kb + 2 < kbn) issue(kb + 2);
        MBARRIER_WAIT_PARITY(mbar + 8 * (kb % NSTG), (kb / NSTG) & 1);

        const uint32_t sb = base + (kb % NSTG) * STAGE_SM;

#pragma unroll
        for (int ks = 0; ks < 2; ks++) {
            uint32_t ah[4][4], al[4][4];
#pragma unroll
            for (int mt = 0; mt < 4; mt++) {
                uint32_t off = swz((wm0 + mt * 16 + arow) * 64 + ks * 32 + aoff);
                ldmx4(ah[mt], sb + off);
                ldmx4(al[mt], sb + HSUB + off);
            }
#pragma unroll
            for (int p = 0; p < 2; p++) {
                uint32_t offb = swz((wn0 + p * 16 + bprow) * 64 + ks * 32 + bpoff);
                uint32_t bh4[4], bl4[4];
                ldmx4(bh4, sb + SLOT + offb);
                ldmx4(bl4, sb + SLOT + HSUB + offb);
#pragma unroll
                for (int mt = 0; mt < 4; mt++)
#pragma unroll
                    for (int h = 0; h < 2; h++)
                        mma_bf16(acc[mt][2 * p + h], ah[mt], bh4 + 2 * h);
#pragma unroll
                for (int mt = 0; mt < 4; mt++)
#pragma unroll
                    for (int h = 0; h < 2; h++)
                        mma_bf16(acc[mt][2 * p + h], ah[mt], bl4 + 2 * h);
#pragma unroll
                for (int mt = 0; mt < 4; mt++)
#pragma unroll
                    for (int h = 0; h < 2; h++)
                        mma_bf16(acc[mt][2 * p + h], al[mt], bh4 + 2 * h);
            }
        }
        __syncthreads();
    }

#pragma unroll
    for (int mt = 0; mt < 4; mt++) {
        int r0 = m0 + wm0 + mt * 16 + gid;
#pragma unroll
        for (int nt = 0; nt < 4; nt++) {
            int c0 = n0 + wn0 + nt * 8 + 2 * tig;
            if (r0 < Mtotal)
                *(float2*)(C + (size_t)r0 * ldc + c0) =
                    make_float2(acc[mt][nt][0], acc[mt][nt][1]);
            if (r0 + 8 < Mtotal)
                *(float2*)(C + (size_t)(r0 + 8) * ldc + c0) =
                    make_float2(acc[mt][nt][2], acc[mt][nt][3]);
        }
    }
}

// ---------------------------------------------------------------------------
// C GEMM (2-term): A is hi-only (8KB slots), B is hi|lo. 64 MMAs/kb.
// ---------------------------------------------------------------------------
__global__ __launch_bounds__(256, 2) void gemm_c(
    const char* __restrict__ Ap, int bsA,        // bsA in ASLOT units
    const char* __restrict__ Bp, int bsB,        // bsB in SLOT units
    float* __restrict__ C, int ldc, size_t sC,
    int kbn, int Mtotal)
{
    extern __shared__ char smem_raw[];
    const uint32_t base = (smem_to_u32(smem_raw) + 1023) & ~1023u;
    const uint32_t mbar = base + NSTG * STAGE_C;

    const int t    = threadIdx.x;
    const int wid  = t >> 5, lane = t & 31;
    const int gid  = lane >> 2, tig = lane & 3;
    const int bz   = blockIdx.z;
    const int m0   = blockIdx.y * TM;
    const int n0   = blockIdx.x * TN;

    C += (size_t)bz * sC;

    const int wm0 = (wid & 1) * 64;
    const int wn0 = (wid >> 1) * 32;

    float acc[4][4][4];
#pragma unroll
    for (int i = 0; i < 4; i++)
#pragma unroll
        for (int j = 0; j < 4; j++)
#pragma unroll
            for (int q = 0; q < 4; q++) acc[i][j][q] = 0.f;

    if (t == 0) {
        MBARRIER_INIT(mbar, 1); MBARRIER_INIT(mbar + 8, 1); MBARRIER_INIT(mbar + 16, 1);
    }
    __syncthreads();

    auto issue = [&](int kb) {
        if (t == 0) {
            int stg = kb % NSTG;
            uint32_t bar = mbar + 8 * stg;
            MBARRIER_EXPECT_TX(bar, ASLOT + SLOT);
            bulk_g2s(base + stg * STAGE_C,
                     Ap + ((size_t)bz * bsA + (size_t)(m0 >> 7) * kbn + kb) * ASLOT,
                     ASLOT, bar);
            bulk_g2s(base + stg * STAGE_C + ASLOT,
                     Bp + ((size_t)bz * bsB + (size_t)(n0 >> 7) * kbn + kb) * SLOT,
                     SLOT, bar);
        }
    };

    const int arow = lane & 15;
    const int aoff = (lane >> 4) * 16;
    const int bprow = ((lane >> 4) & 1) * 8 + (lane & 7);
    const int bpoff = ((lane >> 3) & 1) * 16;

    issue(0);
    if (1 < kbn) issue(1);

    for (int kb = 0; kb < kbn; kb++) {
        if (kb + 2 < kbn) issue(kb + 2);
        MBARRIER_WAIT_PARITY(mbar + 8 * (kb % NSTG), (kb / NSTG) & 1);

        const uint32_t sb = base + (kb % NSTG) * STAGE_C;

#pragma unroll
        for (int ks = 0; ks < 2; ks++) {
            uint32_t ah[4][4];
#pragma unroll
            for (int mt = 0; mt < 4; mt++) {
                uint32_t off = swz((wm0 + mt * 16 + arow) * 64 + ks * 32 + aoff);
                ldmx4(ah[mt], sb + off);
            }
#pragma unroll
            for (int p = 0; p < 2; p++) {
                uint32_t offb = swz((wn0 + p * 16 + bprow) * 64 + ks * 32 + bpoff);
                uint32_t bh4[4], bl4[4];
                ldmx4(bh4, sb + ASLOT + offb);
                ldmx4(bl4, sb + ASLOT + HSUB + offb);
#pragma unroll
                for (int mt = 0; mt < 4; mt++)
#pragma unroll
                    for (int h = 0; h < 2; h++)
                        mma_bf16(acc[mt][2 * p + h], ah[mt], bh4 + 2 * h);
#pragma unroll
                for (int mt = 0; mt < 4; mt++)
#pragma unroll
                    for (int h = 0; h < 2; h++)
                        mma_bf16(acc[mt][2 * p + h], ah[mt], bl4 + 2 * h);
            }
        }
        __syncthreads();
    }

#pragma unroll
    for (int mt = 0; mt < 4; mt++) {
        int r0 = m0 + wm0 + mt * 16 + gid;
#pragma unroll
        for (int nt = 0; nt < 4; nt++) {
            int c0 = n0 + wn0 + nt * 8 + 2 * tig;
            if (r0 < Mtotal)
                *(float2*)(C + (size_t)r0 * ldc + c0) =
                    make_float2(acc[mt][nt][0], acc[mt][nt][1]);
            if (r0 + 8 < Mtotal)
                *(float2*)(C + (size_t)(r0 + 8) * ldc + c0) =
                    make_float2(acc[mt][nt][2], acc[mt][nt][3]);
        }
    }
}

// ---------------------------------------------------------------------------
// KV GEMM (3-term): epilogue = bias + ELU + bf16 split into PACKED output.
// ---------------------------------------------------------------------------
__global__ __launch_bounds__(256, 2) void kv_gemm_bulk(
    const char* __restrict__ Ap, int bsA,
    const char* __restrict__ Bp, int bsB,
    char* __restrict__ Op, int bsO, int kbO,
    const float* __restrict__ bias, int biasRow,
    int kbn)
{
    extern __shared__ char smem_raw[];
    const uint32_t base = (smem_to_u32(smem_raw) + 1023) & ~1023u;
    const uint32_t mbar = base + NSTG * STAGE_SM;

    const int t    = threadIdx.x;
    const int wid  = t >> 5, lane = t & 31;
    const int gid  = lane >> 2, tig = lane & 3;
    const int bz   = blockIdx.z;
    const int m0   = blockIdx.y * TM;
    const int n0   = blockIdx.x * TN;

    const int wm0 = (wid & 1) * 64;
    const int wn0 = (wid >> 1) * 32;

    float acc[4][4][4];
#pragma unroll
    for (int i = 0; i < 4; i++)
#pragma unroll
        for (int j = 0; j < 4; j++)
#pragma unroll
            for (int q = 0; q < 4; q++) acc[i][j][q] = 0.f;

    if (t == 0) {
        MBARRIER_INIT(mbar, 1); MBARRIER_INIT(mbar + 8, 1); MBARRIER_INIT(mbar + 16, 1);
    }
    __syncthreads();

    auto issue = [&](int kb) {
        if (t == 0) {
            int stg = kb % NSTG;
            uint32_t bar = mbar + 8 * stg;
            MBARRIER_EXPECT_TX(bar, 2 * SLOT);
            bulk_g2s(base + stg * STAGE_SM,
                     SLOT_PTR(Ap, bz, bsA, m0 >> 7, kbn, kb), SLOT, bar);
            bulk_g2s(base + stg * STAGE_SM + SLOT,
                     SLOT_PTR(Bp, bz, bsB, n0 >> 7, kbn, kb), SLOT, bar);
        }
    };

    const int arow = lane & 15;
    const int aoff = (lane >> 4) * 16;
    const int bprow = ((lane >> 4) & 1) * 8 + (lane & 7);
    const int bpoff = ((lane >> 3) & 1) * 16;

    issue(0);
    if (1 < kbn) issue(1);

    for (int kb = 0; kb < kbn; kb++) {
        if (kb + 2 < kbn) issue(kb + 2);
        MBARRIER_WAIT_PARITY(mbar + 8 * (kb % NSTG), (kb / NSTG) & 1);

        const uint32_t sb = base + (kb % NSTG) * STAGE_SM;

#pragma unroll
        for (int ks = 0; ks < 2; ks++) {
            uint32_t ah[4][4], al[4][4];
#pragma unroll
            for (int mt = 0; mt < 4; mt++) {
                uint32_t off = swz((wm0 + mt * 16 + arow) * 64 + ks * 32 + aoff);
                ldmx4(ah[mt], sb + off);
                ldmx4(al[mt], sb + HSUB + off);
            }
#pragma unroll
            for (int p = 0; p < 2; p++) {
                uint32_t offb = swz((wn0 + p * 16 + bprow) * 64 + ks * 32 + bpoff);
                uint32_t bh4[4], bl4[4];
                ldmx4(bh4, sb + SLOT + offb);
                ldmx4(bl4, sb + SLOT + HSUB + offb);
#pragma unroll
                for (int mt = 0; mt < 4; mt++)
#pragma unroll
                    for (int h = 0; h < 2; h++)
                        mma_bf16(acc[mt][2 * p + h], ah[mt], bh4 + 2 * h);
#pragma unroll
                for (int mt = 0; mt < 4; mt++)
#pragma unroll
                    for (int h = 0; h < 2; h++)
                        mma_bf16(acc[mt][2 * p + h], ah[mt], bl4 + 2 * h);
#pragma unroll
                for (int mt = 0; mt < 4; mt++)
#pragma unroll
                    for (int h = 0; h < 2; h++)
                        mma_bf16(acc[mt][2 * p + h], al[mt], bh4 + 2 * h);
            }
        }
        __syncthreads();
    }

    // epilogue: packed-swizzled bf16 hi/lo writes
#pragma unroll
    for (int mt = 0; mt < 4; mt++) {
#pragma unroll
        for (int half = 0; half < 2; half++) {
            int m = m0 + wm0 + mt * 16 + gid + half * 8;
#pragma unroll
            for (int nt = 0; nt < 4; nt++) {
                int n = n0 + wn0 + nt * 8 + 2 * tig;
                float v0 = acc[mt][nt][2 * half + 0];
                float v1 = acc[mt][nt][2 * half + 1];
                float b0 = biasRow ? bias[m] : bias[n];
                float b1 = biasRow ? bias[m] : bias[n + 1];
                __nv_bfloat16 h0, l0, h1, l1;
                split_bf16(elu_f(v0 + b0), h0, l0);
                split_bf16(elu_f(v1 + b1), h1, l1);
                char* slot = Op + ((size_t)bz * bsO + (size_t)(m >> 7) * kbO + (n >> 5)) * SLOT;
                uint32_t off = swz((uint32_t)(m & 127) * 64 + (uint32_t)(n & 31) * 2);
                *(__nv_bfloat162*)(slot + off)        = __nv_bfloat162(h0, h1);
                *(__nv_bfloat162*)(slot + HSUB + off) = __nv_bfloat162(l0, l1);
            }
        }
    }
}

// ===========================================================================
// Packers
// ===========================================================================
__global__ __launch_bounds__(256) void pack_q(const float* __restrict__ Q)
{
    int row = blockIdx.x;                     // 0..8959
    int src = row < L_ ? row : L_ - 1;
    int t = threadIdx.x;
    float2 v = *(const float2*)(Q + (size_t)src * D_ + t * 2);
    __nv_bfloat16 h0, l0, h1, l1;
    split_bf16(v.x, h0, l0);
    split_bf16(v.y, h1, l1);
    int r = row & 127, tile = row >> 7;
    int d0 = t * 2, kb = d0 >> 5, c = d0 & 31;
    char* slot = g_Qp + ((size_t)tile * 16 + kb) * SLOT;
    uint32_t off = swz((uint32_t)r * 64 + (uint32_t)c * 2);
    *(__nv_bfloat162*)(slot + off)        = __nv_bfloat162(h0, h1);
    *(__nv_bfloat162*)(slot + HSUB + off) = __nv_bfloat162(l0, l1);
}

__global__ __launch_bounds__(256) void pack_h(const float* __restrict__ H)
{
    __shared__ float tile[64][33];
    const int b = blockIdx.z, s0 = blockIdx.x * 32, d0 = blockIdx.y * 64;
    const int tx = threadIdx.x, ty = threadIdx.y;
    const float* Hb = H + ((size_t)b * D_ + d0) * S_ + s0;

#pragma unroll
    for (int i = 0; i < 8; i++)
        tile[ty * 8 + i][tx] = Hb[(size_t)(ty * 8 + i) * S_ + tx];
    __syncthreads();

    const int t = ty * 32 + tx;
    const int s = t & 31;
    const int dp = t >> 5;
    const int gs = s0 + s;
    const int r = gs & 127;
#pragma unroll
    for (int i = 0; i < 4; i++) {
        int d = dp * 2 + i * 16;
        int kbl = d >> 5, c = d & 31;
        char* slot = g_Hp + (((size_t)b * 16 + (gs >> 7)) * 16 + blockIdx.y * 2 + kbl) * SLOT;
        __nv_bfloat16 h0, l0, h1, l1;
        split_bf16(tile[d][s], h0, l0);
        split_bf16(tile[d + 1][s], h1, l1);
        uint32_t off = swz((uint32_t)r * 64 + (uint32_t)c * 2);
        *(__nv_bfloat162*)(slot + off)        = __nv_bfloat162(h0, h1);
        *(__nv_bfloat162*)(slot + HSUB + off) = __nv_bfloat162(l0, l1);
    }
}

__global__ __launch_bounds__(256) void pack_w(
    const float* __restrict__ Wk, const float* __restrict__ Wv)
{
    int which = blockIdx.x >> 9;
    int o = blockIdx.x & 511;
    const float* W = which ? Wv : Wk;
    int t = threadIdx.x;
    float2 v = *(const float2*)(W + (size_t)o * D_ + t * 2);
    __nv_bfloat16 h0, l0, h1, l1;
    split_bf16(v.x, h0, l0);
    split_bf16(v.y, h1, l1);
    int r = o & 127, tile = o >> 7;
    int d0 = t * 2, kb = d0 >> 5, c = d0 & 31;
    char* slot = g_Wp + (((size_t)which * 4 + tile) * 16 + kb) * SLOT;
    uint32_t off = swz((uint32_t)r * 64 + (uint32_t)c * 2);
    *(__nv_bfloat162*)(slot + off)        = __nv_bfloat162(h0, h1);
    *(__nv_bfloat162*)(slot + HSUB + off) = __nv_bfloat162(l0, l1);
}

// ===========================================================================
// In-place row softmax over S=2048; emits packed bf16 HI of A only.
// ===========================================================================
__global__ __launch_bounds__(256) void softmax_kernel(float* __restrict__ A)
{
    const int row = blockIdx.x;               // b*L + l
    const int b = row / L_;
    const int l = row - b * L_;
    float* p = A + (size_t)row * S_;
    const int t = threadIdx.x;
    const int lane = t & 31, wid = t >> 5;

    float4 va = *(const float4*)(p + t * 4);
    float4 vb = *(const float4*)(p + 1024 + t * 4);

    float m = fmaxf(fmaxf(fmaxf(va.x, va.y), fmaxf(va.z, va.w)),
                    fmaxf(fmaxf(vb.x, vb.y), fmaxf(vb.z, vb.w)));
#pragma unroll
    for (int o = 16; o > 0; o >>= 1) m = fmaxf(m, __shfl_xor_sync(0xffffffffu, m, o));

    __shared__ float red[8];
    if (lane == 0) red[wid] = m;
    __syncthreads();
    {
        float r = red[lane & 7];
#pragma unroll
        for (int o = 4; o > 0; o >>= 1) r = fmaxf(r, __shfl_xor_sync(0xffffffffu, r, o));
        m = r;
    }

    va.x = __expf(va.x - m); va.y = __expf(va.y - m);
    va.z = __expf(va.z - m); va.w = __expf(va.w - m);
    vb.x = __expf(vb.x - m); vb.y = __expf(vb.y - m);
    vb.z = __expf(vb.z - m); vb.w = __expf(vb.w - m);

    float s = va.x + va.y + va.z + va.w + vb.x + vb.y + vb.z + vb.w;
#pragma unroll
    for (int o = 16; o > 0; o >>= 1) s += __shfl_xor_sync(0xffffffffu, s, o);
    __syncthreads();
    if (lane == 0) red[wid] = s;
    __syncthreads();
    {
        float r = red[lane & 7];
#pragma unroll
        for (int o = 4; o > 0; o >>= 1) r += __shfl_xor_sync(0xffffffffu, r, o);
        s = r;
    }
    float inv = 1.f / s;

    va.x *= inv; va.y *= inv; va.z *= inv; va.w *= inv;
    vb.x *= inv; vb.y *= inv; vb.z *= inv; vb.w *= inv;

    *(float4*)(p + t * 4) = va;
    *(float4*)(p + 1024 + t * 4) = vb;

    char* tslot = g_Ap + ((size_t)b * (70 * 64) + (size_t)(l >> 7) * 64) * ASLOT;
    const uint32_t r = l & 127;

    float g[2][4] = {{va.x, va.y, va.z, va.w}, {vb.x, vb.y, vb.z, vb.w}};
#pragma unroll
    for (int half = 0; half < 2; half++) {
        int sidx = half * 1024 + t * 4;
        int kb = sidx >> 5, c = sidx & 31;
        char* slot = tslot + (size_t)kb * ASLOT;
        uint32_t off = swz(r * 64 + (uint32_t)c * 2);
        *(__nv_bfloat162*)(slot + off) =
            __nv_bfloat162(__float2bfloat16(g[half][0]), __float2bfloat16(g[half][1]));
        *(__nv_bfloat162*)(slot + off + 4) =
            __nv_bfloat162(__float2bfloat16(g[half][2]), __float2bfloat16(g[half][3]));
    }
}

// ===========================================================================
extern "C" void kernel_launch(void* const* d_in, const int* in_sizes, int n_in,
                              void* d_out, int out_size)
{
    const float* H  = (const float*)d_in[0];
    const float* Wk = (const float*)d_in[1];
    const float* bk = (const float*)d_in[2];
    const float* Wv = (const float*)d_in[3];
    const float* bv = (const float*)d_in[4];
    const float* Q  = (const float*)d_in[5];

    float* out  = (float*)d_out;
    float* Cout = out;                          // [B, L, D]
    float* Aout = out + (size_t)B_ * L_ * D_;   // [B, L, S]

    static char *gQp, *gHp, *gWp, *gKp, *gVp, *gAp;
    static bool init = false;
    if (!init) {
        cudaGetSymbolAddress((void**)&gQp, g_Qp);
        cudaGetSymbolAddress((void**)&gHp, g_Hp);
        cudaGetSymbolAddress((void**)&gWp, g_Wp);
        cudaGetSymbolAddress((void**)&gKp, g_Kp);
        cudaGetSymbolAddress((void**)&gVp, g_Vp);
        cudaGetSymbolAddress((void**)&gAp, g_Ap);
        cudaFuncSetAttribute(gemm_bulk, cudaFuncAttributeMaxDynamicSharedMemorySize, DSMEM);
        cudaFuncSetAttribute(gemm_c, cudaFuncAttributeMaxDynamicSharedMemorySize, DSMEM_C);
        cudaFuncSetAttribute(kv_gemm_bulk, cudaFuncAttributeMaxDynamicSharedMemorySize, DSMEM);
        init = true;
    }

    // 0) packers
    pack_q<<<8960, 256>>>(Q);
    pack_h<<<dim3(S_ / 32, D_ / 64, B_), dim3(32, 8)>>>(H);
    pack_w<<<1024, 256>>>(Wk, Wv);

    // 1a) K = H^T * Wk
    kv_gemm_bulk<<<dim3(D_ / TN, S_ / TM, B_), 256, DSMEM>>>(
        gHp, 256, gWp, 0,
        gKp, 256, 16, bk, 0, 16);

    // 1b) V^T = Wv * H^T
    kv_gemm_bulk<<<dim3(S_ / TN, D_ / TM, B_), 256, DSMEM>>>(
        gWp + (size_t)64 * SLOT, 0, gHp, 256,
        gVp, 256, 64, bv, 1, 16);

    // 2) E = Q K^T -> Aout (fp32), 3-term
    gemm_bulk<<<dim3(S_ / TN, 70, B_), 256, DSMEM>>>(
        gQp, 0, gKp, 256,
        Aout, S_, (size_t)L_ * S_, 16, L_);

    // 3) softmax (+ packed HI split of A)
    softmax_kernel<<<dim3(B_ * L_), 256>>>(Aout);

    // 4) C = A V -> Cout, 2-term (A hi-only)
    gemm_c<<<dim3(D_ / TN, 70, B_), 256, DSMEM_C>>>(
        gAp, 70 * 64, gVp, 256,
        Cout, D_, (size_t)L_ * D_, 64, L_);
}

// round 14
// speedup vs baseline: 1.7066x; 1.0281x over previous
#include <cuda_runtime.h>
#include <cuda_bf16.h>
#include <math.h>
#include <cstdint>

#define B_ 4
#define D_ 512
#define S_ 2048
#define L_ 8921

#define SLOT 16384              // packed (tile128 x k32) slot: hi 8KB | lo 8KB
#define HSUB 8192
#define ASLOT 8192              // hi-only slot (C-gemm A operand)

// Packed operand buffers (swizzled tiles, bulk-copy ready)
__device__ char g_Qp[(size_t)70 * 16 * SLOT];            // Q  [8960, 512] hi|lo
__device__ char g_Hp[(size_t)4 * 16 * 16 * SLOT];        // H^T per b: [2048, 512]
__device__ char g_Wp[(size_t)2 * 4 * 16 * SLOT];         // Wk|Wv [512, 512]
__device__ char g_Kp[(size_t)4 * 16 * 16 * SLOT];        // K per b: [2048, 512]
__device__ char g_Vp[(size_t)4 * 4 * 64 * SLOT];         // V^T per b: [512, 2048]
__device__ char g_Ap[(size_t)4 * 70 * 64 * ASLOT];       // attn per b: [8960, 2048] HI ONLY

// ---------------------------------------------------------------------------
// helpers
// ---------------------------------------------------------------------------
__device__ __forceinline__ uint32_t smem_to_u32(const void* p) {
    uint32_t a;
    asm("{ .reg .u64 t; cvta.to.shared.u64 t, %1; cvt.u32.u64 %0, t; }" : "=r"(a) : "l"(p));
    return a;
}
// SW64 swizzle for 64B rows
__device__ __forceinline__ uint32_t swz(uint32_t off) { return off ^ ((off >> 3) & 0x30); }

__device__ __forceinline__ void bulk_g2s(uint32_t dst, const void* src, uint32_t bytes, uint32_t mbar) {
    asm volatile("cp.async.bulk.shared::cta.global.mbarrier::complete_tx::bytes [%0], [%1], %2, [%3];"
        :: "r"(dst), "l"(src), "r"(bytes), "r"(mbar) : "memory");
}
#define MBARRIER_INIT(mbar, count) \
    asm volatile("mbarrier.init.shared.b64 [%0], %1;" :: "r"((uint32_t)(mbar)), "r"((uint32_t)(count)) : "memory")
#define MBARRIER_EXPECT_TX(mbar, bytes) \
    asm volatile("mbarrier.arrive.expect_tx.shared.b64 _, [%0], %1;" :: "r"((uint32_t)(mbar)), "r"((uint32_t)(bytes)) : "memory")
#define MBARRIER_ARRIVE(mbar) \
    asm volatile("mbarrier.arrive.release.cta.shared::cta.b64 _, [%0];" :: "r"((uint32_t)(mbar)) : "memory")
#define MBARRIER_WAIT_PARITY(mbar, parity) do { \
    uint32_t _m = (uint32_t)(mbar), _p = (uint32_t)(parity), _d; \
    asm volatile("{\n\t.reg .pred p;\n\t" \
        "mbarrier.try_wait.parity.acquire.cta.shared::cta.b64 p, [%1], %2;\n\t" \
        "selp.b32 %0, 1, 0, p;\n\t}" : "=r"(_d) : "r"(_m), "r"(_p) : "memory"); \
    if (!_d) { \
        asm volatile("{\n\t.reg .pred P1;\n\t" \
            "WL_%=:\n\t" \
            "mbarrier.try_wait.parity.acquire.cta.shared::cta.b64 P1, [%0], %1, 0x989680;\n\t" \
            "@P1 bra.uni WD_%=;\n\t" \
            "bra.uni WL_%=;\n\t" \
            "WD_%=:\n\t}" :: "r"(_m), "r"(_p) : "memory"); \
    } \
} while (0)

__device__ __forceinline__ void mma_bf16(float* d, const uint32_t* a, const uint32_t* b) {
    asm("mma.sync.aligned.m16n8k16.row.col.f32.bf16.bf16.f32 "
        "{%0,%1,%2,%3}, {%4,%5,%6,%7}, {%8,%9}, {%0,%1,%2,%3};"
        : "+f"(d[0]), "+f"(d[1]), "+f"(d[2]), "+f"(d[3])
        : "r"(a[0]), "r"(a[1]), "r"(a[2]), "r"(a[3]), "r"(b[0]), "r"(b[1]));
}
__device__ __forceinline__ void ldmx4(uint32_t* r, uint32_t addr) {
    asm volatile("ldmatrix.sync.aligned.m8n8.x4.shared.b16 {%0,%1,%2,%3}, [%4];"
        : "=r"(r[0]), "=r"(r[1]), "=r"(r[2]), "=r"(r[3]) : "r"(addr));
}
__device__ __forceinline__ float elu_f(float x) { return x > 0.f ? x : expm1f(x); }
__device__ __forceinline__ void split_bf16(float x, __nv_bfloat16& hi, __nv_bfloat16& lo) {
    hi = __float2bfloat16(x);
    lo = __float2bfloat16(x - __bfloat162float(hi));
}

// ===========================================================================
// GEMM config: CTA tile 128x128, TK=32, triple-buffered stages via
// cp.async.bulk, 8 warps (warp tile 64x32), 2 CTAs/SM.
// Per-slot full/empty mbarriers — NO per-kb __syncthreads (warps drift).
// ===========================================================================
#define TM 128
#define TN 128
#define NSTG 3
#define STAGE_SM 32768
#define DSMEM (1024 + NSTG * STAGE_SM + 96)

#define STAGE_C (ASLOT + SLOT)            // 24576
#define DSMEM_C (1024 + NSTG * STAGE_C + 96)

#define SLOT_PTR(base, bz, bs, tile, kbn, kb) \
    ((base) + ((size_t)(bz) * (bs) + (size_t)(tile) * (kbn) + (kb)) * SLOT)

// barrier block layout (at mb): full[0..2] at +0,+8,+16 ; empty[0..2] at +24,+32,+40
#define INIT_BARRIERS(mb) do { \
    MBARRIER_INIT((mb) + 0, 1);  MBARRIER_INIT((mb) + 8, 1);  MBARRIER_INIT((mb) + 16, 1); \
    MBARRIER_INIT((mb) + 24, 256); MBARRIER_INIT((mb) + 32, 256); MBARRIER_INIT((mb) + 40, 256); \
} while (0)

// ---------------------------------------------------------------------------
// Main GEMM (3-term): C[m,n] = sum_k A[m,k]*B[n,k], fp32 output with M guard.
// ---------------------------------------------------------------------------
__global__ __launch_bounds__(256, 2) void gemm_bulk(
    const char* __restrict__ Ap, int bsA,
    const char* __restrict__ Bp, int bsB,
    float* __restrict__ C, int ldc, size_t sC,
    int kbn, int Mtotal)
{
    extern __shared__ char smem_raw[];
    const uint32_t base = (smem_to_u32(smem_raw) + 1023) & ~1023u;
    const uint32_t mbar = base + NSTG * STAGE_SM;

    const int t    = threadIdx.x;
    const int wid  = t >> 5, lane = t & 31;
    const int gid  = lane >> 2, tig = lane & 3;
    const int bz   = blockIdx.z;
    const int m0   = blockIdx.y * TM;
    const int n0   = blockIdx.x * TN;

    C += (size_t)bz * sC;

    const int wm0 = (wid & 1) * 64;
    const int wn0 = (wid >> 1) * 32;

    float acc[4][4][4];
#pragma unroll
    for (int i = 0; i < 4; i++)
#pragma unroll
        for (int j = 0; j < 4; j++)
#pragma unroll
            for (int q = 0; q < 4; q++) acc[i][j][q] = 0.f;

    if (t == 0) INIT_BARRIERS(mbar);
    __syncthreads();

    auto issue = [&](int kb) {
        int stg = kb % NSTG;
        uint32_t bar = mbar + 8 * stg;
        MBARRIER_EXPECT_TX(bar, 2 * SLOT);
        bulk_g2s(base + stg * STAGE_SM,
                 SLOT_PTR(Ap, bz, bsA, m0 >> 7, kbn, kb), SLOT, bar);
        bulk_g2s(base + stg * STAGE_SM + SLOT,
                 SLOT_PTR(Bp, bz, bsB, n0 >> 7, kbn, kb), SLOT, bar);
    };

    const int arow = lane & 15;
    const int aoff = (lane >> 4) * 16;
    const int bprow = ((lane >> 4) & 1) * 8 + (lane & 7);
    const int bpoff = ((lane >> 3) & 1) * 16;

    if (t == 0) { issue(0); if (1 < kbn) issue(1); }

    for (int kb = 0; kb < kbn; kb++) {
        if (t == 0 && kb + 2 < kbn) {
            if (kb >= 1)  // slot (kb+2)%3 previously consumed at kb-1
                MBARRIER_WAIT_PARITY(mbar + 24 + 8 * ((kb + 2) % NSTG),
                                     ((kb + 2) / NSTG - 1) & 1);
            issue(kb + 2);
        }
        MBARRIER_WAIT_PARITY(mbar + 8 * (kb % NSTG), (kb / NSTG) & 1);

        const uint32_t sb = base + (kb % NSTG) * STAGE_SM;

#pragma unroll
        for (int ks = 0; ks < 2; ks++) {
            uint32_t ah[4][4], al[4][4];
#pragma unroll
            for (int mt = 0; mt < 4; mt++) {
                uint32_t off = swz((wm0 + mt * 16 + arow) * 64 + ks * 32 + aoff);
                ldmx4(ah[mt], sb + off);
                ldmx4(al[mt], sb + HSUB + off);
            }
#pragma unroll
            for (int p = 0; p < 2; p++) {
                uint32_t offb = swz((wn0 + p * 16 + bprow) * 64 + ks * 32 + bpoff);
                uint32_t bh4[4], bl4[4];
                ldmx4(bh4, sb + SLOT + offb);
                ldmx4(bl4, sb + SLOT + HSUB + offb);
#pragma unroll
                for (int mt = 0; mt < 4; mt++)
#pragma unroll
                    for (int h = 0; h < 2; h++)
                        mma_bf16(acc[mt][2 * p + h], ah[mt], bh4 + 2 * h);
#pragma unroll
                for (int mt = 0; mt < 4; mt++)
#pragma unroll
                    for (int h = 0; h < 2; h++)
                        mma_bf16(acc[mt][2 * p + h], ah[mt], bl4 + 2 * h);
#pragma unroll
                for (int mt = 0; mt < 4; mt++)
#pragma unroll
                    for (int h = 0; h < 2; h++)
                        mma_bf16(acc[mt][2 * p + h], al[mt], bh4 + 2 * h);
            }
        }
        MBARRIER_ARRIVE(mbar + 24 + 8 * (kb % NSTG));
    }

#pragma unroll
    for (int mt = 0; mt < 4; mt++) {
        int r0 = m0 + wm0 + mt * 16 + gid;
#pragma unroll
        for (int nt = 0; nt < 4; nt++) {
            int c0 = n0 + wn0 + nt * 8 + 2 * tig;
            if (r0 < Mtotal)
                *(float2*)(C + (size_t)r0 * ldc + c0) =
                    make_float2(acc[mt][nt][0], acc[mt][nt][1]);
            if (r0 + 8 < Mtotal)
                *(float2*)(C + (size_t)(r0 + 8) * ldc + c0) =
                    make_float2(acc[mt][nt][2], acc[mt][nt][3]);
        }
    }
}

// ---------------------------------------------------------------------------
// C GEMM (2-term): A is hi-only (8KB slots), B is hi|lo. 64 MMAs/kb.
// ---------------------------------------------------------------------------
__global__ __launch_bounds__(256, 2) void gemm_c(
    const char* __restrict__ Ap, int bsA,        // bsA in ASLOT units
    const char* __restrict__ Bp, int bsB,        // bsB in SLOT units
    float* __restrict__ C, int ldc, size_t sC,
    int kbn, int Mtotal)
{
    extern __shared__ char smem_raw[];
    const uint32_t base = (smem_to_u32(smem_raw) + 1023) & ~1023u;
    const uint32_t mbar = base + NSTG * STAGE_C;

    const int t    = threadIdx.x;
    const int wid  = t >> 5, lane = t & 31;
    const int gid  = lane >> 2, tig = lane & 3;
    const int bz   = blockIdx.z;
    const int m0   = blockIdx.y * TM;
    const int n0   = blockIdx.x * TN;

    C += (size_t)bz * sC;

    const int wm0 = (wid & 1) * 64;
    const int wn0 = (wid >> 1) * 32;

    float acc[4][4][4];
#pragma unroll
    for (int i = 0; i < 4; i++)
#pragma unroll
        for (int j = 0; j < 4; j++)
#pragma unroll
            for (int q = 0; q < 4; q++) acc[i][j][q] = 0.f;

    if (t == 0) INIT_BARRIERS(mbar);
    __syncthreads();

    auto issue = [&](int kb) {
        int stg = kb % NSTG;
        uint32_t bar = mbar + 8 * stg;
        MBARRIER_EXPECT_TX(bar, ASLOT + SLOT);
        bulk_g2s(base + stg * STAGE_C,
                 Ap + ((size_t)bz * bsA + (size_t)(m0 >> 7) * kbn + kb) * ASLOT,
                 ASLOT, bar);
        bulk_g2s(base + stg * STAGE_C + ASLOT,
                 Bp + ((size_t)bz * bsB + (size_t)(n0 >> 7) * kbn + kb) * SLOT,
                 SLOT, bar);
    };

    const int arow = lane & 15;
    const int aoff = (lane >> 4) * 16;
    const int bprow = ((lane >> 4) & 1) * 8 + (lane & 7);
    const int bpoff = ((lane >> 3) & 1) * 16;

    if (t == 0) { issue(0); if (1 < kbn) issue(1); }

    for (int kb = 0; kb < kbn; kb++) {
        if (t == 0 && kb + 2 < kbn) {
            if (kb >= 1)
                MBARRIER_WAIT_PARITY(mbar + 24 + 8 * ((kb + 2) % NSTG),
                                     ((kb + 2) / NSTG - 1) & 1);
            issue(kb + 2);
        }
        MBARRIER_WAIT_PARITY(mbar + 8 * (kb % NSTG), (kb / NSTG) & 1);

        const uint32_t sb = base + (kb % NSTG) * STAGE_C;

#pragma unroll
        for (int ks = 0; ks < 2; ks++) {
            uint32_t ah[4][4];
#pragma unroll
            for (int mt = 0; mt < 4; mt++) {
                uint32_t off = swz((wm0 + mt * 16 + arow) * 64 + ks * 32 + aoff);
                ldmx4(ah[mt], sb + off);
            }
#pragma unroll
            for (int p = 0; p < 2; p++) {
                uint32_t offb = swz((wn0 + p * 16 + bprow) * 64 + ks * 32 + bpoff);
                uint32_t bh4[4], bl4[4];
                ldmx4(bh4, sb + ASLOT + offb);
                ldmx4(bl4, sb + ASLOT + HSUB + offb);
#pragma unroll
                for (int mt = 0; mt < 4; mt++)
#pragma unroll
                    for (int h = 0; h < 2; h++)
                        mma_bf16(acc[mt][2 * p + h], ah[mt], bh4 + 2 * h);
#pragma unroll
                for (int mt = 0; mt < 4; mt++)
#pragma unroll
                    for (int h = 0; h < 2; h++)
                        mma_bf16(acc[mt][2 * p + h], ah[mt], bl4 + 2 * h);
            }
        }
        MBARRIER_ARRIVE(mbar + 24 + 8 * (kb % NSTG));
    }

#pragma unroll
    for (int mt = 0; mt < 4; mt++) {
        int r0 = m0 + wm0 + mt * 16 + gid;
#pragma unroll
        for (int nt = 0; nt < 4; nt++) {
            int c0 = n0 + wn0 + nt * 8 + 2 * tig;
            if (r0 < Mtotal)
                *(float2*)(C + (size_t)r0 * ldc + c0) =
                    make_float2(acc[mt][nt][0], acc[mt][nt][1]);
            if (r0 + 8 < Mtotal)
                *(float2*)(C + (size_t)(r0 + 8) * ldc + c0) =
                    make_float2(acc[mt][nt][2], acc[mt][nt][3]);
        }
    }
}

// ---------------------------------------------------------------------------
// KV GEMM (3-term): epilogue = bias + ELU + bf16 split into PACKED output.
// ---------------------------------------------------------------------------
__global__ __launch_bounds__(256, 2) void kv_gemm_bulk(
    const char* __restrict__ Ap, int bsA,
    const char* __restrict__ Bp, int bsB,
    char* __restrict__ Op, int bsO, int kbO,
    const float* __restrict__ bias, int biasRow,
    int kbn)
{
    extern __shared__ char smem_raw[];
    const uint32_t base = (smem_to_u32(smem_raw) + 1023) & ~1023u;
    const uint32_t mbar = base + NSTG * STAGE_SM;

    const int t    = threadIdx.x;
    const int wid  = t >> 5, lane = t & 31;
    const int gid  = lane >> 2, tig = lane & 3;
    const int bz   = blockIdx.z;
    const int m0   = blockIdx.y * TM;
    const int n0   = blockIdx.x * TN;

    const int wm0 = (wid & 1) * 64;
    const int wn0 = (wid >> 1) * 32;

    float acc[4][4][4];
#pragma unroll
    for (int i = 0; i < 4; i++)
#pragma unroll
        for (int j = 0; j < 4; j++)
#pragma unroll
            for (int q = 0; q < 4; q++) acc[i][j][q] = 0.f;

    if (t == 0) INIT_BARRIERS(mbar);
    __syncthreads();

    auto issue = [&](int kb) {
        int stg = kb % NSTG;
        uint32_t bar = mbar + 8 * stg;
        MBARRIER_EXPECT_TX(bar, 2 * SLOT);
        bulk_g2s(base + stg * STAGE_SM,
                 SLOT_PTR(Ap, bz, bsA, m0 >> 7, kbn, kb), SLOT, bar);
        bulk_g2s(base + stg * STAGE_SM + SLOT,
                 SLOT_PTR(Bp, bz, bsB, n0 >> 7, kbn, kb), SLOT, bar);
    };

    const int arow = lane & 15;
    const int aoff = (lane >> 4) * 16;
    const int bprow = ((lane >> 4) & 1) * 8 + (lane & 7);
    const int bpoff = ((lane >> 3) & 1) * 16;

    if (t == 0) { issue(0); if (1 < kbn) issue(1); }

    for (int kb = 0; kb < kbn; kb++) {
        if (t == 0 && kb + 2 < kbn) {
            if (kb >= 1)
                MBARRIER_WAIT_PARITY(mbar + 24 + 8 * ((kb + 2) % NSTG),
                                     ((kb + 2) / NSTG - 1) & 1);
            issue(kb + 2);
        }
        MBARRIER_WAIT_PARITY(mbar + 8 * (kb % NSTG), (kb / NSTG) & 1);

        const uint32_t sb = base + (kb % NSTG) * STAGE_SM;

#pragma unroll
        for (int ks = 0; ks < 2; ks++) {
            uint32_t ah[4][4], al[4][4];
#pragma unroll
            for (int mt = 0; mt < 4; mt++) {
                uint32_t off = swz((wm0 + mt * 16 + arow) * 64 + ks * 32 + aoff);
                ldmx4(ah[mt], sb + off);
                ldmx4(al[mt], sb + HSUB + off);
            }
#pragma unroll
            for (int p = 0; p < 2; p++) {
                uint32_t offb = swz((wn0 + p * 16 + bprow) * 64 + ks * 32 + bpoff);
                uint32_t bh4[4], bl4[4];
                ldmx4(bh4, sb + SLOT + offb);
                ldmx4(bl4, sb + SLOT + HSUB + offb);
#pragma unroll
                for (int mt = 0; mt < 4; mt++)
#pragma unroll
                    for (int h = 0; h < 2; h++)
                        mma_bf16(acc[mt][2 * p + h], ah[mt], bh4 + 2 * h);
#pragma unroll
                for (int mt = 0; mt < 4; mt++)
#pragma unroll
                    for (int h = 0; h < 2; h++)
                        mma_bf16(acc[mt][2 * p + h], ah[mt], bl4 + 2 * h);
#pragma unroll
                for (int mt = 0; mt < 4; mt++)
#pragma unroll
                    for (int h = 0; h < 2; h++)
                        mma_bf16(acc[mt][2 * p + h], al[mt], bh4 + 2 * h);
            }
        }
        MBARRIER_ARRIVE(mbar + 24 + 8 * (kb % NSTG));
    }

    // epilogue: packed-swizzled bf16 hi/lo writes
#pragma unroll
    for (int mt = 0; mt < 4; mt++) {
#pragma unroll
        for (int half = 0; half < 2; half++) {
            int m = m0 + wm0 + mt * 16 + gid + half * 8;
#pragma unroll
            for (int nt = 0; nt < 4; nt++) {
                int n = n0 + wn0 + nt * 8 + 2 * tig;
                float v0 = acc[mt][nt][2 * half + 0];
                float v1 = acc[mt][nt][2 * half + 1];
                float b0 = biasRow ? bias[m] : bias[n];
                float b1 = biasRow ? bias[m] : bias[n + 1];
                __nv_bfloat16 h0, l0, h1, l1;
                split_bf16(elu_f(v0 + b0), h0, l0);
                split_bf16(elu_f(v1 + b1), h1, l1);
                char* slot = Op + ((size_t)bz * bsO + (size_t)(m >> 7) * kbO + (n >> 5)) * SLOT;
                uint32_t off = swz((uint32_t)(m & 127) * 64 + (uint32_t)(n & 31) * 2);
                *(__nv_bfloat162*)(slot + off)        = __nv_bfloat162(h0, h1);
                *(__nv_bfloat162*)(slot + HSUB + off) = __nv_bfloat162(l0, l1);
            }
        }
    }
}

// ===========================================================================
// Packers
// ===========================================================================
__global__ __launch_bounds__(256) void pack_q(const float* __restrict__ Q)
{
    int row = blockIdx.x;                     // 0..8959
    int src = row < L_ ? row : L_ - 1;
    int t = threadIdx.x;
    float2 v = *(const float2*)(Q + (size_t)src * D_ + t * 2);
    __nv_bfloat16 h0, l0, h1, l1;
    split_bf16(v.x, h0, l0);
    split_bf16(v.y, h1, l1);
    int r = row & 127, tile = row >> 7;
    int d0 = t * 2, kb = d0 >> 5, c = d0 & 31;
    char* slot = g_Qp + ((size_t)tile * 16 + kb) * SLOT;
    uint32_t off = swz((uint32_t)r * 64 + (uint32_t)c * 2);
    *(__nv_bfloat162*)(slot + off)        = __nv_bfloat162(h0, h1);
    *(__nv_bfloat162*)(slot + HSUB + off) = __nv_bfloat162(l0, l1);
}

__global__ __launch_bounds__(256) void pack_h(const float* __restrict__ H)
{
    __shared__ float tile[64][33];
    const int b = blockIdx.z, s0 = blockIdx.x * 32, d0 = blockIdx.y * 64;
    const int tx = threadIdx.x, ty = threadIdx.y;
    const float* Hb = H + ((size_t)b * D_ + d0) * S_ + s0;

#pragma unroll
    for (int i = 0; i < 8; i++)
        tile[ty * 8 + i][tx] = Hb[(size_t)(ty * 8 + i) * S_ + tx];
    __syncthreads();

    const int t = ty * 32 + tx;
    const int s = t & 31;
    const int dp = t >> 5;
    const int gs = s0 + s;
    const int r = gs & 127;
#pragma unroll
    for (int i = 0; i < 4; i++) {
        int d = dp * 2 + i * 16;
        int kbl = d >> 5, c = d & 31;
        char* slot = g_Hp + (((size_t)b * 16 + (gs >> 7)) * 16 + blockIdx.y * 2 + kbl) * SLOT;
        __nv_bfloat16 h0, l0, h1, l1;
        split_bf16(tile[d][s], h0, l0);
        split_bf16(tile[d + 1][s], h1, l1);
        uint32_t off = swz((uint32_t)r * 64 + (uint32_t)c * 2);
        *(__nv_bfloat162*)(slot + off)        = __nv_bfloat162(h0, h1);
        *(__nv_bfloat162*)(slot + HSUB + off) = __nv_bfloat162(l0, l1);
    }
}

__global__ __launch_bounds__(256) void pack_w(
    const float* __restrict__ Wk, const float* __restrict__ Wv)
{
    int which = blockIdx.x >> 9;
    int o = blockIdx.x & 511;
    const float* W = which ? Wv : Wk;
    int t = threadIdx.x;
    float2 v = *(const float2*)(W + (size_t)o * D_ + t * 2);
    __nv_bfloat16 h0, l0, h1, l1;
    split_bf16(v.x, h0, l0);
    split_bf16(v.y, h1, l1);
    int r = o & 127, tile = o >> 7;
    int d0 = t * 2, kb = d0 >> 5, c = d0 & 31;
    char* slot = g_Wp + (((size_t)which * 4 + tile) * 16 + kb) * SLOT;
    uint32_t off = swz((uint32_t)r * 64 + (uint32_t)c * 2);
    *(__nv_bfloat162*)(slot + off)        = __nv_bfloat162(h0, h1);
    *(__nv_bfloat162*)(slot + HSUB + off) = __nv_bfloat162(l0, l1);
}

// ===========================================================================
// In-place row softmax over S=2048; emits packed bf16 HI of A only.
// ===========================================================================
__global__ __launch_bounds__(256) void softmax_kernel(float* __restrict__ A)
{
    const int row = blockIdx.x;               // b*L + l
    const int b = row / L_;
    const int l = row - b * L_;
    float* p = A + (size_t)row * S_;
    const int t = threadIdx.x;
    const int lane = t & 31, wid = t >> 5;

    float4 va = *(const float4*)(p + t * 4);
    float4 vb = *(const float4*)(p + 1024 + t * 4);

    float m = fmaxf(fmaxf(fmaxf(va.x, va.y), fmaxf(va.z, va.w)),
                    fmaxf(fmaxf(vb.x, vb.y), fmaxf(vb.z, vb.w)));
#pragma unroll
    for (int o = 16; o > 0; o >>= 1) m = fmaxf(m, __shfl_xor_sync(0xffffffffu, m, o));

    __shared__ float red[8];
    if (lane == 0) red[wid] = m;
    __syncthreads();
    {
        float r = red[lane & 7];
#pragma unroll
        for (int o = 4; o > 0; o >>= 1) r = fmaxf(r, __shfl_xor_sync(0xffffffffu, r, o));
        m = r;
    }

    va.x = __expf(va.x - m); va.y = __expf(va.y - m);
    va.z = __expf(va.z - m); va.w = __expf(va.w - m);
    vb.x = __expf(vb.x - m); vb.y = __expf(vb.y - m);
    vb.z = __expf(vb.z - m); vb.w = __expf(vb.w - m);

    float s = va.x + va.y + va.z + va.w + vb.x + vb.y + vb.z + vb.w;
#pragma unroll
    for (int o = 16; o > 0; o >>= 1) s += __shfl_xor_sync(0xffffffffu, s, o);
    __syncthreads();
    if (lane == 0) red[wid] = s;
    __syncthreads();
    {
        float r = red[lane & 7];
#pragma unroll
        for (int o = 4; o > 0; o >>= 1) r += __shfl_xor_sync(0xffffffffu, r, o);
        s = r;
    }
    float inv = 1.f / s;

    va.x *= inv; va.y *= inv; va.z *= inv; va.w *= inv;
    vb.x *= inv; vb.y *= inv; vb.z *= inv; vb.w *= inv;

    *(float4*)(p + t * 4) = va;
    *(float4*)(p + 1024 + t * 4) = vb;

    char* tslot = g_Ap + ((size_t)b * (70 * 64) + (size_t)(l >> 7) * 64) * ASLOT;
    const uint32_t r = l & 127;

    float g[2][4] = {{va.x, va.y, va.z, va.w}, {vb.x, vb.y, vb.z, vb.w}};
#pragma unroll
    for (int half = 0; half < 2; half++) {
        int sidx = half * 1024 + t * 4;
        int kb = sidx >> 5, c = sidx & 31;
        char* slot = tslot + (size_t)kb * ASLOT;
        uint32_t off = swz(r * 64 + (uint32_t)c * 2);
        *(__nv_bfloat162*)(slot + off) =
            __nv_bfloat162(__float2bfloat16(g[half][0]), __float2bfloat16(g[half][1]));
        *(__nv_bfloat162*)(slot + off + 4) =
            __nv_bfloat162(__float2bfloat16(g[half][2]), __float2bfloat16(g[half][3]));
    }
}

// ===========================================================================
extern "C" void kernel_launch(void* const* d_in, const int* in_sizes, int n_in,
                              void* d_out, int out_size)
{
    const float* H  = (const float*)d_in[0];
    const float* Wk = (const float*)d_in[1];
    const float* bk = (const float*)d_in[2];
    const float* Wv = (const float*)d_in[3];
    const float* bv = (const float*)d_in[4];
    const float* Q  = (const float*)d_in[5];

    float* out  = (float*)d_out;
    float* Cout = out;                          // [B, L, D]
    float* Aout = out + (size_t)B_ * L_ * D_;   // [B, L, S]

    static char *gQp, *gHp, *gWp, *gKp, *gVp, *gAp;
    static bool init = false;
    if (!init) {
        cudaGetSymbolAddress((void**)&gQp, g_Qp);
        cudaGetSymbolAddress((void**)&gHp, g_Hp);
        cudaGetSymbolAddress((void**)&gWp, g_Wp);
        cudaGetSymbolAddress((void**)&gKp, g_Kp);
        cudaGetSymbolAddress((void**)&gVp, g_Vp);
        cudaGetSymbolAddress((void**)&gAp, g_Ap);
        cudaFuncSetAttribute(gemm_bulk, cudaFuncAttributeMaxDynamicSharedMemorySize, DSMEM);
        cudaFuncSetAttribute(gemm_c, cudaFuncAttributeMaxDynamicSharedMemorySize, DSMEM_C);
        cudaFuncSetAttribute(kv_gemm_bulk, cudaFuncAttributeMaxDynamicSharedMemorySize, DSMEM);
        init = true;
    }

    // 0) packers
    pack_q<<<8960, 256>>>(Q);
    pack_h<<<dim3(S_ / 32, D_ / 64, B_), dim3(32, 8)>>>(H);
    pack_w<<<1024, 256>>>(Wk, Wv);

    // 1a) K = H^T * Wk
    kv_gemm_bulk<<<dim3(D_ / TN, S_ / TM, B_), 256, DSMEM>>>(
        gHp, 256, gWp, 0,
        gKp, 256, 16, bk, 0, 16);

    // 1b) V^T = Wv * H^T
    kv_gemm_bulk<<<dim3(S_ / TN, D_ / TM, B_), 256, DSMEM>>>(
        gWp + (size_t)64 * SLOT, 0, gHp, 256,
        gVp, 256, 64, bv, 1, 16);

    // 2) E = Q K^T -> Aout (fp32), 3-term
    gemm_bulk<<<dim3(S_ / TN, 70, B_), 256, DSMEM>>>(
        gQp, 0, gKp, 256,
        Aout, S_, (size_t)L_ * S_, 16, L_);

    // 3) softmax (+ packed HI split of A)
    softmax_kernel<<<dim3(B_ * L_), 256>>>(Aout);

    // 4) C = A V -> Cout, 2-term (A hi-only)
    gemm_c<<<dim3(D_ / TN, 70, B_), 256, DSMEM_C>>>(
        gAp, 70 * 64, gVp, 256,
        Cout, D_, (size_t)L_ * D_, 64, L_);
}

// round 15
// speedup vs baseline: 1.9808x; 1.1607x over previous
#include <cuda_runtime.h>
#include <cuda_bf16.h>
#include <cuda_fp16.h>
#include <math.h>
#include <cstdint>

#define B_ 4
#define D_ 512
#define S_ 2048
#define L_ 8921

#define SLOT 16384              // packed (tile128 x k32) slot: hi 8KB | lo 8KB
#define HSUB 8192
#define ASLOT 8192              // single-precision-operand slot (fp16/bf16 single)

// Packed operand buffers (swizzled tiles, bulk-copy ready)
__device__ char g_Qp[(size_t)70 * 16 * SLOT];            // Q  [8960, 512] bf16 hi|lo
__device__ char g_Hp[(size_t)4 * 16 * 16 * SLOT];        // H^T per b: [2048, 512] bf16 hi|lo
__device__ char g_Wp[(size_t)2 * 4 * 16 * SLOT];         // Wk|Wv [512, 512] bf16 hi|lo
__device__ char g_Kp[(size_t)4 * 16 * 16 * SLOT];        // K per b: [2048, 512] bf16 hi|lo
__device__ char g_Vp[(size_t)4 * 4 * 64 * ASLOT];        // V^T per b: [512, 2048] FP16 single
__device__ char g_Ap[(size_t)4 * 70 * 64 * ASLOT];       // attn per b: [8960, 2048] FP16 single

// ---------------------------------------------------------------------------
// helpers
// ---------------------------------------------------------------------------
__device__ __forceinline__ uint32_t smem_to_u32(const void* p) {
    uint32_t a;
    asm("{ .reg .u64 t; cvta.to.shared.u64 t, %1; cvt.u32.u64 %0, t; }" : "=r"(a) : "l"(p));
    return a;
}
// SW64 swizzle for 64B rows
__device__ __forceinline__ uint32_t swz(uint32_t off) { return off ^ ((off >> 3) & 0x30); }

__device__ __forceinline__ void bulk_g2s(uint32_t dst, const void* src, uint32_t bytes, uint32_t mbar) {
    asm volatile("cp.async.bulk.shared::cta.global.mbarrier::complete_tx::bytes [%0], [%1], %2, [%3];"
        :: "r"(dst), "l"(src), "r"(bytes), "r"(mbar) : "memory");
}
#define MBARRIER_INIT(mbar, count) \
    asm volatile("mbarrier.init.shared.b64 [%0], %1;" :: "r"((uint32_t)(mbar)), "r"((uint32_t)(count)) : "memory")
#define MBARRIER_EXPECT_TX(mbar, bytes) \
    asm volatile("mbarrier.arrive.expect_tx.shared.b64 _, [%0], %1;" :: "r"((uint32_t)(mbar)), "r"((uint32_t)(bytes)) : "memory")
#define MBARRIER_ARRIVE(mbar) \
    asm volatile("mbarrier.arrive.release.cta.shared::cta.b64 _, [%0];" :: "r"((uint32_t)(mbar)) : "memory")
#define MBARRIER_WAIT_PARITY(mbar, parity) do { \
    uint32_t _m = (uint32_t)(mbar), _p = (uint32_t)(parity), _d; \
    asm volatile("{\n\t.reg .pred p;\n\t" \
        "mbarrier.try_wait.parity.acquire.cta.shared::cta.b64 p, [%1], %2;\n\t" \
        "selp.b32 %0, 1, 0, p;\n\t}" : "=r"(_d) : "r"(_m), "r"(_p) : "memory"); \
    if (!_d) { \
        asm volatile("{\n\t.reg .pred P1;\n\t" \
            "WL_%=:\n\t" \
            "mbarrier.try_wait.parity.acquire.cta.shared::cta.b64 P1, [%0], %1, 0x989680;\n\t" \
            "@P1 bra.uni WD_%=;\n\t" \
            "bra.uni WL_%=;\n\t" \
            "WD_%=:\n\t}" :: "r"(_m), "r"(_p) : "memory"); \
    } \
} while (0)

__device__ __forceinline__ void mma_bf16(float* d, const uint32_t* a, const uint32_t* b) {
    asm("mma.sync.aligned.m16n8k16.row.col.f32.bf16.bf16.f32 "
        "{%0,%1,%2,%3}, {%4,%5,%6,%7}, {%8,%9}, {%0,%1,%2,%3};"
        : "+f"(d[0]), "+f"(d[1]), "+f"(d[2]), "+f"(d[3])
        : "r"(a[0]), "r"(a[1]), "r"(a[2]), "r"(a[3]), "r"(b[0]), "r"(b[1]));
}
__device__ __forceinline__ void mma_f16(float* d, const uint32_t* a, const uint32_t* b) {
    asm("mma.sync.aligned.m16n8k16.row.col.f32.f16.f16.f32 "
        "{%0,%1,%2,%3}, {%4,%5,%6,%7}, {%8,%9}, {%0,%1,%2,%3};"
        : "+f"(d[0]), "+f"(d[1]), "+f"(d[2]), "+f"(d[3])
        : "r"(a[0]), "r"(a[1]), "r"(a[2]), "r"(a[3]), "r"(b[0]), "r"(b[1]));
}
__device__ __forceinline__ void ldmx4(uint32_t* r, uint32_t addr) {
    asm volatile("ldmatrix.sync.aligned.m8n8.x4.shared.b16 {%0,%1,%2,%3}, [%4];"
        : "=r"(r[0]), "=r"(r[1]), "=r"(r[2]), "=r"(r[3]) : "r"(addr));
}
__device__ __forceinline__ float elu_f(float x) { return x > 0.f ? x : expm1f(x); }
__device__ __forceinline__ void split_bf16(float x, __nv_bfloat16& hi, __nv_bfloat16& lo) {
    hi = __float2bfloat16(x);
    lo = __float2bfloat16(x - __bfloat162float(hi));
}

// ===========================================================================
// GEMM config: CTA tile 128x128, TK=32, triple-buffered stages via
// cp.async.bulk, 8 warps (warp tile 64x32), 2 CTAs/SM.
// Per-slot full/empty mbarriers — no per-kb __syncthreads.
// ===========================================================================
#define TM 128
#define TN 128
#define NSTG 3
#define STAGE_SM 32768
#define DSMEM (1024 + NSTG * STAGE_SM + 96)

#define STAGE_C (2 * ASLOT)               // 16384 (fp16 A | fp16 V)
#define DSMEM_C (1024 + NSTG * STAGE_C + 96)

#define SLOT_PTR(base, bz, bs, tile, kbn, kb) \
    ((base) + ((size_t)(bz) * (bs) + (size_t)(tile) * (kbn) + (kb)) * SLOT)

// barrier block: full[0..2] at +0,+8,+16 ; empty[0..2] at +24,+32,+40
#define INIT_BARRIERS(mb) do { \
    MBARRIER_INIT((mb) + 0, 1);  MBARRIER_INIT((mb) + 8, 1);  MBARRIER_INIT((mb) + 16, 1); \
    MBARRIER_INIT((mb) + 24, 256); MBARRIER_INIT((mb) + 32, 256); MBARRIER_INIT((mb) + 40, 256); \
} while (0)

// ---------------------------------------------------------------------------
// E GEMM (3-term bf16): C[m,n] = sum_k A[m,k]*B[n,k], fp32 output, M guard.
// ---------------------------------------------------------------------------
__global__ __launch_bounds__(256, 2) void gemm_bulk(
    const char* __restrict__ Ap, int bsA,
    const char* __restrict__ Bp, int bsB,
    float* __restrict__ C, int ldc, size_t sC,
    int kbn, int Mtotal)
{
    extern __shared__ char smem_raw[];
    const uint32_t base = (smem_to_u32(smem_raw) + 1023) & ~1023u;
    const uint32_t mbar = base + NSTG * STAGE_SM;

    const int t    = threadIdx.x;
    const int wid  = t >> 5, lane = t & 31;
    const int gid  = lane >> 2, tig = lane & 3;
    const int bz   = blockIdx.z;
    const int m0   = blockIdx.y * TM;
    const int n0   = blockIdx.x * TN;

    C += (size_t)bz * sC;

    const int wm0 = (wid & 1) * 64;
    const int wn0 = (wid >> 1) * 32;

    float acc[4][4][4];
#pragma unroll
    for (int i = 0; i < 4; i++)
#pragma unroll
        for (int j = 0; j < 4; j++)
#pragma unroll
            for (int q = 0; q < 4; q++) acc[i][j][q] = 0.f;

    if (t == 0) INIT_BARRIERS(mbar);
    __syncthreads();

    auto issue = [&](int kb) {
        int stg = kb % NSTG;
        uint32_t bar = mbar + 8 * stg;
        MBARRIER_EXPECT_TX(bar, 2 * SLOT);
        bulk_g2s(base + stg * STAGE_SM,
                 SLOT_PTR(Ap, bz, bsA, m0 >> 7, kbn, kb), SLOT, bar);
        bulk_g2s(base + stg * STAGE_SM + SLOT,
                 SLOT_PTR(Bp, bz, bsB, n0 >> 7, kbn, kb), SLOT, bar);
    };

    const int arow = lane & 15;
    const int aoff = (lane >> 4) * 16;
    const int bprow = ((lane >> 4) & 1) * 8 + (lane & 7);
    const int bpoff = ((lane >> 3) & 1) * 16;

    if (t == 0) { issue(0); if (1 < kbn) issue(1); }

    for (int kb = 0; kb < kbn; kb++) {
        if (t == 0 && kb + 2 < kbn) {
            if (kb >= 1)
                MBARRIER_WAIT_PARITY(mbar + 24 + 8 * ((kb + 2) % NSTG),
                                     ((kb + 2) / NSTG - 1) & 1);
            issue(kb + 2);
        }
        MBARRIER_WAIT_PARITY(mbar + 8 * (kb % NSTG), (kb / NSTG) & 1);

        const uint32_t sb = base + (kb % NSTG) * STAGE_SM;

#pragma unroll
        for (int ks = 0; ks < 2; ks++) {
            uint32_t ah[4][4], al[4][4];
#pragma unroll
            for (int mt = 0; mt < 4; mt++) {
                uint32_t off = swz((wm0 + mt * 16 + arow) * 64 + ks * 32 + aoff);
                ldmx4(ah[mt], sb + off);
                ldmx4(al[mt], sb + HSUB + off);
            }
#pragma unroll
            for (int p = 0; p < 2; p++) {
                uint32_t offb = swz((wn0 + p * 16 + bprow) * 64 + ks * 32 + bpoff);
                uint32_t bh4[4], bl4[4];
                ldmx4(bh4, sb + SLOT + offb);
                ldmx4(bl4, sb + SLOT + HSUB + offb);
#pragma unroll
                for (int mt = 0; mt < 4; mt++)
#pragma unroll
                    for (int h = 0; h < 2; h++)
                        mma_bf16(acc[mt][2 * p + h], ah[mt], bh4 + 2 * h);
#pragma unroll
                for (int mt = 0; mt < 4; mt++)
#pragma unroll
                    for (int h = 0; h < 2; h++)
                        mma_bf16(acc[mt][2 * p + h], ah[mt], bl4 + 2 * h);
#pragma unroll
                for (int mt = 0; mt < 4; mt++)
#pragma unroll
                    for (int h = 0; h < 2; h++)
                        mma_bf16(acc[mt][2 * p + h], al[mt], bh4 + 2 * h);
            }
        }
        MBARRIER_ARRIVE(mbar + 24 + 8 * (kb % NSTG));
    }

#pragma unroll
    for (int mt = 0; mt < 4; mt++) {
        int r0 = m0 + wm0 + mt * 16 + gid;
#pragma unroll
        for (int nt = 0; nt < 4; nt++) {
            int c0 = n0 + wn0 + nt * 8 + 2 * tig;
            if (r0 < Mtotal)
                *(float2*)(C + (size_t)r0 * ldc + c0) =
                    make_float2(acc[mt][nt][0], acc[mt][nt][1]);
            if (r0 + 8 < Mtotal)
                *(float2*)(C + (size_t)(r0 + 8) * ldc + c0) =
                    make_float2(acc[mt][nt][2], acc[mt][nt][3]);
        }
    }
}

// ---------------------------------------------------------------------------
// C GEMM (1-product fp16): A fp16 single x V fp16 single, f32 accumulate.
// ---------------------------------------------------------------------------
__global__ __launch_bounds__(256, 2) void gemm_c(
    const char* __restrict__ Ap, int bsA,        // in ASLOT units
    const char* __restrict__ Bp, int bsB,        // in ASLOT units
    float* __restrict__ C, int ldc, size_t sC,
    int kbn, int Mtotal)
{
    extern __shared__ char smem_raw[];
    const uint32_t base = (smem_to_u32(smem_raw) + 1023) & ~1023u;
    const uint32_t mbar = base + NSTG * STAGE_C;

    const int t    = threadIdx.x;
    const int wid  = t >> 5, lane = t & 31;
    const int gid  = lane >> 2, tig = lane & 3;
    const int bz   = blockIdx.z;
    const int m0   = blockIdx.y * TM;
    const int n0   = blockIdx.x * TN;

    C += (size_t)bz * sC;

    const int wm0 = (wid & 1) * 64;
    const int wn0 = (wid >> 1) * 32;

    float acc[4][4][4];
#pragma unroll
    for (int i = 0; i < 4; i++)
#pragma unroll
        for (int j = 0; j < 4; j++)
#pragma unroll
            for (int q = 0; q < 4; q++) acc[i][j][q] = 0.f;

    if (t == 0) INIT_BARRIERS(mbar);
    __syncthreads();

    auto issue = [&](int kb) {
        int stg = kb % NSTG;
        uint32_t bar = mbar + 8 * stg;
        MBARRIER_EXPECT_TX(bar, 2 * ASLOT);
        bulk_g2s(base + stg * STAGE_C,
                 Ap + ((size_t)bz * bsA + (size_t)(m0 >> 7) * kbn + kb) * ASLOT,
                 ASLOT, bar);
        bulk_g2s(base + stg * STAGE_C + ASLOT,
                 Bp + ((size_t)bz * bsB + (size_t)(n0 >> 7) * kbn + kb) * ASLOT,
                 ASLOT, bar);
    };

    const int arow = lane & 15;
    const int aoff = (lane >> 4) * 16;
    const int bprow = ((lane >> 4) & 1) * 8 + (lane & 7);
    const int bpoff = ((lane >> 3) & 1) * 16;

    if (t == 0) { issue(0); if (1 < kbn) issue(1); }

    for (int kb = 0; kb < kbn; kb++) {
        if (t == 0 && kb + 2 < kbn) {
            if (kb >= 1)
                MBARRIER_WAIT_PARITY(mbar + 24 + 8 * ((kb + 2) % NSTG),
                                     ((kb + 2) / NSTG - 1) & 1);
            issue(kb + 2);
        }
        MBARRIER_WAIT_PARITY(mbar + 8 * (kb % NSTG), (kb / NSTG) & 1);

        const uint32_t sb = base + (kb % NSTG) * STAGE_C;

#pragma unroll
        for (int ks = 0; ks < 2; ks++) {
            uint32_t ah[4][4];
#pragma unroll
            for (int mt = 0; mt < 4; mt++) {
                uint32_t off = swz((wm0 + mt * 16 + arow) * 64 + ks * 32 + aoff);
                ldmx4(ah[mt], sb + off);
            }
#pragma unroll
            for (int p = 0; p < 2; p++) {
                uint32_t offb = swz((wn0 + p * 16 + bprow) * 64 + ks * 32 + bpoff);
                uint32_t bh4[4];
                ldmx4(bh4, sb + ASLOT + offb);
#pragma unroll
                for (int mt = 0; mt < 4; mt++)
#pragma unroll
                    for (int h = 0; h < 2; h++)
                        mma_f16(acc[mt][2 * p + h], ah[mt], bh4 + 2 * h);
            }
        }
        MBARRIER_ARRIVE(mbar + 24 + 8 * (kb % NSTG));
    }

#pragma unroll
    for (int mt = 0; mt < 4; mt++) {
        int r0 = m0 + wm0 + mt * 16 + gid;
#pragma unroll
        for (int nt = 0; nt < 4; nt++) {
            int c0 = n0 + wn0 + nt * 8 + 2 * tig;
            if (r0 < Mtotal)
                *(float2*)(C + (size_t)r0 * ldc + c0) =
                    make_float2(acc[mt][nt][0], acc[mt][nt][1]);
            if (r0 + 8 < Mtotal)
                *(float2*)(C + (size_t)(r0 + 8) * ldc + c0) =
                    make_float2(acc[mt][nt][2], acc[mt][nt][3]);
        }
    }
}

// ---------------------------------------------------------------------------
// KV GEMM (3-term bf16): epilogue = bias + ELU; output either bf16 hi/lo
// packed (outHalf=0, SLOT) or fp16 single packed (outHalf=1, ASLOT).
// ---------------------------------------------------------------------------
__global__ __launch_bounds__(256, 2) void kv_gemm_bulk(
    const char* __restrict__ Ap, int bsA,
    const char* __restrict__ Bp, int bsB,
    char* __restrict__ Op, int bsO, int kbO,
    const float* __restrict__ bias, int biasRow, int outHalf,
    int kbn)
{
    extern __shared__ char smem_raw[];
    const uint32_t base = (smem_to_u32(smem_raw) + 1023) & ~1023u;
    const uint32_t mbar = base + NSTG * STAGE_SM;

    const int t    = threadIdx.x;
    const int wid  = t >> 5, lane = t & 31;
    const int gid  = lane >> 2, tig = lane & 3;
    const int bz   = blockIdx.z;
    const int m0   = blockIdx.y * TM;
    const int n0   = blockIdx.x * TN;

    const int wm0 = (wid & 1) * 64;
    const int wn0 = (wid >> 1) * 32;

    float acc[4][4][4];
#pragma unroll
    for (int i = 0; i < 4; i++)
#pragma unroll
        for (int j = 0; j < 4; j++)
#pragma unroll
            for (int q = 0; q < 4; q++) acc[i][j][q] = 0.f;

    if (t == 0) INIT_BARRIERS(mbar);
    __syncthreads();

    auto issue = [&](int kb) {
        int stg = kb % NSTG;
        uint32_t bar = mbar + 8 * stg;
        MBARRIER_EXPECT_TX(bar, 2 * SLOT);
        bulk_g2s(base + stg * STAGE_SM,
                 SLOT_PTR(Ap, bz, bsA, m0 >> 7, kbn, kb), SLOT, bar);
        bulk_g2s(base + stg * STAGE_SM + SLOT,
                 SLOT_PTR(Bp, bz, bsB, n0 >> 7, kbn, kb), SLOT, bar);
    };

    const int arow = lane & 15;
    const int aoff = (lane >> 4) * 16;
    const int bprow = ((lane >> 4) & 1) * 8 + (lane & 7);
    const int bpoff = ((lane >> 3) & 1) * 16;

    if (t == 0) { issue(0); if (1 < kbn) issue(1); }

    for (int kb = 0; kb < kbn; kb++) {
        if (t == 0 && kb + 2 < kbn) {
            if (kb >= 1)
                MBARRIER_WAIT_PARITY(mbar + 24 + 8 * ((kb + 2) % NSTG),
                                     ((kb + 2) / NSTG - 1) & 1);
            issue(kb + 2);
        }
        MBARRIER_WAIT_PARITY(mbar + 8 * (kb % NSTG), (kb / NSTG) & 1);

        const uint32_t sb = base + (kb % NSTG) * STAGE_SM;

#pragma unroll
        for (int ks = 0; ks < 2; ks++) {
            uint32_t ah[4][4], al[4][4];
#pragma unroll
            for (int mt = 0; mt < 4; mt++) {
                uint32_t off = swz((wm0 + mt * 16 + arow) * 64 + ks * 32 + aoff);
                ldmx4(ah[mt], sb + off);
                ldmx4(al[mt], sb + HSUB + off);
            }
#pragma unroll
            for (int p = 0; p < 2; p++) {
                uint32_t offb = swz((wn0 + p * 16 + bprow) * 64 + ks * 32 + bpoff);
                uint32_t bh4[4], bl4[4];
                ldmx4(bh4, sb + SLOT + offb);
                ldmx4(bl4, sb + SLOT + HSUB + offb);
#pragma unroll
                for (int mt = 0; mt < 4; mt++)
#pragma unroll
                    for (int h = 0; h < 2; h++)
                        mma_bf16(acc[mt][2 * p + h], ah[mt], bh4 + 2 * h);
#pragma unroll
                for (int mt = 0; mt < 4; mt++)
#pragma unroll
                    for (int h = 0; h < 2; h++)
                        mma_bf16(acc[mt][2 * p + h], ah[mt], bl4 + 2 * h);
#pragma unroll
                for (int mt = 0; mt < 4; mt++)
#pragma unroll
                    for (int h = 0; h < 2; h++)
                        mma_bf16(acc[mt][2 * p + h], al[mt], bh4 + 2 * h);
            }
        }
        MBARRIER_ARRIVE(mbar + 24 + 8 * (kb % NSTG));
    }

    // epilogue
#pragma unroll
    for (int mt = 0; mt < 4; mt++) {
#pragma unroll
        for (int half = 0; half < 2; half++) {
            int m = m0 + wm0 + mt * 16 + gid + half * 8;
#pragma unroll
            for (int nt = 0; nt < 4; nt++) {
                int n = n0 + wn0 + nt * 8 + 2 * tig;
                float v0 = acc[mt][nt][2 * half + 0];
                float v1 = acc[mt][nt][2 * half + 1];
                float b0 = biasRow ? bias[m] : bias[n];
                float b1 = biasRow ? bias[m] : bias[n + 1];
                float e0 = elu_f(v0 + b0);
                float e1 = elu_f(v1 + b1);
                uint32_t off = swz((uint32_t)(m & 127) * 64 + (uint32_t)(n & 31) * 2);
                if (!outHalf) {
                    __nv_bfloat16 h0, l0, h1, l1;
                    split_bf16(e0, h0, l0);
                    split_bf16(e1, h1, l1);
                    char* slot = Op + ((size_t)bz * bsO + (size_t)(m >> 7) * kbO + (n >> 5)) * SLOT;
                    *(__nv_bfloat162*)(slot + off)        = __nv_bfloat162(h0, h1);
                    *(__nv_bfloat162*)(slot + HSUB + off) = __nv_bfloat162(l0, l1);
                } else {
                    char* slot = Op + ((size_t)bz * bsO + (size_t)(m >> 7) * kbO + (n >> 5)) * ASLOT;
                    *(__half2*)(slot + off) = __floats2half2_rn(e0, e1);
                }
            }
        }
    }
}

// ===========================================================================
// Packers (bf16 hi|lo)
// ===========================================================================
__global__ __launch_bounds__(256) void pack_q(const float* __restrict__ Q)
{
    int row = blockIdx.x;                     // 0..8959
    int src = row < L_ ? row : L_ - 1;
    int t = threadIdx.x;
    float2 v = *(const float2*)(Q + (size_t)src * D_ + t * 2);
    __nv_bfloat16 h0, l0, h1, l1;
    split_bf16(v.x, h0, l0);
    split_bf16(v.y, h1, l1);
    int r = row & 127, tile = row >> 7;
    int d0 = t * 2, kb = d0 >> 5, c = d0 & 31;
    char* slot = g_Qp + ((size_t)tile * 16 + kb) * SLOT;
    uint32_t off = swz((uint32_t)r * 64 + (uint32_t)c * 2);
    *(__nv_bfloat162*)(slot + off)        = __nv_bfloat162(h0, h1);
    *(__nv_bfloat162*)(slot + HSUB + off) = __nv_bfloat162(l0, l1);
}

__global__ __launch_bounds__(256) void pack_h(const float* __restrict__ H)
{
    __shared__ float tile[64][33];
    const int b = blockIdx.z, s0 = blockIdx.x * 32, d0 = blockIdx.y * 64;
    const int tx = threadIdx.x, ty = threadIdx.y;
    const float* Hb = H + ((size_t)b * D_ + d0) * S_ + s0;

#pragma unroll
    for (int i = 0; i < 8; i++)
        tile[ty * 8 + i][tx] = Hb[(size_t)(ty * 8 + i) * S_ + tx];
    __syncthreads();

    const int t = ty * 32 + tx;
    const int s = t & 31;
    const int dp = t >> 5;
    const int gs = s0 + s;
    const int r = gs & 127;
#pragma unroll
    for (int i = 0; i < 4; i++) {
        int d = dp * 2 + i * 16;
        int kbl = d >> 5, c = d & 31;
        char* slot = g_Hp + (((size_t)b * 16 + (gs >> 7)) * 16 + blockIdx.y * 2 + kbl) * SLOT;
        __nv_bfloat16 h0, l0, h1, l1;
        split_bf16(tile[d][s], h0, l0);
        split_bf16(tile[d + 1][s], h1, l1);
        uint32_t off = swz((uint32_t)r * 64 + (uint32_t)c * 2);
        *(__nv_bfloat162*)(slot + off)        = __nv_bfloat162(h0, h1);
        *(__nv_bfloat162*)(slot + HSUB + off) = __nv_bfloat162(l0, l1);
    }
}

__global__ __launch_bounds__(256) void pack_w(
    const float* __restrict__ Wk, const float* __restrict__ Wv)
{
    int which = blockIdx.x >> 9;
    int o = blockIdx.x & 511;
    const float* W = which ? Wv : Wk;
    int t = threadIdx.x;
    float2 v = *(const float2*)(W + (size_t)o * D_ + t * 2);
    __nv_bfloat16 h0, l0, h1, l1;
    split_bf16(v.x, h0, l0);
    split_bf16(v.y, h1, l1);
    int r = o & 127, tile = o >> 7;
    int d0 = t * 2, kb = d0 >> 5, c = d0 & 31;
    char* slot = g_Wp + (((size_t)which * 4 + tile) * 16 + kb) * SLOT;
    uint32_t off = swz((uint32_t)r * 64 + (uint32_t)c * 2);
    *(__nv_bfloat162*)(slot + off)        = __nv_bfloat162(h0, h1);
    *(__nv_bfloat162*)(slot + HSUB + off) = __nv_bfloat162(l0, l1);
}

// ===========================================================================
// In-place row softmax over S=2048; emits packed FP16 single of A.
// ===========================================================================
__global__ __launch_bounds__(256) void softmax_kernel(float* __restrict__ A)
{
    const int row = blockIdx.x;               // b*L + l
    const int b = row / L_;
    const int l = row - b * L_;
    float* p = A + (size_t)row * S_;
    const int t = threadIdx.x;
    const int lane = t & 31, wid = t >> 5;

    float4 va = *(const float4*)(p + t * 4);
    float4 vb = *(const float4*)(p + 1024 + t * 4);

    float m = fmaxf(fmaxf(fmaxf(va.x, va.y), fmaxf(va.z, va.w)),
                    fmaxf(fmaxf(vb.x, vb.y), fmaxf(vb.z, vb.w)));
#pragma unroll
    for (int o = 16; o > 0; o >>= 1) m = fmaxf(m, __shfl_xor_sync(0xffffffffu, m, o));

    __shared__ float red[8];
    if (lane == 0) red[wid] = m;
    __syncthreads();
    {
        float r = red[lane & 7];
#pragma unroll
        for (int o = 4; o > 0; o >>= 1) r = fmaxf(r, __shfl_xor_sync(0xffffffffu, r, o));
        m = r;
    }

    va.x = __expf(va.x - m); va.y = __expf(va.y - m);
    va.z = __expf(va.z - m); va.w = __expf(va.w - m);
    vb.x = __expf(vb.x - m); vb.y = __expf(vb.y - m);
    vb.z = __expf(vb.z - m); vb.w = __expf(vb.w - m);

    float s = va.x + va.y + va.z + va.w + vb.x + vb.y + vb.z + vb.w;
#pragma unroll
    for (int o = 16; o > 0; o >>= 1) s += __shfl_xor_sync(0xffffffffu, s, o);
    __syncthreads();
    if (lane == 0) red[wid] = s;
    __syncthreads();
    {
        float r = red[lane & 7];
#pragma unroll
        for (int o = 4; o > 0; o >>= 1) r += __shfl_xor_sync(0xffffffffu, r, o);
        s = r;
    }
    float inv = 1.f / s;

    va.x *= inv; va.y *= inv; va.z *= inv; va.w *= inv;
    vb.x *= inv; vb.y *= inv; vb.z *= inv; vb.w *= inv;

    *(float4*)(p + t * 4) = va;
    *(float4*)(p + 1024 + t * 4) = vb;

    char* tslot = g_Ap + ((size_t)b * (70 * 64) + (size_t)(l >> 7) * 64) * ASLOT;
    const uint32_t r = l & 127;

    float g[2][4] = {{va.x, va.y, va.z, va.w}, {vb.x, vb.y, vb.z, vb.w}};
#pragma unroll
    for (int half = 0; half < 2; half++) {
        int sidx = half * 1024 + t * 4;
        int kb = sidx >> 5, c = sidx & 31;
        char* slot = tslot + (size_t)kb * ASLOT;
        uint32_t off = swz(r * 64 + (uint32_t)c * 2);
        *(__half2*)(slot + off)     = __floats2half2_rn(g[half][0], g[half][1]);
        *(__half2*)(slot + off + 4) = __floats2half2_rn(g[half][2], g[half][3]);
    }
}

// ===========================================================================
extern "C" void kernel_launch(void* const* d_in, const int* in_sizes, int n_in,
                              void* d_out, int out_size)
{
    const float* H  = (const float*)d_in[0];
    const float* Wk = (const float*)d_in[1];
    const float* bk = (const float*)d_in[2];
    const float* Wv = (const float*)d_in[3];
    const float* bv = (const float*)d_in[4];
    const float* Q  = (const float*)d_in[5];

    float* out  = (float*)d_out;
    float* Cout = out;                          // [B, L, D]
    float* Aout = out + (size_t)B_ * L_ * D_;   // [B, L, S]

    static char *gQp, *gHp, *gWp, *gKp, *gVp, *gAp;
    static bool init = false;
    if (!init) {
        cudaGetSymbolAddress((void**)&gQp, g_Qp);
        cudaGetSymbolAddress((void**)&gHp, g_Hp);
        cudaGetSymbolAddress((void**)&gWp, g_Wp);
        cudaGetSymbolAddress((void**)&gKp, g_Kp);
        cudaGetSymbolAddress((void**)&gVp, g_Vp);
        cudaGetSymbolAddress((void**)&gAp, g_Ap);
        cudaFuncSetAttribute(gemm_bulk, cudaFuncAttributeMaxDynamicSharedMemorySize, DSMEM);
        cudaFuncSetAttribute(gemm_c, cudaFuncAttributeMaxDynamicSharedMemorySize, DSMEM_C);
        cudaFuncSetAttribute(kv_gemm_bulk, cudaFuncAttributeMaxDynamicSharedMemorySize, DSMEM);
        init = true;
    }

    // 0) packers
    pack_q<<<8960, 256>>>(Q);
    pack_h<<<dim3(S_ / 32, D_ / 64, B_), dim3(32, 8)>>>(H);
    pack_w<<<1024, 256>>>(Wk, Wv);

    // 1a) K = H^T * Wk  (bf16 hi/lo output)
    kv_gemm_bulk<<<dim3(D_ / TN, S_ / TM, B_), 256, DSMEM>>>(
        gHp, 256, gWp, 0,
        gKp, 256, 16, bk, 0, 0, 16);

    // 1b) V^T = Wv * H^T (fp16 single output)
    kv_gemm_bulk<<<dim3(S_ / TN, D_ / TM, B_), 256, DSMEM>>>(
        gWp + (size_t)64 * SLOT, 0, gHp, 256,
        gVp, 256, 64, bv, 1, 1, 16);

    // 2) E = Q K^T -> Aout (fp32), 3-term bf16
    gemm_bulk<<<dim3(S_ / TN, 70, B_), 256, DSMEM>>>(
        gQp, 0, gKp, 256,
        Aout, S_, (size_t)L_ * S_, 16, L_);

    // 3) softmax (+ packed fp16 A)
    softmax_kernel<<<dim3(B_ * L_), 256>>>(Aout);

    // 4) C = A V -> Cout, 1-product fp16
    gemm_c<<<dim3(D_ / TN, 70, B_), 256, DSMEM_C>>>(
        gAp, 70 * 64, gVp, 256,
        Cout, D_, (size_t)L_ * D_, 64, L_);
}

// round 16
// speedup vs baseline: 2.3469x; 1.1848x over previous
#include <cuda_runtime.h>
#include <cuda_bf16.h>
#include <cuda_fp16.h>
#include <math.h>
#include <cstdint>

#define B_ 4
#define D_ 512
#define S_ 2048
#define L_ 8921

#define SLOT 16384              // packed (tile128 x k32) dual slot: hi 8KB | lo 8KB
#define HSUB 8192
#define ASLOT 8192              // single-operand slot (fp16 single)

// Packed operand buffers (swizzled tiles, bulk-copy ready)
__device__ char g_Qp[(size_t)70 * 16 * SLOT];            // Q  [8960, 512] FP16 hi|lo
__device__ char g_Hp[(size_t)4 * 16 * 16 * SLOT];        // H^T per b: [2048, 512] bf16 hi|lo
__device__ char g_Wp[(size_t)2 * 4 * 16 * SLOT];         // Wk|Wv [512, 512] bf16 hi|lo
__device__ char g_Kp[(size_t)4 * 16 * 16 * ASLOT];       // K per b: [2048, 512] FP16 single
__device__ char g_Vp[(size_t)4 * 4 * 64 * ASLOT];        // V^T per b: [512, 2048] FP16 single
__device__ char g_Ap[(size_t)4 * 70 * 64 * ASLOT];       // attn per b: [8960, 2048] FP16 single

// ---------------------------------------------------------------------------
// helpers
// ---------------------------------------------------------------------------
__device__ __forceinline__ uint32_t smem_to_u32(const void* p) {
    uint32_t a;
    asm("{ .reg .u64 t; cvta.to.shared.u64 t, %1; cvt.u32.u64 %0, t; }" : "=r"(a) : "l"(p));
    return a;
}
// SW64 swizzle for 64B rows
__device__ __forceinline__ uint32_t swz(uint32_t off) { return off ^ ((off >> 3) & 0x30); }

__device__ __forceinline__ void bulk_g2s(uint32_t dst, const void* src, uint32_t bytes, uint32_t mbar) {
    asm volatile("cp.async.bulk.shared::cta.global.mbarrier::complete_tx::bytes [%0], [%1], %2, [%3];"
        :: "r"(dst), "l"(src), "r"(bytes), "r"(mbar) : "memory");
}
#define MBARRIER_INIT(mbar, count) \
    asm volatile("mbarrier.init.shared.b64 [%0], %1;" :: "r"((uint32_t)(mbar)), "r"((uint32_t)(count)) : "memory")
#define MBARRIER_EXPECT_TX(mbar, bytes) \
    asm volatile("mbarrier.arrive.expect_tx.shared.b64 _, [%0], %1;" :: "r"((uint32_t)(mbar)), "r"((uint32_t)(bytes)) : "memory")
#define MBARRIER_ARRIVE(mbar) \
    asm volatile("mbarrier.arrive.release.cta.shared::cta.b64 _, [%0];" :: "r"((uint32_t)(mbar)) : "memory")
#define MBARRIER_WAIT_PARITY(mbar, parity) do { \
    uint32_t _m = (uint32_t)(mbar), _p = (uint32_t)(parity), _d; \
    asm volatile("{\n\t.reg .pred p;\n\t" \
        "mbarrier.try_wait.parity.acquire.cta.shared::cta.b64 p, [%1], %2;\n\t" \
        "selp.b32 %0, 1, 0, p;\n\t}" : "=r"(_d) : "r"(_m), "r"(_p) : "memory"); \
    if (!_d) { \
        asm volatile("{\n\t.reg .pred P1;\n\t" \
            "WL_%=:\n\t" \
            "mbarrier.try_wait.parity.acquire.cta.shared::cta.b64 P1, [%0], %1, 0x989680;\n\t" \
            "@P1 bra.uni WD_%=;\n\t" \
            "bra.uni WL_%=;\n\t" \
            "WD_%=:\n\t}" :: "r"(_m), "r"(_p) : "memory"); \
    } \
} while (0)

__device__ __forceinline__ void mma_bf16(float* d, const uint32_t* a, const uint32_t* b) {
    asm("mma.sync.aligned.m16n8k16.row.col.f32.bf16.bf16.f32 "
        "{%0,%1,%2,%3}, {%4,%5,%6,%7}, {%8,%9}, {%0,%1,%2,%3};"
        : "+f"(d[0]), "+f"(d[1]), "+f"(d[2]), "+f"(d[3])
        : "r"(a[0]), "r"(a[1]), "r"(a[2]), "r"(a[3]), "r"(b[0]), "r"(b[1]));
}
__device__ __forceinline__ void mma_f16(float* d, const uint32_t* a, const uint32_t* b) {
    asm("mma.sync.aligned.m16n8k16.row.col.f32.f16.f16.f32 "
        "{%0,%1,%2,%3}, {%4,%5,%6,%7}, {%8,%9}, {%0,%1,%2,%3};"
        : "+f"(d[0]), "+f"(d[1]), "+f"(d[2]), "+f"(d[3])
        : "r"(a[0]), "r"(a[1]), "r"(a[2]), "r"(a[3]), "r"(b[0]), "r"(b[1]));
}
__device__ __forceinline__ void ldmx4(uint32_t* r, uint32_t addr) {
    asm volatile("ldmatrix.sync.aligned.m8n8.x4.shared.b16 {%0,%1,%2,%3}, [%4];"
        : "=r"(r[0]), "=r"(r[1]), "=r"(r[2]), "=r"(r[3]) : "r"(addr));
}
__device__ __forceinline__ float elu_f(float x) { return x > 0.f ? x : expm1f(x); }
__device__ __forceinline__ void split_bf16(float x, __nv_bfloat16& hi, __nv_bfloat16& lo) {
    hi = __float2bfloat16(x);
    lo = __float2bfloat16(x - __bfloat162float(hi));
}
__device__ __forceinline__ void split_f16(float x, __half& hi, __half& lo) {
    hi = __float2half_rn(x);
    lo = __float2half_rn(x - __half2float(hi));
}

// ===========================================================================
// GEMM config: CTA tile 128x128, TK=32, triple-buffered via cp.async.bulk,
// 8 warps (warp tile 64x32), 2 CTAs/SM, per-slot full/empty mbarriers.
// ===========================================================================
#define TM 128
#define TN 128
#define NSTG 3
#define STAGE_KV 32768                    // bf16 dual | bf16 dual
#define DSMEM_KV (1024 + NSTG * STAGE_KV + 96)

#define STAGE_E (SLOT + ASLOT)            // 24576: fp16 Q hi|lo + fp16 K
#define DSMEM_E (1024 + NSTG * STAGE_E + 96)

#define STAGE_C (2 * ASLOT)               // 16384: fp16 A + fp16 V
#define DSMEM_C (1024 + NSTG * STAGE_C + 96)

// barrier block: full[0..2] at +0,+8,+16 ; empty[0..2] at +24,+32,+40
#define INIT_BARRIERS(mb) do { \
    MBARRIER_INIT((mb) + 0, 1);  MBARRIER_INIT((mb) + 8, 1);  MBARRIER_INIT((mb) + 16, 1); \
    MBARRIER_INIT((mb) + 24, 256); MBARRIER_INIT((mb) + 32, 256); MBARRIER_INIT((mb) + 40, 256); \
} while (0)

// ---------------------------------------------------------------------------
// E GEMM (2-product fp16): E = (Qh+Ql) * K.  A: SLOT (hi|lo), B: ASLOT.
// fp32 output with M guard.
// ---------------------------------------------------------------------------
__global__ __launch_bounds__(256, 2) void gemm_e(
    const char* __restrict__ Ap, int bsA,        // in SLOT units
    const char* __restrict__ Bp, int bsB,        // in ASLOT units
    float* __restrict__ C, int ldc, size_t sC,
    int kbn, int Mtotal)
{
    extern __shared__ char smem_raw[];
    const uint32_t base = (smem_to_u32(smem_raw) + 1023) & ~1023u;
    const uint32_t mbar = base + NSTG * STAGE_E;

    const int t    = threadIdx.x;
    const int wid  = t >> 5, lane = t & 31;
    const int gid  = lane >> 2, tig = lane & 3;
    const int bz   = blockIdx.z;
    const int m0   = blockIdx.y * TM;
    const int n0   = blockIdx.x * TN;

    C += (size_t)bz * sC;

    const int wm0 = (wid & 1) * 64;
    const int wn0 = (wid >> 1) * 32;

    float acc[4][4][4];
#pragma unroll
    for (int i = 0; i < 4; i++)
#pragma unroll
        for (int j = 0; j < 4; j++)
#pragma unroll
            for (int q = 0; q < 4; q++) acc[i][j][q] = 0.f;

    if (t == 0) INIT_BARRIERS(mbar);
    __syncthreads();

    auto issue = [&](int kb) {
        int stg = kb % NSTG;
        uint32_t bar = mbar + 8 * stg;
        MBARRIER_EXPECT_TX(bar, SLOT + ASLOT);
        bulk_g2s(base + stg * STAGE_E,
                 Ap + ((size_t)bz * bsA + (size_t)(m0 >> 7) * kbn + kb) * SLOT,
                 SLOT, bar);
        bulk_g2s(base + stg * STAGE_E + SLOT,
                 Bp + ((size_t)bz * bsB + (size_t)(n0 >> 7) * kbn + kb) * ASLOT,
                 ASLOT, bar);
    };

    const int arow = lane & 15;
    const int aoff = (lane >> 4) * 16;
    const int bprow = ((lane >> 4) & 1) * 8 + (lane & 7);
    const int bpoff = ((lane >> 3) & 1) * 16;

    if (t == 0) { issue(0); if (1 < kbn) issue(1); }

    for (int kb = 0; kb < kbn; kb++) {
        if (t == 0 && kb + 2 < kbn) {
            if (kb >= 1)
                MBARRIER_WAIT_PARITY(mbar + 24 + 8 * ((kb + 2) % NSTG),
                                     ((kb + 2) / NSTG - 1) & 1);
            issue(kb + 2);
        }
        MBARRIER_WAIT_PARITY(mbar + 8 * (kb % NSTG), (kb / NSTG) & 1);

        const uint32_t sb = base + (kb % NSTG) * STAGE_E;

#pragma unroll
        for (int ks = 0; ks < 2; ks++) {
            uint32_t qh[4][4], ql[4][4];
#pragma unroll
            for (int mt = 0; mt < 4; mt++) {
                uint32_t off = swz((wm0 + mt * 16 + arow) * 64 + ks * 32 + aoff);
                ldmx4(qh[mt], sb + off);
                ldmx4(ql[mt], sb + HSUB + off);
            }
#pragma unroll
            for (int p = 0; p < 2; p++) {
                uint32_t offb = swz((wn0 + p * 16 + bprow) * 64 + ks * 32 + bpoff);
                uint32_t kh4[4];
                ldmx4(kh4, sb + SLOT + offb);
#pragma unroll
                for (int mt = 0; mt < 4; mt++)
#pragma unroll
                    for (int h = 0; h < 2; h++)
                        mma_f16(acc[mt][2 * p + h], qh[mt], kh4 + 2 * h);
#pragma unroll
                for (int mt = 0; mt < 4; mt++)
#pragma unroll
                    for (int h = 0; h < 2; h++)
                        mma_f16(acc[mt][2 * p + h], ql[mt], kh4 + 2 * h);
            }
        }
        MBARRIER_ARRIVE(mbar + 24 + 8 * (kb % NSTG));
    }

#pragma unroll
    for (int mt = 0; mt < 4; mt++) {
        int r0 = m0 + wm0 + mt * 16 + gid;
#pragma unroll
        for (int nt = 0; nt < 4; nt++) {
            int c0 = n0 + wn0 + nt * 8 + 2 * tig;
            if (r0 < Mtotal)
                *(float2*)(C + (size_t)r0 * ldc + c0) =
                    make_float2(acc[mt][nt][0], acc[mt][nt][1]);
            if (r0 + 8 < Mtotal)
                *(float2*)(C + (size_t)(r0 + 8) * ldc + c0) =
                    make_float2(acc[mt][nt][2], acc[mt][nt][3]);
        }
    }
}

// ---------------------------------------------------------------------------
// C GEMM (1-product fp16): A fp16 x V fp16, f32 accumulate.
// ---------------------------------------------------------------------------
__global__ __launch_bounds__(256, 2) void gemm_c(
    const char* __restrict__ Ap, int bsA,        // in ASLOT units
    const char* __restrict__ Bp, int bsB,        // in ASLOT units
    float* __restrict__ C, int ldc, size_t sC,
    int kbn, int Mtotal)
{
    extern __shared__ char smem_raw[];
    const uint32_t base = (smem_to_u32(smem_raw) + 1023) & ~1023u;
    const uint32_t mbar = base + NSTG * STAGE_C;

    const int t    = threadIdx.x;
    const int wid  = t >> 5, lane = t & 31;
    const int gid  = lane >> 2, tig = lane & 3;
    const int bz   = blockIdx.z;
    const int m0   = blockIdx.y * TM;
    const int n0   = blockIdx.x * TN;

    C += (size_t)bz * sC;

    const int wm0 = (wid & 1) * 64;
    const int wn0 = (wid >> 1) * 32;

    float acc[4][4][4];
#pragma unroll
    for (int i = 0; i < 4; i++)
#pragma unroll
        for (int j = 0; j < 4; j++)
#pragma unroll
            for (int q = 0; q < 4; q++) acc[i][j][q] = 0.f;

    if (t == 0) INIT_BARRIERS(mbar);
    __syncthreads();

    auto issue = [&](int kb) {
        int stg = kb % NSTG;
        uint32_t bar = mbar + 8 * stg;
        MBARRIER_EXPECT_TX(bar, 2 * ASLOT);
        bulk_g2s(base + stg * STAGE_C,
                 Ap + ((size_t)bz * bsA + (size_t)(m0 >> 7) * kbn + kb) * ASLOT,
                 ASLOT, bar);
        bulk_g2s(base + stg * STAGE_C + ASLOT,
                 Bp + ((size_t)bz * bsB + (size_t)(n0 >> 7) * kbn + kb) * ASLOT,
                 ASLOT, bar);
    };

    const int arow = lane & 15;
    const int aoff = (lane >> 4) * 16;
    const int bprow = ((lane >> 4) & 1) * 8 + (lane & 7);
    const int bpoff = ((lane >> 3) & 1) * 16;

    if (t == 0) { issue(0); if (1 < kbn) issue(1); }

    for (int kb = 0; kb < kbn; kb++) {
        if (t == 0 && kb + 2 < kbn) {
            if (kb >= 1)
                MBARRIER_WAIT_PARITY(mbar + 24 + 8 * ((kb + 2) % NSTG),
                                     ((kb + 2) / NSTG - 1) & 1);
            issue(kb + 2);
        }
        MBARRIER_WAIT_PARITY(mbar + 8 * (kb % NSTG), (kb / NSTG) & 1);

        const uint32_t sb = base + (kb % NSTG) * STAGE_C;

#pragma unroll
        for (int ks = 0; ks < 2; ks++) {
            uint32_t ah[4][4];
#pragma unroll
            for (int mt = 0; mt < 4; mt++) {
                uint32_t off = swz((wm0 + mt * 16 + arow) * 64 + ks * 32 + aoff);
                ldmx4(ah[mt], sb + off);
            }
#pragma unroll
            for (int p = 0; p < 2; p++) {
                uint32_t offb = swz((wn0 + p * 16 + bprow) * 64 + ks * 32 + bpoff);
                uint32_t bh4[4];
                ldmx4(bh4, sb + ASLOT + offb);
#pragma unroll
                for (int mt = 0; mt < 4; mt++)
#pragma unroll
                    for (int h = 0; h < 2; h++)
                        mma_f16(acc[mt][2 * p + h], ah[mt], bh4 + 2 * h);
            }
        }
        MBARRIER_ARRIVE(mbar + 24 + 8 * (kb % NSTG));
    }

#pragma unroll
    for (int mt = 0; mt < 4; mt++) {
        int r0 = m0 + wm0 + mt * 16 + gid;
#pragma unroll
        for (int nt = 0; nt < 4; nt++) {
            int c0 = n0 + wn0 + nt * 8 + 2 * tig;
            if (r0 < Mtotal)
                *(float2*)(C + (size_t)r0 * ldc + c0) =
                    make_float2(acc[mt][nt][0], acc[mt][nt][1]);
            if (r0 + 8 < Mtotal)
                *(float2*)(C + (size_t)(r0 + 8) * ldc + c0) =
                    make_float2(acc[mt][nt][2], acc[mt][nt][3]);
        }
    }
}

// ---------------------------------------------------------------------------
// KV GEMM (3-term bf16): epilogue = bias + ELU; output fp16 single (ASLOT).
// ---------------------------------------------------------------------------
__global__ __launch_bounds__(256, 2) void kv_gemm_bulk(
    const char* __restrict__ Ap, int bsA,        // SLOT units
    const char* __restrict__ Bp, int bsB,        // SLOT units
    char* __restrict__ Op, int bsO, int kbO,     // ASLOT units
    const float* __restrict__ bias, int biasRow,
    int kbn)
{
    extern __shared__ char smem_raw[];
    const uint32_t base = (smem_to_u32(smem_raw) + 1023) & ~1023u;
    const uint32_t mbar = base + NSTG * STAGE_KV;

    const int t    = threadIdx.x;
    const int wid  = t >> 5, lane = t & 31;
    const int gid  = lane >> 2, tig = lane & 3;
    const int bz   = blockIdx.z;
    const int m0   = blockIdx.y * TM;
    const int n0   = blockIdx.x * TN;

    const int wm0 = (wid & 1) * 64;
    const int wn0 = (wid >> 1) * 32;

    float acc[4][4][4];
#pragma unroll
    for (int i = 0; i < 4; i++)
#pragma unroll
        for (int j = 0; j < 4; j++)
#pragma unroll
            for (int q = 0; q < 4; q++) acc[i][j][q] = 0.f;

    if (t == 0) INIT_BARRIERS(mbar);
    __syncthreads();

    auto issue = [&](int kb) {
        int stg = kb % NSTG;
        uint32_t bar = mbar + 8 * stg;
        MBARRIER_EXPECT_TX(bar, 2 * SLOT);
        bulk_g2s(base + stg * STAGE_KV,
                 Ap + ((size_t)bz * bsA + (size_t)(m0 >> 7) * kbn + kb) * SLOT, SLOT, bar);
        bulk_g2s(base + stg * STAGE_KV + SLOT,
                 Bp + ((size_t)bz * bsB + (size_t)(n0 >> 7) * kbn + kb) * SLOT, SLOT, bar);
    };

    const int arow = lane & 15;
    const int aoff = (lane >> 4) * 16;
    const int bprow = ((lane >> 4) & 1) * 8 + (lane & 7);
    const int bpoff = ((lane >> 3) & 1) * 16;

    if (t == 0) { issue(0); if (1 < kbn) issue(1); }

    for (int kb = 0; kb < kbn; kb++) {
        if (t == 0 && kb + 2 < kbn) {
            if (kb >= 1)
                MBARRIER_WAIT_PARITY(mbar + 24 + 8 * ((kb + 2) % NSTG),
                                     ((kb + 2) / NSTG - 1) & 1);
            issue(kb + 2);
        }
        MBARRIER_WAIT_PARITY(mbar + 8 * (kb % NSTG), (kb / NSTG) & 1);

        const uint32_t sb = base + (kb % NSTG) * STAGE_KV;

#pragma unroll
        for (int ks = 0; ks < 2; ks++) {
            uint32_t ah[4][4], al[4][4];
#pragma unroll
            for (int mt = 0; mt < 4; mt++) {
                uint32_t off = swz((wm0 + mt * 16 + arow) * 64 + ks * 32 + aoff);
                ldmx4(ah[mt], sb + off);
                ldmx4(al[mt], sb + HSUB + off);
            }
#pragma unroll
            for (int p = 0; p < 2; p++) {
                uint32_t offb = swz((wn0 + p * 16 + bprow) * 64 + ks * 32 + bpoff);
                uint32_t bh4[4], bl4[4];
                ldmx4(bh4, sb + SLOT + offb);
                ldmx4(bl4, sb + SLOT + HSUB + offb);
#pragma unroll
                for (int mt = 0; mt < 4; mt++)
#pragma unroll
                    for (int h = 0; h < 2; h++)
                        mma_bf16(acc[mt][2 * p + h], ah[mt], bh4 + 2 * h);
#pragma unroll
                for (int mt = 0; mt < 4; mt++)
#pragma unroll
                    for (int h = 0; h < 2; h++)
                        mma_bf16(acc[mt][2 * p + h], ah[mt], bl4 + 2 * h);
#pragma unroll
                for (int mt = 0; mt < 4; mt++)
#pragma unroll
                    for (int h = 0; h < 2; h++)
                        mma_bf16(acc[mt][2 * p + h], al[mt], bh4 + 2 * h);
            }
        }
        MBARRIER_ARRIVE(mbar + 24 + 8 * (kb % NSTG));
    }

    // epilogue: bias + ELU -> fp16 single packed
#pragma unroll
    for (int mt = 0; mt < 4; mt++) {
#pragma unroll
        for (int half = 0; half < 2; half++) {
            int m = m0 + wm0 + mt * 16 + gid + half * 8;
#pragma unroll
            for (int nt = 0; nt < 4; nt++) {
                int n = n0 + wn0 + nt * 8 + 2 * tig;
                float v0 = acc[mt][nt][2 * half + 0];
                float v1 = acc[mt][nt][2 * half + 1];
                float b0 = biasRow ? bias[m] : bias[n];
                float b1 = biasRow ? bias[m] : bias[n + 1];
                float e0 = elu_f(v0 + b0);
                float e1 = elu_f(v1 + b1);
                uint32_t off = swz((uint32_t)(m & 127) * 64 + (uint32_t)(n & 31) * 2);
                char* slot = Op + ((size_t)bz * bsO + (size_t)(m >> 7) * kbO + (n >> 5)) * ASLOT;
                *(__half2*)(slot + off) = __floats2half2_rn(e0, e1);
            }
        }
    }
}

// ===========================================================================
// Packers
// ===========================================================================
// Q: fp16 hi|lo
__global__ __launch_bounds__(256) void pack_q(const float* __restrict__ Q)
{
    int row = blockIdx.x;                     // 0..8959
    int src = row < L_ ? row : L_ - 1;
    int t = threadIdx.x;
    float2 v = *(const float2*)(Q + (size_t)src * D_ + t * 2);
    __half h0, l0, h1, l1;
    split_f16(v.x, h0, l0);
    split_f16(v.y, h1, l1);
    int r = row & 127, tile = row >> 7;
    int d0 = t * 2, kb = d0 >> 5, c = d0 & 31;
    char* slot = g_Qp + ((size_t)tile * 16 + kb) * SLOT;
    uint32_t off = swz((uint32_t)r * 64 + (uint32_t)c * 2);
    *(__half2*)(slot + off)        = __half2(h0, h1);
    *(__half2*)(slot + HSUB + off) = __half2(l0, l1);
}

__global__ __launch_bounds__(256) void pack_h(const float* __restrict__ H)
{
    __shared__ float tile[64][33];
    const int b = blockIdx.z, s0 = blockIdx.x * 32, d0 = blockIdx.y * 64;
    const int tx = threadIdx.x, ty = threadIdx.y;
    const float* Hb = H + ((size_t)b * D_ + d0) * S_ + s0;

#pragma unroll
    for (int i = 0; i < 8; i++)
        tile[ty * 8 + i][tx] = Hb[(size_t)(ty * 8 + i) * S_ + tx];
    __syncthreads();

    const int t = ty * 32 + tx;
    const int s = t & 31;
    const int dp = t >> 5;
    const int gs = s0 + s;
    const int r = gs & 127;
#pragma unroll
    for (int i = 0; i < 4; i++) {
        int d = dp * 2 + i * 16;
        int kbl = d >> 5, c = d & 31;
        char* slot = g_Hp + (((size_t)b * 16 + (gs >> 7)) * 16 + blockIdx.y * 2 + kbl) * SLOT;
        __nv_bfloat16 h0, l0, h1, l1;
        split_bf16(tile[d][s], h0, l0);
        split_bf16(tile[d + 1][s], h1, l1);
        uint32_t off = swz((uint32_t)r * 64 + (uint32_t)c * 2);
        *(__nv_bfloat162*)(slot + off)        = __nv_bfloat162(h0, h1);
        *(__nv_bfloat162*)(slot + HSUB + off) = __nv_bfloat162(l0, l1);
    }
}

__global__ __launch_bounds__(256) void pack_w(
    const float* __restrict__ Wk, const float* __restrict__ Wv)
{
    int which = blockIdx.x >> 9;
    int o = blockIdx.x & 511;
    const float* W = which ? Wv : Wk;
    int t = threadIdx.x;
    float2 v = *(const float2*)(W + (size_t)o * D_ + t * 2);
    __nv_bfloat16 h0, l0, h1, l1;
    split_bf16(v.x, h0, l0);
    split_bf16(v.y, h1, l1);
    int r = o & 127, tile = o >> 7;
    int d0 = t * 2, kb = d0 >> 5, c = d0 & 31;
    char* slot = g_Wp + (((size_t)which * 4 + tile) * 16 + kb) * SLOT;
    uint32_t off = swz((uint32_t)r * 64 + (uint32_t)c * 2);
    *(__nv_bfloat162*)(slot + off)        = __nv_bfloat162(h0, h1);
    *(__nv_bfloat162*)(slot + HSUB + off) = __nv_bfloat162(l0, l1);
}

// ===========================================================================
// In-place row softmax over S=2048; emits packed FP16 single of A.
// ===========================================================================
__global__ __launch_bounds__(256) void softmax_kernel(float* __restrict__ A)
{
    const int row = blockIdx.x;               // b*L + l
    const int b = row / L_;
    const int l = row - b * L_;
    float* p = A + (size_t)row * S_;
    const int t = threadIdx.x;
    const int lane = t & 31, wid = t >> 5;

    float4 va = *(const float4*)(p + t * 4);
    float4 vb = *(const float4*)(p + 1024 + t * 4);

    float m = fmaxf(fmaxf(fmaxf(va.x, va.y), fmaxf(va.z, va.w)),
                    fmaxf(fmaxf(vb.x, vb.y), fmaxf(vb.z, vb.w)));
#pragma unroll
    for (int o = 16; o > 0; o >>= 1) m = fmaxf(m, __shfl_xor_sync(0xffffffffu, m, o));

    __shared__ float red[8];
    if (lane == 0) red[wid] = m;
    __syncthreads();
    {
        float r = red[lane & 7];
#pragma unroll
        for (int o = 4; o > 0; o >>= 1) r = fmaxf(r, __shfl_xor_sync(0xffffffffu, r, o));
        m = r;
    }

    va.x = __expf(va.x - m); va.y = __expf(va.y - m);
    va.z = __expf(va.z - m); va.w = __expf(va.w - m);
    vb.x = __expf(vb.x - m); vb.y = __expf(vb.y - m);
    vb.z = __expf(vb.z - m); vb.w = __expf(vb.w - m);

    float s = va.x + va.y + va.z + va.w + vb.x + vb.y + vb.z + vb.w;
#pragma unroll
    for (int o = 16; o > 0; o >>= 1) s += __shfl_xor_sync(0xffffffffu, s, o);
    __syncthreads();
    if (lane == 0) red[wid] = s;
    __syncthreads();
    {
        float r = red[lane & 7];
#pragma unroll
        for (int o = 4; o > 0; o >>= 1) r += __shfl_xor_sync(0xffffffffu, r, o);
        s = r;
    }
    float inv = 1.f / s;

    va.x *= inv; va.y *= inv; va.z *= inv; va.w *= inv;
    vb.x *= inv; vb.y *= inv; vb.z *= inv; vb.w *= inv;

    *(float4*)(p + t * 4) = va;
    *(float4*)(p + 1024 + t * 4) = vb;

    char* tslot = g_Ap + ((size_t)b * (70 * 64) + (size_t)(l >> 7) * 64) * ASLOT;
    const uint32_t r = l & 127;

    float g[2][4] = {{va.x, va.y, va.z, va.w}, {vb.x, vb.y, vb.z, vb.w}};
#pragma unroll
    for (int half = 0; half < 2; half++) {
        int sidx = half * 1024 + t * 4;
        int kb = sidx >> 5, c = sidx & 31;
        char* slot = tslot + (size_t)kb * ASLOT;
        uint32_t off = swz(r * 64 + (uint32_t)c * 2);
        *(__half2*)(slot + off)     = __floats2half2_rn(g[half][0], g[half][1]);
        *(__half2*)(slot + off + 4) = __floats2half2_rn(g[half][2], g[half][3]);
    }
}

// ===========================================================================
extern "C" void kernel_launch(void* const* d_in, const int* in_sizes, int n_in,
                              void* d_out, int out_size)
{
    const float* H  = (const float*)d_in[0];
    const float* Wk = (const float*)d_in[1];
    const float* bk = (const float*)d_in[2];
    const float* Wv = (const float*)d_in[3];
    const float* bv = (const float*)d_in[4];
    const float* Q  = (const float*)d_in[5];

    float* out  = (float*)d_out;
    float* Cout = out;                          // [B, L, D]
    float* Aout = out + (size_t)B_ * L_ * D_;   // [B, L, S]

    static char *gQp, *gHp, *gWp, *gKp, *gVp, *gAp;
    static bool init = false;
    if (!init) {
        cudaGetSymbolAddress((void**)&gQp, g_Qp);
        cudaGetSymbolAddress((void**)&gHp, g_Hp);
        cudaGetSymbolAddress((void**)&gWp, g_Wp);
        cudaGetSymbolAddress((void**)&gKp, g_Kp);
        cudaGetSymbolAddress((void**)&gVp, g_Vp);
        cudaGetSymbolAddress((void**)&gAp, g_Ap);
        cudaFuncSetAttribute(gemm_e, cudaFuncAttributeMaxDynamicSharedMemorySize, DSMEM_E);
        cudaFuncSetAttribute(gemm_c, cudaFuncAttributeMaxDynamicSharedMemorySize, DSMEM_C);
        cudaFuncSetAttribute(kv_gemm_bulk, cudaFuncAttributeMaxDynamicSharedMemorySize, DSMEM_KV);
        init = true;
    }

    // 0) packers
    pack_q<<<8960, 256>>>(Q);
    pack_h<<<dim3(S_ / 32, D_ / 64, B_), dim3(32, 8)>>>(H);
    pack_w<<<1024, 256>>>(Wk, Wv);

    // 1a) K = H^T * Wk  -> fp16 single, packed (s-tile, o-kb)
    kv_gemm_bulk<<<dim3(D_ / TN, S_ / TM, B_), 256, DSMEM_KV>>>(
        gHp, 256, gWp, 0,
        gKp, 256, 16, bk, 0, 16);

    // 1b) V^T = Wv * H^T -> fp16 single, packed (o-tile, s-kb)
    kv_gemm_bulk<<<dim3(S_ / TN, D_ / TM, B_), 256, DSMEM_KV>>>(
        gWp + (size_t)64 * SLOT, 0, gHp, 256,
        gVp, 256, 64, bv, 1, 16);

    // 2) E = Q K^T -> Aout (fp32), 2-product fp16
    gemm_e<<<dim3(S_ / TN, 70, B_), 256, DSMEM_E>>>(
        gQp, 0, gKp, 256,
        Aout, S_, (size_t)L_ * S_, 16, L_);

    // 3) softmax (+ packed fp16 A)
    softmax_kernel<<<dim3(B_ * L_), 256>>>(Aout);

    // 4) C = A V -> Cout, 1-product fp16
    gemm_c<<<dim3(D_ / TN, 70, B_), 256, DSMEM_C>>>(
        gAp, 70 * 64, gVp, 256,
        Cout, D_, (size_t)L_ * D_, 64, L_);
}

// round 17
// speedup vs baseline: 2.8171x; 1.2003x over previous
#include <cuda_runtime.h>
#include <cuda_bf16.h>
#include <cuda_fp16.h>
#include <math.h>
#include <cstdint>

#define B_ 4
#define D_ 512
#define S_ 2048
#define L_ 8921

#define SLOT 16384              // packed (tile128 x k32) dual slot: hi 8KB | lo 8KB
#define HSUB 8192
#define ASLOT 8192              // single-operand slot (fp16 single)

// Packed operand buffers (swizzled tiles, bulk-copy ready)
__device__ char g_Qp[(size_t)70 * 16 * ASLOT];           // Q  [8960, 512] FP16 single
__device__ char g_Hp[(size_t)4 * 16 * 16 * SLOT];        // H^T per b: [2048, 512] bf16 hi|lo
__device__ char g_Wp[(size_t)2 * 4 * 16 * SLOT];         // Wk|Wv [512, 512] bf16 hi|lo
__device__ char g_Kp[(size_t)4 * 16 * 16 * ASLOT];       // K per b: [2048, 512] FP16 single
__device__ char g_Vp[(size_t)4 * 4 * 64 * ASLOT];        // V^T per b: [512, 2048] FP16 single
__device__ char g_Ap[(size_t)4 * 70 * 64 * ASLOT];       // attn per b: [8960, 2048] FP16 single

// ---------------------------------------------------------------------------
// helpers
// ---------------------------------------------------------------------------
__device__ __forceinline__ uint32_t smem_to_u32(const void* p) {
    uint32_t a;
    asm("{ .reg .u64 t; cvta.to.shared.u64 t, %1; cvt.u32.u64 %0, t; }" : "=r"(a) : "l"(p));
    return a;
}
// SW64 swizzle for 64B rows
__device__ __forceinline__ uint32_t swz(uint32_t off) { return off ^ ((off >> 3) & 0x30); }

__device__ __forceinline__ void bulk_g2s(uint32_t dst, const void* src, uint32_t bytes, uint32_t mbar) {
    asm volatile("cp.async.bulk.shared::cta.global.mbarrier::complete_tx::bytes [%0], [%1], %2, [%3];"
        :: "r"(dst), "l"(src), "r"(bytes), "r"(mbar) : "memory");
}
#define MBARRIER_INIT(mbar, count) \
    asm volatile("mbarrier.init.shared.b64 [%0], %1;" :: "r"((uint32_t)(mbar)), "r"((uint32_t)(count)) : "memory")
#define MBARRIER_EXPECT_TX(mbar, bytes) \
    asm volatile("mbarrier.arrive.expect_tx.shared.b64 _, [%0], %1;" :: "r"((uint32_t)(mbar)), "r"((uint32_t)(bytes)) : "memory")
#define MBARRIER_ARRIVE(mbar) \
    asm volatile("mbarrier.arrive.release.cta.shared::cta.b64 _, [%0];" :: "r"((uint32_t)(mbar)) : "memory")
#define MBARRIER_WAIT_PARITY(mbar, parity) do { \
    uint32_t _m = (uint32_t)(mbar), _p = (uint32_t)(parity), _d; \
    asm volatile("{\n\t.reg .pred p;\n\t" \
        "mbarrier.try_wait.parity.acquire.cta.shared::cta.b64 p, [%1], %2;\n\t" \
        "selp.b32 %0, 1, 0, p;\n\t}" : "=r"(_d) : "r"(_m), "r"(_p) : "memory"); \
    if (!_d) { \
        asm volatile("{\n\t.reg .pred P1;\n\t" \
            "WL_%=:\n\t" \
            "mbarrier.try_wait.parity.acquire.cta.shared::cta.b64 P1, [%0], %1, 0x989680;\n\t" \
            "@P1 bra.uni WD_%=;\n\t" \
            "bra.uni WL_%=;\n\t" \
            "WD_%=:\n\t}" :: "r"(_m), "r"(_p) : "memory"); \
    } \
} while (0)

__device__ __forceinline__ void mma_bf16(float* d, const uint32_t* a, const uint32_t* b) {
    asm("mma.sync.aligned.m16n8k16.row.col.f32.bf16.bf16.f32 "
        "{%0,%1,%2,%3}, {%4,%5,%6,%7}, {%8,%9}, {%0,%1,%2,%3};"
        : "+f"(d[0]), "+f"(d[1]), "+f"(d[2]), "+f"(d[3])
        : "r"(a[0]), "r"(a[1]), "r"(a[2]), "r"(a[3]), "r"(b[0]), "r"(b[1]));
}
__device__ __forceinline__ void mma_f16(float* d, const uint32_t* a, const uint32_t* b) {
    asm("mma.sync.aligned.m16n8k16.row.col.f32.f16.f16.f32 "
        "{%0,%1,%2,%3}, {%4,%5,%6,%7}, {%8,%9}, {%0,%1,%2,%3};"
        : "+f"(d[0]), "+f"(d[1]), "+f"(d[2]), "+f"(d[3])
        : "r"(a[0]), "r"(a[1]), "r"(a[2]), "r"(a[3]), "r"(b[0]), "r"(b[1]));
}
__device__ __forceinline__ void ldmx4(uint32_t* r, uint32_t addr) {
    asm volatile("ldmatrix.sync.aligned.m8n8.x4.shared.b16 {%0,%1,%2,%3}, [%4];"
        : "=r"(r[0]), "=r"(r[1]), "=r"(r[2]), "=r"(r[3]) : "r"(addr));
}
__device__ __forceinline__ float elu_f(float x) { return x > 0.f ? x : expm1f(x); }
__device__ __forceinline__ void split_bf16(float x, __nv_bfloat16& hi, __nv_bfloat16& lo) {
    hi = __float2bfloat16(x);
    lo = __float2bfloat16(x - __bfloat162float(hi));
}

// ===========================================================================
// GEMM config: CTA tile 128x128, TK=32, triple-buffered via cp.async.bulk,
// 8 warps (warp tile 64x32), 2 CTAs/SM, per-slot full/empty mbarriers.
// ===========================================================================
#define TM 128
#define TN 128
#define NSTG 3
#define STAGE_KV 32768                    // bf16 dual | bf16 dual
#define DSMEM_KV (1024 + NSTG * STAGE_KV + 96)

#define STAGE_C (2 * ASLOT)               // 16384: fp16 | fp16
#define DSMEM_C (1024 + NSTG * STAGE_C + 96)

// barrier block: full[0..2] at +0,+8,+16 ; empty[0..2] at +24,+32,+40
#define INIT_BARRIERS(mb) do { \
    MBARRIER_INIT((mb) + 0, 1);  MBARRIER_INIT((mb) + 8, 1);  MBARRIER_INIT((mb) + 16, 1); \
    MBARRIER_INIT((mb) + 24, 256); MBARRIER_INIT((mb) + 32, 256); MBARRIER_INIT((mb) + 40, 256); \
} while (0)

// ---------------------------------------------------------------------------
// fp16 1-product GEMM (used for E and C): A fp16 x B fp16, f32 accumulate.
// ---------------------------------------------------------------------------
__global__ __launch_bounds__(256, 2) void gemm_c(
    const char* __restrict__ Ap, int bsA,        // in ASLOT units
    const char* __restrict__ Bp, int bsB,        // in ASLOT units
    float* __restrict__ C, int ldc, size_t sC,
    int kbn, int Mtotal)
{
    extern __shared__ char smem_raw[];
    const uint32_t base = (smem_to_u32(smem_raw) + 1023) & ~1023u;
    const uint32_t mbar = base + NSTG * STAGE_C;

    const int t    = threadIdx.x;
    const int wid  = t >> 5, lane = t & 31;
    const int gid  = lane >> 2, tig = lane & 3;
    const int bz   = blockIdx.z;
    const int m0   = blockIdx.y * TM;
    const int n0   = blockIdx.x * TN;

    C += (size_t)bz * sC;

    const int wm0 = (wid & 1) * 64;
    const int wn0 = (wid >> 1) * 32;

    float acc[4][4][4];
#pragma unroll
    for (int i = 0; i < 4; i++)
#pragma unroll
        for (int j = 0; j < 4; j++)
#pragma unroll
            for (int q = 0; q < 4; q++) acc[i][j][q] = 0.f;

    if (t == 0) INIT_BARRIERS(mbar);
    __syncthreads();

    auto issue = [&](int kb) {
        int stg = kb % NSTG;
        uint32_t bar = mbar + 8 * stg;
        MBARRIER_EXPECT_TX(bar, 2 * ASLOT);
        bulk_g2s(base + stg * STAGE_C,
                 Ap + ((size_t)bz * bsA + (size_t)(m0 >> 7) * kbn + kb) * ASLOT,
                 ASLOT, bar);
        bulk_g2s(base + stg * STAGE_C + ASLOT,
                 Bp + ((size_t)bz * bsB + (size_t)(n0 >> 7) * kbn + kb) * ASLOT,
                 ASLOT, bar);
    };

    const int arow = lane & 15;
    const int aoff = (lane >> 4) * 16;
    const int bprow = ((lane >> 4) & 1) * 8 + (lane & 7);
    const int bpoff = ((lane >> 3) & 1) * 16;

    if (t == 0) { issue(0); if (1 < kbn) issue(1); }

    for (int kb = 0; kb < kbn; kb++) {
        if (t == 0 && kb + 2 < kbn) {
            if (kb >= 1)
                MBARRIER_WAIT_PARITY(mbar + 24 + 8 * ((kb + 2) % NSTG),
                                     ((kb + 2) / NSTG - 1) & 1);
            issue(kb + 2);
        }
        MBARRIER_WAIT_PARITY(mbar + 8 * (kb % NSTG), (kb / NSTG) & 1);

        const uint32_t sb = base + (kb % NSTG) * STAGE_C;

#pragma unroll
        for (int ks = 0; ks < 2; ks++) {
            uint32_t ah[4][4];
#pragma unroll
            for (int mt = 0; mt < 4; mt++) {
                uint32_t off = swz((wm0 + mt * 16 + arow) * 64 + ks * 32 + aoff);
                ldmx4(ah[mt], sb + off);
            }
#pragma unroll
            for (int p = 0; p < 2; p++) {
                uint32_t offb = swz((wn0 + p * 16 + bprow) * 64 + ks * 32 + bpoff);
                uint32_t bh4[4];
                ldmx4(bh4, sb + ASLOT + offb);
#pragma unroll
                for (int mt = 0; mt < 4; mt++)
#pragma unroll
                    for (int h = 0; h < 2; h++)
                        mma_f16(acc[mt][2 * p + h], ah[mt], bh4 + 2 * h);
            }
        }
        MBARRIER_ARRIVE(mbar + 24 + 8 * (kb % NSTG));
    }

#pragma unroll
    for (int mt = 0; mt < 4; mt++) {
        int r0 = m0 + wm0 + mt * 16 + gid;
#pragma unroll
        for (int nt = 0; nt < 4; nt++) {
            int c0 = n0 + wn0 + nt * 8 + 2 * tig;
            if (r0 < Mtotal)
                *(float2*)(C + (size_t)r0 * ldc + c0) =
                    make_float2(acc[mt][nt][0], acc[mt][nt][1]);
            if (r0 + 8 < Mtotal)
                *(float2*)(C + (size_t)(r0 + 8) * ldc + c0) =
                    make_float2(acc[mt][nt][2], acc[mt][nt][3]);
        }
    }
}

// ---------------------------------------------------------------------------
// KV GEMM (3-term bf16): epilogue = bias + ELU; output fp16 single (ASLOT).
// ---------------------------------------------------------------------------
__global__ __launch_bounds__(256, 2) void kv_gemm_bulk(
    const char* __restrict__ Ap, int bsA,        // SLOT units
    const char* __restrict__ Bp, int bsB,        // SLOT units
    char* __restrict__ Op, int bsO, int kbO,     // ASLOT units
    const float* __restrict__ bias, int biasRow,
    int kbn)
{
    extern __shared__ char smem_raw[];
    const uint32_t base = (smem_to_u32(smem_raw) + 1023) & ~1023u;
    const uint32_t mbar = base + NSTG * STAGE_KV;

    const int t    = threadIdx.x;
    const int wid  = t >> 5, lane = t & 31;
    const int gid  = lane >> 2, tig = lane & 3;
    const int bz   = blockIdx.z;
    const int m0   = blockIdx.y * TM;
    const int n0   = blockIdx.x * TN;

    const int wm0 = (wid & 1) * 64;
    const int wn0 = (wid >> 1) * 32;

    float acc[4][4][4];
#pragma unroll
    for (int i = 0; i < 4; i++)
#pragma unroll
        for (int j = 0; j < 4; j++)
#pragma unroll
            for (int q = 0; q < 4; q++) acc[i][j][q] = 0.f;

    if (t == 0) INIT_BARRIERS(mbar);
    __syncthreads();

    auto issue = [&](int kb) {
        int stg = kb % NSTG;
        uint32_t bar = mbar + 8 * stg;
        MBARRIER_EXPECT_TX(bar, 2 * SLOT);
        bulk_g2s(base + stg * STAGE_KV,
                 Ap + ((size_t)bz * bsA + (size_t)(m0 >> 7) * kbn + kb) * SLOT, SLOT, bar);
        bulk_g2s(base + stg * STAGE_KV + SLOT,
                 Bp + ((size_t)bz * bsB + (size_t)(n0 >> 7) * kbn + kb) * SLOT, SLOT, bar);
    };

    const int arow = lane & 15;
    const int aoff = (lane >> 4) * 16;
    const int bprow = ((lane >> 4) & 1) * 8 + (lane & 7);
    const int bpoff = ((lane >> 3) & 1) * 16;

    if (t == 0) { issue(0); if (1 < kbn) issue(1); }

    for (int kb = 0; kb < kbn; kb++) {
        if (t == 0 && kb + 2 < kbn) {
            if (kb >= 1)
                MBARRIER_WAIT_PARITY(mbar + 24 + 8 * ((kb + 2) % NSTG),
                                     ((kb + 2) / NSTG - 1) & 1);
            issue(kb + 2);
        }
        MBARRIER_WAIT_PARITY(mbar + 8 * (kb % NSTG), (kb / NSTG) & 1);

        const uint32_t sb = base + (kb % NSTG) * STAGE_KV;

#pragma unroll
        for (int ks = 0; ks < 2; ks++) {
            uint32_t ah[4][4], al[4][4];
#pragma unroll
            for (int mt = 0; mt < 4; mt++) {
                uint32_t off = swz((wm0 + mt * 16 + arow) * 64 + ks * 32 + aoff);
                ldmx4(ah[mt], sb + off);
                ldmx4(al[mt], sb + HSUB + off);
            }
#pragma unroll
            for (int p = 0; p < 2; p++) {
                uint32_t offb = swz((wn0 + p * 16 + bprow) * 64 + ks * 32 + bpoff);
                uint32_t bh4[4], bl4[4];
                ldmx4(bh4, sb + SLOT + offb);
                ldmx4(bl4, sb + SLOT + HSUB + offb);
#pragma unroll
                for (int mt = 0; mt < 4; mt++)
#pragma unroll
                    for (int h = 0; h < 2; h++)
                        mma_bf16(acc[mt][2 * p + h], ah[mt], bh4 + 2 * h);
#pragma unroll
                for (int mt = 0; mt < 4; mt++)
#pragma unroll
                    for (int h = 0; h < 2; h++)
                        mma_bf16(acc[mt][2 * p + h], ah[mt], bl4 + 2 * h);
#pragma unroll
                for (int mt = 0; mt < 4; mt++)
#pragma unroll
                    for (int h = 0; h < 2; h++)
                        mma_bf16(acc[mt][2 * p + h], al[mt], bh4 + 2 * h);
            }
        }
        MBARRIER_ARRIVE(mbar + 24 + 8 * (kb % NSTG));
    }

    // epilogue: bias + ELU -> fp16 single packed
#pragma unroll
    for (int mt = 0; mt < 4; mt++) {
#pragma unroll
        for (int half = 0; half < 2; half++) {
            int m = m0 + wm0 + mt * 16 + gid + half * 8;
#pragma unroll
            for (int nt = 0; nt < 4; nt++) {
                int n = n0 + wn0 + nt * 8 + 2 * tig;
                float v0 = acc[mt][nt][2 * half + 0];
                float v1 = acc[mt][nt][2 * half + 1];
                float b0 = biasRow ? bias[m] : bias[n];
                float b1 = biasRow ? bias[m] : bias[n + 1];
                float e0 = elu_f(v0 + b0);
                float e1 = elu_f(v1 + b1);
                uint32_t off = swz((uint32_t)(m & 127) * 64 + (uint32_t)(n & 31) * 2);
                char* slot = Op + ((size_t)bz * bsO + (size_t)(m >> 7) * kbO + (n >> 5)) * ASLOT;
                *(__half2*)(slot + off) = __floats2half2_rn(e0, e1);
            }
        }
    }
}

// ===========================================================================
// Packers
// ===========================================================================
// Q: fp16 single (ASLOT)
__global__ __launch_bounds__(256) void pack_q(const float* __restrict__ Q)
{
    int row = blockIdx.x;                     // 0..8959
    int src = row < L_ ? row : L_ - 1;
    int t = threadIdx.x;
    float2 v = *(const float2*)(Q + (size_t)src * D_ + t * 2);
    int r = row & 127, tile = row >> 7;
    int d0 = t * 2, kb = d0 >> 5, c = d0 & 31;
    char* slot = g_Qp + ((size_t)tile * 16 + kb) * ASLOT;
    uint32_t off = swz((uint32_t)r * 64 + (uint32_t)c * 2);
    *(__half2*)(slot + off) = __floats2half2_rn(v.x, v.y);
}

__global__ __launch_bounds__(256) void pack_h(const float* __restrict__ H)
{
    __shared__ float tile[64][33];
    const int b = blockIdx.z, s0 = blockIdx.x * 32, d0 = blockIdx.y * 64;
    const int tx = threadIdx.x, ty = threadIdx.y;
    const float* Hb = H + ((size_t)b * D_ + d0) * S_ + s0;

#pragma unroll
    for (int i = 0; i < 8; i++)
        tile[ty * 8 + i][tx] = Hb[(size_t)(ty * 8 + i) * S_ + tx];
    __syncthreads();

    const int t = ty * 32 + tx;
    const int s = t & 31;
    const int dp = t >> 5;
    const int gs = s0 + s;
    const int r = gs & 127;
#pragma unroll
    for (int i = 0; i < 4; i++) {
        int d = dp * 2 + i * 16;
        int kbl = d >> 5, c = d & 31;
        char* slot = g_Hp + (((size_t)b * 16 + (gs >> 7)) * 16 + blockIdx.y * 2 + kbl) * SLOT;
        __nv_bfloat16 h0, l0, h1, l1;
        split_bf16(tile[d][s], h0, l0);
        split_bf16(tile[d + 1][s], h1, l1);
        uint32_t off = swz((uint32_t)r * 64 + (uint32_t)c * 2);
        *(__nv_bfloat162*)(slot + off)        = __nv_bfloat162(h0, h1);
        *(__nv_bfloat162*)(slot + HSUB + off) = __nv_bfloat162(l0, l1);
    }
}

__global__ __launch_bounds__(256) void pack_w(
    const float* __restrict__ Wk, const float* __restrict__ Wv)
{
    int which = blockIdx.x >> 9;
    int o = blockIdx.x & 511;
    const float* W = which ? Wv : Wk;
    int t = threadIdx.x;
    float2 v = *(const float2*)(W + (size_t)o * D_ + t * 2);
    __nv_bfloat16 h0, l0, h1, l1;
    split_bf16(v.x, h0, l0);
    split_bf16(v.y, h1, l1);
    int r = o & 127, tile = o >> 7;
    int d0 = t * 2, kb = d0 >> 5, c = d0 & 31;
    char* slot = g_Wp + (((size_t)which * 4 + tile) * 16 + kb) * SLOT;
    uint32_t off = swz((uint32_t)r * 64 + (uint32_t)c * 2);
    *(__nv_bfloat162*)(slot + off)        = __nv_bfloat162(h0, h1);
    *(__nv_bfloat162*)(slot + HSUB + off) = __nv_bfloat162(l0, l1);
}

// ===========================================================================
// In-place row softmax over S=2048; emits packed FP16 single of A.
// ===========================================================================
__global__ __launch_bounds__(256) void softmax_kernel(float* __restrict__ A)
{
    const int row = blockIdx.x;               // b*L + l
    const int b = row / L_;
    const int l = row - b * L_;
    float* p = A + (size_t)row * S_;
    const int t = threadIdx.x;
    const int lane = t & 31, wid = t >> 5;

    float4 va = *(const float4*)(p + t * 4);
    float4 vb = *(const float4*)(p + 1024 + t * 4);

    float m = fmaxf(fmaxf(fmaxf(va.x, va.y), fmaxf(va.z, va.w)),
                    fmaxf(fmaxf(vb.x, vb.y), fmaxf(vb.z, vb.w)));
#pragma unroll
    for (int o = 16; o > 0; o >>= 1) m = fmaxf(m, __shfl_xor_sync(0xffffffffu, m, o));

    __shared__ float red[8];
    if (lane == 0) red[wid] = m;
    __syncthreads();
    {
        float r = red[lane & 7];
#pragma unroll
        for (int o = 4; o > 0; o >>= 1) r = fmaxf(r, __shfl_xor_sync(0xffffffffu, r, o));
        m = r;
    }

    va.x = __expf(va.x - m); va.y = __expf(va.y - m);
    va.z = __expf(va.z - m); va.w = __expf(va.w - m);
    vb.x = __expf(vb.x - m); vb.y = __expf(vb.y - m);
    vb.z = __expf(vb.z - m); vb.w = __expf(vb.w - m);

    float s = va.x + va.y + va.z + va.w + vb.x + vb.y + vb.z + vb.w;
#pragma unroll
    for (int o = 16; o > 0; o >>= 1) s += __shfl_xor_sync(0xffffffffu, s, o);
    __syncthreads();
    if (lane == 0) red[wid] = s;
    __syncthreads();
    {
        float r = red[lane & 7];
#pragma unroll
        for (int o = 4; o > 0; o >>= 1) r += __shfl_xor_sync(0xffffffffu, r, o);
        s = r;
    }
    float inv = 1.f / s;

    va.x *= inv; va.y *= inv; va.z *= inv; va.w *= inv;
    vb.x *= inv; vb.y *= inv; vb.z *= inv; vb.w *= inv;

    *(float4*)(p + t * 4) = va;
    *(float4*)(p + 1024 + t * 4) = vb;

    char* tslot = g_Ap + ((size_t)b * (70 * 64) + (size_t)(l >> 7) * 64) * ASLOT;
    const uint32_t r = l & 127;

    float g[2][4] = {{va.x, va.y, va.z, va.w}, {vb.x, vb.y, vb.z, vb.w}};
#pragma unroll
    for (int half = 0; half < 2; half++) {
        int sidx = half * 1024 + t * 4;
        int kb = sidx >> 5, c = sidx & 31;
        char* slot = tslot + (size_t)kb * ASLOT;
        uint32_t off = swz(r * 64 + (uint32_t)c * 2);
        *(__half2*)(slot + off)     = __floats2half2_rn(g[half][0], g[half][1]);
        *(__half2*)(slot + off + 4) = __floats2half2_rn(g[half][2], g[half][3]);
    }
}

// ===========================================================================
extern "C" void kernel_launch(void* const* d_in, const int* in_sizes, int n_in,
                              void* d_out, int out_size)
{
    const float* H  = (const float*)d_in[0];
    const float* Wk = (const float*)d_in[1];
    const float* bk = (const float*)d_in[2];
    const float* Wv = (const float*)d_in[3];
    const float* bv = (const float*)d_in[4];
    const float* Q  = (const float*)d_in[5];

    float* out  = (float*)d_out;
    float* Cout = out;                          // [B, L, D]
    float* Aout = out + (size_t)B_ * L_ * D_;   // [B, L, S]

    static char *gQp, *gHp, *gWp, *gKp, *gVp, *gAp;
    static bool init = false;
    if (!init) {
        cudaGetSymbolAddress((void**)&gQp, g_Qp);
        cudaGetSymbolAddress((void**)&gHp, g_Hp);
        cudaGetSymbolAddress((void**)&gWp, g_Wp);
        cudaGetSymbolAddress((void**)&gKp, g_Kp);
        cudaGetSymbolAddress((void**)&gVp, g_Vp);
        cudaGetSymbolAddress((void**)&gAp, g_Ap);
        cudaFuncSetAttribute(gemm_c, cudaFuncAttributeMaxDynamicSharedMemorySize, DSMEM_C);
        cudaFuncSetAttribute(kv_gemm_bulk, cudaFuncAttributeMaxDynamicSharedMemorySize, DSMEM_KV);
        init = true;
    }

    // 0) packers
    pack_q<<<8960, 256>>>(Q);
    pack_h<<<dim3(S_ / 32, D_ / 64, B_), dim3(32, 8)>>>(H);
    pack_w<<<1024, 256>>>(Wk, Wv);

    // 1a) K = H^T * Wk  -> fp16 single, packed (s-tile, o-kb)
    kv_gemm_bulk<<<dim3(D_ / TN, S_ / TM, B_), 256, DSMEM_KV>>>(
        gHp, 256, gWp, 0,
        gKp, 256, 16, bk, 0, 16);

    // 1b) V^T = Wv * H^T -> fp16 single, packed (o-tile, s-kb)
    kv_gemm_bulk<<<dim3(S_ / TN, D_ / TM, B_), 256, DSMEM_KV>>>(
        gWp + (size_t)64 * SLOT, 0, gHp, 256,
        gVp, 256, 64, bv, 1, 16);

    // 2) E = Q K^T -> Aout (fp32), 1-product fp16
    gemm_c<<<dim3(S_ / TN, 70, B_), 256, DSMEM_C>>>(
        gQp, 0, gKp, 256,
        Aout, S_, (size_t)L_ * S_, 16, L_);

    // 3) softmax (+ packed fp16 A)
    softmax_kernel<<<dim3(B_ * L_), 256>>>(Aout);

    // 4) C = A V -> Cout, 1-product fp16
    gemm_c<<<dim3(D_ / TN, 70, B_), 256, DSMEM_C>>>(
        gAp, 70 * 64, gVp, 256,
        Cout, D_, (size_t)L_ * D_, 64, L_);
}